// round 8
// baseline (speedup 1.0000x reference)
#include <cuda_runtime.h>
#include <math.h>
#include <stdint.h>

#define NS 1024
#define T  32
#define NF 16
#define H  192
#define G  768

typedef unsigned long long u64;

static __device__ float g_gx0[(size_t)2*NS*T*G];   // time-major: [dir][tt][G][NS]
static __device__ float g_gx1[(size_t)NS*T*G];     // time-major: [tt][G][NS]
static __device__ float g_gx1b[(size_t)NS*G];      // [s][G]
static __device__ float g_h1[(size_t)NS*T*384];    // [s][tt][384]
static __device__ float g_h2[(size_t)NS*384];
static __device__ float g_BetaT[(size_t)NS*NS];
static __device__ float g_t3[NS*3];
static __device__ int   g_pid[NS];
static __device__ int   g_off[NS];
static __device__ float g_M[NS*128];
static __device__ float g_E[NS*128];
static __device__ float g_n1[NS*128];
static __device__ float g_n2[NS*128];

__device__ __forceinline__ float sigm(float x){ return 1.f/(1.f+expf(-x)); }
__device__ __forceinline__ u64 pk(float x, float y){ u64 r; asm("mov.b64 %0,{%1,%2};":"=l"(r):"f"(x),"f"(y)); return r; }
__device__ __forceinline__ void fma2(u64& d, u64 a, u64 b){ asm("fma.rn.f32x2 %0,%1,%2,%0;":"+l"(d):"l"(a),"l"(b)); }
__device__ __forceinline__ void unpk(u64 v, float& x, float& y){ asm("mov.b64 {%0,%1},%2;":"=f"(x),"=f"(y):"l"(v)); }
__device__ __forceinline__ float lohi(u64 v){ float x,y; unpk(v,x,y); return x+y; }
__device__ __forceinline__ uint32_t smem_u32(const void* p){
    uint32_t a; asm("{ .reg .u64 t; cvta.to.shared.u64 t, %1; cvt.u32.u64 %0, t; }":"=r"(a):"l"(p)); return a;
}
#define CL_ARRIVE() asm volatile("barrier.cluster.arrive.aligned;" ::: "memory")
#define CL_WAIT()   asm volatile("barrier.cluster.wait.aligned;"   ::: "memory")

// ---- transposing gx GEMM, double-buffered (1 sync/iter, LDG overlapped):
// Ct[tt][n][s] = sum_k A[s][tt][k]*B[n][k] + bias0[n] + bias1[n]
__global__ __launch_bounds__(256,2)
void gemm_nt128T(const float* __restrict__ A, int lda,
                 const float* __restrict__ B, int ldb,
                 float* __restrict__ Ct, int K,
                 const float* __restrict__ bias0, const float* __restrict__ bias1)
{
    extern __shared__ __align__(16) float csh[];   // [128][132]
    __shared__ __align__(16) float As[2][16][136];
    __shared__ __align__(16) float Bs[2][16][136];
    const int tt = blockIdx.x >> 3;
    const int s0 = (blockIdx.x & 7) * 128;
    const int n0 = blockIdx.y * 128;
    const int tid = threadIdx.x;
    const int ty = tid>>4, tx = tid&15;
    const int row = tid>>1, kq = (tid&1)*8;
    const float* aBase = A + ((size_t)(s0+row)*T + tt)*lda + kq;
    const float* bBase = B + (size_t)(n0+row)*ldb + kq;
    u64 acc[4][8];
    #pragma unroll
    for (int i=0;i<4;i++)
        #pragma unroll
        for (int j=0;j<8;j++) acc[i][j]=0ull;

    float4 a0 = *(const float4*)(aBase);
    float4 a1 = *(const float4*)(aBase+4);
    float4 b0 = *(const float4*)(bBase);
    float4 b1 = *(const float4*)(bBase+4);
    As[0][kq+0][row]=a0.x; As[0][kq+1][row]=a0.y; As[0][kq+2][row]=a0.z; As[0][kq+3][row]=a0.w;
    As[0][kq+4][row]=a1.x; As[0][kq+5][row]=a1.y; As[0][kq+6][row]=a1.z; As[0][kq+7][row]=a1.w;
    Bs[0][kq+0][row]=b0.x; Bs[0][kq+1][row]=b0.y; Bs[0][kq+2][row]=b0.z; Bs[0][kq+3][row]=b0.w;
    Bs[0][kq+4][row]=b1.x; Bs[0][kq+5][row]=b1.y; Bs[0][kq+6][row]=b1.z; Bs[0][kq+7][row]=b1.w;
    __syncthreads();

    int buf = 0;
    for (int k0=0;k0<K;k0+=16){
        const bool nxt = (k0+16)<K;
        if (nxt){
            a0 = *(const float4*)(aBase + k0+16);
            a1 = *(const float4*)(aBase + k0+20);
            b0 = *(const float4*)(bBase + k0+16);
            b1 = *(const float4*)(bBase + k0+20);
        }
        #pragma unroll
        for (int k=0;k<16;k++){
            ulonglong2 av0 = *(const ulonglong2*)&As[buf][k][tx*8];
            ulonglong2 av1 = *(const ulonglong2*)&As[buf][k][tx*8+4];
            float4 bA = *(const float4*)&Bs[buf][k][ty*8];
            float4 bB = *(const float4*)&Bs[buf][k][ty*8+4];
            u64 bb[8];
            bb[0]=pk(bA.x,bA.x); bb[1]=pk(bA.y,bA.y); bb[2]=pk(bA.z,bA.z); bb[3]=pk(bA.w,bA.w);
            bb[4]=pk(bB.x,bB.x); bb[5]=pk(bB.y,bB.y); bb[6]=pk(bB.z,bB.z); bb[7]=pk(bB.w,bB.w);
            u64 aa[4] = { av0.x, av0.y, av1.x, av1.y };
            #pragma unroll
            for (int i2=0;i2<4;i2++)
                #pragma unroll
                for (int j=0;j<8;j++) fma2(acc[i2][j], aa[i2], bb[j]);
        }
        if (nxt){
            int nb = buf^1;
            As[nb][kq+0][row]=a0.x; As[nb][kq+1][row]=a0.y; As[nb][kq+2][row]=a0.z; As[nb][kq+3][row]=a0.w;
            As[nb][kq+4][row]=a1.x; As[nb][kq+5][row]=a1.y; As[nb][kq+6][row]=a1.z; As[nb][kq+7][row]=a1.w;
            Bs[nb][kq+0][row]=b0.x; Bs[nb][kq+1][row]=b0.y; Bs[nb][kq+2][row]=b0.z; Bs[nb][kq+3][row]=b0.w;
            Bs[nb][kq+4][row]=b1.x; Bs[nb][kq+5][row]=b1.y; Bs[nb][kq+6][row]=b1.z; Bs[nb][kq+7][row]=b1.w;
            __syncthreads();
            buf = nb;
        }
    }
    float bv[8];
    #pragma unroll
    for (int j=0;j<8;j++){
        int n = n0+ty*8+j;
        bv[j] = bias0[n] + bias1[n];
    }
    __syncthreads();
    #pragma unroll
    for (int j=0;j<8;j++){
        float r[8];
        #pragma unroll
        for (int i2=0;i2<4;i2++){ unpk(acc[i2][j], r[2*i2], r[2*i2+1]); }
        #pragma unroll
        for (int v=0;v<8;v++) r[v] += bv[j];
        float* cp = csh + (size_t)(ty*8+j)*132 + tx*8;
        *(float4*)cp     = make_float4(r[0],r[1],r[2],r[3]);
        *(float4*)(cp+4) = make_float4(r[4],r[5],r[6],r[7]);
    }
    __syncthreads();
    {
        int jl = tid>>1, half = (tid&1)*64;
        const float* src = csh + (size_t)jl*132 + half;
        float* dst = Ct + ((size_t)tt*G + n0 + jl)*NS + s0 + half;
        #pragma unroll
        for (int v=0;v<16;v++)
            *(float4*)(dst + v*4) = *(const float4*)(src + v*4);
    }
}

// ---- plain NT gemm (gx1b), double-buffered, C[m][n] layout ----
__global__ __launch_bounds__(256,2)
void gemm_nt128(const float* __restrict__ A, int lda,
                const float* __restrict__ B, int ldb,
                float* __restrict__ C, int ldc, int K,
                const float* __restrict__ bias0, const float* __restrict__ bias1)
{
    __shared__ __align__(16) float As[2][16][136];
    __shared__ __align__(16) float Bs[2][16][136];
    const int m0 = blockIdx.x*128, n0 = blockIdx.y*128;
    const int tid = threadIdx.x;
    const int ty = tid>>4, tx = tid&15;
    const int row = tid>>1, kq = (tid&1)*8;
    const float* aBase = A + (size_t)(m0+row)*lda + kq;
    const float* bBase = B + (size_t)(n0+row)*ldb + kq;
    u64 acc[4][8];
    #pragma unroll
    for (int i=0;i<4;i++)
        #pragma unroll
        for (int j=0;j<8;j++) acc[i][j]=0ull;

    float4 a0 = *(const float4*)(aBase);
    float4 a1 = *(const float4*)(aBase+4);
    float4 b0 = *(const float4*)(bBase);
    float4 b1 = *(const float4*)(bBase+4);
    As[0][kq+0][row]=a0.x; As[0][kq+1][row]=a0.y; As[0][kq+2][row]=a0.z; As[0][kq+3][row]=a0.w;
    As[0][kq+4][row]=a1.x; As[0][kq+5][row]=a1.y; As[0][kq+6][row]=a1.z; As[0][kq+7][row]=a1.w;
    Bs[0][kq+0][row]=b0.x; Bs[0][kq+1][row]=b0.y; Bs[0][kq+2][row]=b0.z; Bs[0][kq+3][row]=b0.w;
    Bs[0][kq+4][row]=b1.x; Bs[0][kq+5][row]=b1.y; Bs[0][kq+6][row]=b1.z; Bs[0][kq+7][row]=b1.w;
    __syncthreads();

    int buf = 0;
    for (int k0=0;k0<K;k0+=16){
        const bool nxt = (k0+16)<K;
        if (nxt){
            a0 = *(const float4*)(aBase + k0+16);
            a1 = *(const float4*)(aBase + k0+20);
            b0 = *(const float4*)(bBase + k0+16);
            b1 = *(const float4*)(bBase + k0+20);
        }
        #pragma unroll
        for (int k=0;k<16;k++){
            ulonglong2 av0 = *(const ulonglong2*)&As[buf][k][ty*8];
            ulonglong2 av1 = *(const ulonglong2*)&As[buf][k][ty*8+4];
            float4 bA = *(const float4*)&Bs[buf][k][tx*8];
            float4 bB = *(const float4*)&Bs[buf][k][tx*8+4];
            u64 bb[8];
            bb[0]=pk(bA.x,bA.x); bb[1]=pk(bA.y,bA.y); bb[2]=pk(bA.z,bA.z); bb[3]=pk(bA.w,bA.w);
            bb[4]=pk(bB.x,bB.x); bb[5]=pk(bB.y,bB.y); bb[6]=pk(bB.z,bB.z); bb[7]=pk(bB.w,bB.w);
            u64 aa[4] = { av0.x, av0.y, av1.x, av1.y };
            #pragma unroll
            for (int i2=0;i2<4;i2++)
                #pragma unroll
                for (int j=0;j<8;j++) fma2(acc[i2][j], aa[i2], bb[j]);
        }
        if (nxt){
            int nb = buf^1;
            As[nb][kq+0][row]=a0.x; As[nb][kq+1][row]=a0.y; As[nb][kq+2][row]=a0.z; As[nb][kq+3][row]=a0.w;
            As[nb][kq+4][row]=a1.x; As[nb][kq+5][row]=a1.y; As[nb][kq+6][row]=a1.z; As[nb][kq+7][row]=a1.w;
            Bs[nb][kq+0][row]=b0.x; Bs[nb][kq+1][row]=b0.y; Bs[nb][kq+2][row]=b0.z; Bs[nb][kq+3][row]=b0.w;
            Bs[nb][kq+4][row]=b1.x; Bs[nb][kq+5][row]=b1.y; Bs[nb][kq+6][row]=b1.z; Bs[nb][kq+7][row]=b1.w;
            __syncthreads();
            buf = nb;
        }
    }
    float bv[8];
    #pragma unroll
    for (int j=0;j<8;j++){
        int n = n0+tx*8+j;
        float v = 0.f;
        if (bias0) v += bias0[n];
        if (bias1) v += bias1[n];
        bv[j]=v;
    }
    #pragma unroll
    for (int i2=0;i2<4;i2++){
        float r0[8], r1[8];
        #pragma unroll
        for (int j=0;j<8;j++){ unpk(acc[i2][j], r0[j], r1[j]); r0[j]+=bv[j]; r1[j]+=bv[j]; }
        float* c0 = C + (size_t)(m0+ty*8+2*i2)*ldc + n0 + tx*8;
        float* c1 = C + (size_t)(m0+ty*8+2*i2+1)*ldc + n0 + tx*8;
        *(float4*)c0     = make_float4(r0[0],r0[1],r0[2],r0[3]);
        *(float4*)(c0+4) = make_float4(r0[4],r0[5],r0[6],r0[7]);
        *(float4*)c1     = make_float4(r1[0],r1[1],r1[2],r1[3]);
        *(float4*)(c1+4) = make_float4(r1[4],r1[5],r1[6],r1[7]);
    }
}

// ---- C[m][n] = sum_k A[m][k]*B[k][n] (+addC), 64x64 tile, 4x4 micro.
__global__ __launch_bounds__(256,1)
void gemm_nn64(const float* __restrict__ A, int lda,
               const float* __restrict__ B, int ldb,
               float* __restrict__ C, int ldc, int K,
               const float* __restrict__ addC)
{
    __shared__ __align__(16) float As[16][68];
    __shared__ __align__(16) float Bs[16][68];
    const int m0 = blockIdx.x*64, n0 = blockIdx.y*64;
    const int tid = threadIdx.x;
    const int ty = tid>>4, tx = tid&15;
    const int arow = tid>>2, akq = (tid&3)*4;
    const int bk = tid>>4, bnq = (tid&15)*4;
    float acc[4][4];
    #pragma unroll
    for (int i=0;i<4;i++)
        #pragma unroll
        for (int j=0;j<4;j++) acc[i][j]=0.f;

    for (int k0=0;k0<K;k0+=16){
        float4 av = *(const float4*)(A + (size_t)(m0+arow)*lda + k0 + akq);
        float4 bv = *(const float4*)(B + (size_t)(k0+bk)*ldb + n0 + bnq);
        __syncthreads();
        As[akq+0][arow]=av.x; As[akq+1][arow]=av.y; As[akq+2][arow]=av.z; As[akq+3][arow]=av.w;
        *(float4*)&Bs[bk][bnq] = bv;
        __syncthreads();
        #pragma unroll
        for (int k=0;k<16;k++){
            float a[4],b[4];
            #pragma unroll
            for (int i=0;i<4;i++){ a[i]=As[k][ty*4+i]; b[i]=Bs[k][tx*4+i]; }
            #pragma unroll
            for (int i=0;i<4;i++)
                #pragma unroll
                for (int j=0;j<4;j++) acc[i][j]+=a[i]*b[j];
        }
    }
    #pragma unroll
    for (int i=0;i<4;i++){
        int m = m0+ty*4+i;
        float* cp = C + (size_t)m*ldc + n0 + tx*4;
        const float* ap = addC ? addC + (size_t)m*ldc + n0 + tx*4 : (const float*)0;
        #pragma unroll
        for (int j=0;j<4;j++){
            float v = acc[i][j];
            if (ap) v += ap[j];
            cp[j] = v;
        }
    }
}

// ---- cluster LSTM recurrence, 768 threads.
// Hs stride 196 (==4 mod 32): LDS.128 h loads are quarter-warp conflict-free.
template<int SPC>
__global__ __launch_bounds__(768,1) __cluster_dims__(4,1,1)
void lstm_cluster(const float* __restrict__ gx_all, const float* __restrict__ Whh_all,
                  float* __restrict__ outp, int mode0)
{
    constexpr int SPT = SPC/32;
    constexpr int HSP = 196;
    constexpr int BSP = 196;
    extern __shared__ float sm[];
    float* Bsh = sm;                   // [192][BSP]
    float* Hs  = sm + 192*BSP;         // [SPC][HSP]

    const int dir  = blockIdx.y;
    const int mode = mode0 + dir;
    const float* gx  = gx_all  + (size_t)dir*NS*T*G;
    const float* Whh = Whh_all + (size_t)dir*G*H;

    const int tid  = threadIdx.x;
    const int sgrp = tid & 31;         // stock lane
    const int u0   = (tid >> 5) * 2;   // first of 2 local units
    uint32_t rank; asm("mov.u32 %0, %%cluster_ctarank;" : "=r"(rank));
    const int cid   = blockIdx.x >> 2;
    const int sbase = cid * SPC;
    const int jsl   = (int)rank * 48;
    const uint32_t hs_base = smem_u32(Hs);

    for (int i = tid; i < 192*48; i += 768){
        int lr = i / 48, c4 = i % 48;
        int q = lr / 48, u = lr % 48;
        float4 v = *(const float4*)(Whh + (size_t)(q*192 + jsl + u)*H + c4*4);
        *(float4*)(Bsh + lr*BSP + c4*4) = v;
    }
    for (int i = tid; i < SPC*HSP; i += 768) Hs[i] = 0.f;
    CL_ARRIVE(); CL_WAIT();

    float c[2][SPT];
    #pragma unroll
    for (int a=0;a<2;a++)
        #pragma unroll
        for (int b=0;b<SPT;b++) c[a][b]=0.f;

    for (int step=0; step<T; ++step){
        const int tt = (mode==1) ? (T-1-step) : step;

        float gxr[2][4][SPT];
        #pragma unroll
        for (int uu=0;uu<2;uu++)
            #pragma unroll
            for (int q=0;q<4;q++)
                #pragma unroll
                for (int ss=0;ss<SPT;ss++)
                    gxr[uu][q][ss] = gx[((size_t)tt*G + q*192 + jsl + u0 + uu)*NS
                                        + sbase + sgrp + 32*ss];

        u64 acc[2][4][SPT];
        #pragma unroll
        for (int uu=0;uu<2;uu++)
            #pragma unroll
            for (int q=0;q<4;q++)
                #pragma unroll
                for (int ss=0;ss<SPT;ss++) acc[uu][q][ss]=0ull;

        #pragma unroll 2
        for (int k=0;k<192;k+=4){
            u64 ha[SPT], hb[SPT];
            #pragma unroll
            for (int ss=0;ss<SPT;ss++){
                ulonglong2 hv4 = *(const ulonglong2*)(Hs + (sgrp + 32*ss)*HSP + k);
                ha[ss]=hv4.x; hb[ss]=hv4.y;
            }
            #pragma unroll
            for (int uu=0;uu<2;uu++)
                #pragma unroll
                for (int q=0;q<4;q++){
                    ulonglong2 bv = *(const ulonglong2*)(Bsh + (q*48 + u0 + uu)*BSP + k);
                    #pragma unroll
                    for (int ss=0;ss<SPT;ss++){
                        fma2(acc[uu][q][ss], ha[ss], bv.x);
                        fma2(acc[uu][q][ss], hb[ss], bv.y);
                    }
                }
        }
        float pre[2][4][SPT];
        #pragma unroll
        for (int uu=0;uu<2;uu++)
            #pragma unroll
            for (int q=0;q<4;q++)
                #pragma unroll
                for (int ss=0;ss<SPT;ss++) pre[uu][q][ss] = lohi(acc[uu][q][ss]) + gxr[uu][q][ss];

        CL_ARRIVE();                   // my reads of Hs(t-1) done
        CL_WAIT();                     // all CTAs' reads done -> safe to write

        float hv[2][SPT];
        #pragma unroll
        for (int uu=0;uu<2;uu++)
            #pragma unroll
            for (int ss=0;ss<SPT;ss++){
                float iv = sigm(pre[uu][0][ss]);
                float fv = sigm(pre[uu][1][ss]);
                float gv = tanhf(pre[uu][2][ss]);
                float ov = sigm(pre[uu][3][ss]);
                float cc = fv*c[uu][ss] + iv*gv;
                c[uu][ss] = cc;
                hv[uu][ss] = ov*tanhf(cc);
            }
        #pragma unroll
        for (int ss=0;ss<SPT;ss++){
            int sl = sgrp + 32*ss;
            #pragma unroll
            for (int uu=0;uu<2;uu++){
                uint32_t la = hs_base + (uint32_t)(sl*HSP + jsl + u0 + uu)*4u;
                float v = hv[uu][ss];
                Hs[sl*HSP + jsl + u0 + uu] = v;
                #pragma unroll
                for (int r=0;r<4;r++){
                    if (r == (int)rank) continue;
                    uint32_t da; asm("mapa.shared::cluster.u32 %0,%1,%2;":"=r"(da):"r"(la),"r"(r));
                    asm volatile("st.shared::cluster.f32 [%0],%1;"::"r"(da),"f"(v));
                }
            }
        }
        CL_ARRIVE();                   // release h(t) writes
        if (mode==0 || mode==1){
            #pragma unroll
            for (int ss=0;ss<SPT;ss++){
                int s = sbase + sgrp + 32*ss;
                float* op = outp + ((size_t)s*T + tt)*384 + (mode==1?192:0) + jsl + u0;
                op[0]=hv[0][ss]; op[1]=hv[1][ss];
            }
        } else if (step==T-1){
            #pragma unroll
            for (int ss=0;ss<SPT;ss++){
                int s = sbase + sgrp + 32*ss;
                float* op = outp + (size_t)s*384 + jsl + u0;
                op[0]=hv[0][ss]; op[1]=hv[1][ss];
            }
        }
        CL_WAIT();                     // acquire peers' h(t)
    }
}

// ---- layer1 bwd @ t=31 only (h0=c0=0) ----
__global__ void bwd1_last(const float* __restrict__ gxb, float* __restrict__ h2)
{
    int n = blockIdx.x, j = threadIdx.x;
    const float* g = gxb + (size_t)n*G;
    float iv = sigm(g[j]);
    float gv = tanhf(g[2*H+j]);
    float ov = sigm(g[3*H+j]);
    float cc = iv*gv;
    h2[(size_t)n*384 + 192 + j] = ov*tanhf(cc);
}

// ---- dynamic network ----
__global__ void dyn_scalars(const float* __restrict__ x, const float* __restrict__ theta,
                            int* __restrict__ pid, int* __restrict__ off)
{
    int n = blockIdx.x*blockDim.x + threadIdx.x;
    if (n >= NS) return;
    float th  = theta[n];
    float x30 = x[((size_t)n*T + 30)*NF];
    float x31 = x[((size_t)n*T + 31)*NF];
    int p0 = (x30 > th) ? 1 : ((x30 < -th) ? -1 : 0);
    int p1 = (x31 > th) ? 1 : ((x31 < -th) ? -1 : 0);
    pid[n] = (p0+1)*3 + (p1+1);
    off[n] = (p1+1)*3;
}

__global__ __launch_bounds__(256,1)
void dyn_beta(const float* __restrict__ PP, const int* __restrict__ pid,
              const int* __restrict__ off, float* __restrict__ BetaT,
              float* __restrict__ t3)
{
    __shared__ float s_raw[1024];
    __shared__ float s_adj[1024*3];
    __shared__ float s_red[256];
    const int y = blockIdx.x, tid = threadIdx.x;
    const int offy = off[y];
    for (int x=tid; x<NS; x+=256){
        size_t base = ((size_t)x*NS + y)*81 + (size_t)pid[x]*9 + offy;
        float a0=PP[base], a1=PP[base+1], a2=PP[base+2];
        s_adj[x*3+0]=a0; s_adj[x*3+1]=a1; s_adj[x*3+2]=a2;
        float nr = sqrtf(a0*a0+a1*a1+a2*a2);
        s_raw[x] = (nr > 0.38f) ? nr : 0.f;
    }
    __syncthreads();
    float lm = -1e30f;
    for (int x=tid; x<NS; x+=256) lm = fmaxf(lm, s_raw[x]);
    s_red[tid]=lm; __syncthreads();
    for (int o=128;o>0;o>>=1){ if(tid<o) s_red[tid]=fmaxf(s_red[tid],s_red[tid+o]); __syncthreads(); }
    const float mx = s_red[0];
    __syncthreads();
    float ls = 0.f;
    for (int x=tid; x<NS; x+=256){ float e=expf(s_raw[x]-mx); s_raw[x]=e; ls+=e; }
    s_red[tid]=ls; __syncthreads();
    for (int o=128;o>0;o>>=1){ if(tid<o) s_red[tid]+=s_red[tid+o]; __syncthreads(); }
    const float inv = 1.f/s_red[0];
    __syncthreads();
    float t0=0.f,t1=0.f,t2=0.f;
    for (int x=tid; x<NS; x+=256){
        float b = s_raw[x]*inv;
        BetaT[(size_t)y*NS + x] = b;
        t0 += b*s_adj[x*3+0]; t1 += b*s_adj[x*3+1]; t2 += b*s_adj[x*3+2];
    }
    s_red[tid]=t0; __syncthreads();
    for (int o=128;o>0;o>>=1){ if(tid<o) s_red[tid]+=s_red[tid+o]; __syncthreads(); }
    if(tid==0) t3[y*3+0]=s_red[0];
    __syncthreads();
    s_red[tid]=t1; __syncthreads();
    for (int o=128;o>0;o>>=1){ if(tid<o) s_red[tid]+=s_red[tid+o]; __syncthreads(); }
    if(tid==0) t3[y*3+1]=s_red[0];
    __syncthreads();
    s_red[tid]=t2; __syncthreads();
    for (int o=128;o>0;o>>=1){ if(tid<o) s_red[tid]+=s_red[tid+o]; __syncthreads(); }
    if(tid==0) t3[y*3+2]=s_red[0];
}

__global__ void agg_extra(const float* __restrict__ t3, const float* __restrict__ Wa,
                          const float* __restrict__ b, float* __restrict__ E)
{
    int y = blockIdx.x, u = threadIdx.x;
    float v = b[u] + t3[y*3+0]*Wa[u] + t3[y*3+1]*Wa[128+u] + t3[y*3+2]*Wa[256+u];
    E[(size_t)y*128 + u] = v;
}

__global__ void out_kernel(const float* __restrict__ nfeat, const float* __restrict__ n1,
                           const float* __restrict__ n2, const float* __restrict__ W,
                           const float* __restrict__ b, float* __restrict__ out)
{
    int warp = (blockIdx.x*blockDim.x + threadIdx.x)>>5;
    int lane = threadIdx.x & 31;
    if (warp >= NS*2) return;
    int n = warp>>1, o = warp&1;
    float s = 0.f;
    for (int k=lane;k<384;k+=32) s += nfeat[(size_t)n*384+k]*W[k*2+o];
    for (int k=lane;k<128;k+=32) s += n1[(size_t)n*128+k]*W[(384+k)*2+o];
    for (int k=lane;k<128;k+=32) s += n2[(size_t)n*128+k]*W[(512+k)*2+o];
    #pragma unroll
    for (int m=16;m>0;m>>=1) s += __shfl_xor_sync(0xffffffffu, s, m);
    if (lane==0) out[warp] = tanhf(s + b[o]);
}

extern "C" void kernel_launch(void* const* d_in, const int* in_sizes, int n_in,
                              void* d_out, int out_size)
{
    const float* x     = (const float*)d_in[0];
    const float* theta = (const float*)d_in[1];
    const float* PP    = (const float*)d_in[2];
    const float* Wih0  = (const float*)d_in[3];
    const float* Whh0  = (const float*)d_in[4];
    const float* bih0  = (const float*)d_in[5];
    const float* bhh0  = (const float*)d_in[6];
    const float* Wih1  = (const float*)d_in[7];
    const float* Whh1  = (const float*)d_in[8];
    const float* bih1  = (const float*)d_in[9];
    const float* bhh1  = (const float*)d_in[10];
    const float* Wagg1 = (const float*)d_in[11];
    const float* bagg1 = (const float*)d_in[12];
    const float* Wagg2 = (const float*)d_in[13];
    const float* bagg2 = (const float*)d_in[14];
    const float* Wout  = (const float*)d_in[15];
    const float* bout  = (const float*)d_in[16];
    float* out = (float*)d_out;

    float *p_gx0, *p_gx1, *p_gx1b, *p_h1, *p_h2, *p_BetaT, *p_t3, *p_M, *p_E, *p_n1, *p_n2;
    int *p_pid, *p_off;
    cudaGetSymbolAddress((void**)&p_gx0,  g_gx0);
    cudaGetSymbolAddress((void**)&p_gx1,  g_gx1);
    cudaGetSymbolAddress((void**)&p_gx1b, g_gx1b);
    cudaGetSymbolAddress((void**)&p_h1,   g_h1);
    cudaGetSymbolAddress((void**)&p_h2,   g_h2);
    cudaGetSymbolAddress((void**)&p_BetaT,g_BetaT);
    cudaGetSymbolAddress((void**)&p_t3,   g_t3);
    cudaGetSymbolAddress((void**)&p_pid,  g_pid);
    cudaGetSymbolAddress((void**)&p_off,  g_off);
    cudaGetSymbolAddress((void**)&p_M,    g_M);
    cudaGetSymbolAddress((void**)&p_E,    g_E);
    cudaGetSymbolAddress((void**)&p_n1,   g_n1);
    cudaGetSymbolAddress((void**)&p_n2,   g_n2);

    const int SM64 = (192*196 + 64*196)*4;   // 200704 B
    const int SM32 = (192*196 + 32*196)*4;   // 175616 B
    const int CSH  = 128*132*4;              // 67584 B
    cudaFuncSetAttribute(lstm_cluster<64>, cudaFuncAttributeMaxDynamicSharedMemorySize, SM64);
    cudaFuncSetAttribute(lstm_cluster<32>, cudaFuncAttributeMaxDynamicSharedMemorySize, SM32);
    cudaFuncSetAttribute(gemm_nt128T, cudaFuncAttributeMaxDynamicSharedMemorySize, CSH);

    // #1-2: layer0 gx, time-major, both dirs
    for (int d=0; d<2; d++){
        gemm_nt128T<<<dim3(256,6), 256, CSH>>>(x, NF, Wih0 + (size_t)d*G*NF, NF,
                                               p_gx0 + (size_t)d*NS*T*G, NF,
                                               bih0 + d*G, bhh0 + d*G);
    }
    // #3: tiny independent kernel (profile slot alignment)
    dyn_scalars<<<4, 256>>>(x, theta, p_pid, p_off);

    // #4: layer0 recurrence, fwd+bwd — profiled slot
    lstm_cluster<64><<<dim3(64,2), 768, SM64>>>(p_gx0, Whh0, p_h1, 0);

    // #5: dynamic network main
    dyn_beta<<<NS, 256>>>(PP, p_pid, p_off, p_BetaT, p_t3);

    // #6: layer1 fwd gx, time-major
    gemm_nt128T<<<dim3(256,6), 256, CSH>>>(p_h1, 384, Wih1, 384, p_gx1, 384,
                                           bih1, bhh1);
    // #7: layer1 bwd gx at t=31 only ([s][j] layout)
    gemm_nt128<<<dim3(8,6), 256>>>(p_h1 + 31*384, T*384, Wih1 + (size_t)G*384, 384,
                                   p_gx1b, G, 384, bih1 + G, bhh1 + G);

    // #8-9: layer1 recurrence fwd; bwd single step
    lstm_cluster<32><<<dim3(128,1), 768, SM32>>>(p_gx1, Whh1, p_h2, 2);
    bwd1_last<<<NS, H>>>(p_gx1b, p_h2);

    // #10-12: agg layer 1
    agg_extra<<<NS, 128>>>(p_t3, Wagg1 + (size_t)384*128, bagg1, p_E);
    gemm_nn64<<<dim3(16,2), 256>>>(p_h2, 384, Wagg1, 128, p_M, 128, 384, (const float*)0);
    gemm_nn64<<<dim3(16,2), 256>>>(p_BetaT, NS, p_M, 128, p_n1, 128, NS, p_E);

    // #13-15: agg layer 2
    gemm_nn64<<<dim3(16,2), 256>>>(p_n1, 128, Wagg2, 128, p_M, 128, 128, (const float*)0);
    agg_extra<<<NS, 128>>>(p_t3, Wagg2 + (size_t)128*128, bagg2, p_E);
    gemm_nn64<<<dim3(16,2), 256>>>(p_BetaT, NS, p_M, 128, p_n2, 128, NS, p_E);

    // #16: output
    out_kernel<<<256, 256>>>(p_h2, p_n1, p_n2, Wout, bout, out);
}

// round 9
// speedup vs baseline: 1.1730x; 1.1730x over previous
#include <cuda_runtime.h>
#include <math.h>
#include <stdint.h>

#define NS 1024
#define T  32
#define NF 16
#define H  192
#define G  768

typedef unsigned long long u64;

static __device__ float g_gx0[(size_t)2*NS*T*G];   // time-major: [dir][tt][G][NS]
static __device__ float g_gx1[(size_t)NS*T*G];     // time-major: [tt][G][NS]
static __device__ float g_gx1b[(size_t)NS*G];      // [s][G]
static __device__ float g_h1[(size_t)NS*T*384];    // [s][tt][384]
static __device__ float g_h2[(size_t)NS*384];
static __device__ float g_BetaT[(size_t)NS*NS];
static __device__ float g_t3[NS*3];
static __device__ int   g_pid[NS];
static __device__ int   g_off[NS];
static __device__ float g_M[NS*128];
static __device__ float g_E[NS*128];
static __device__ float g_n1[NS*128];
static __device__ float g_n2[NS*128];

__device__ __forceinline__ float sigm(float x){ return 1.f/(1.f+expf(-x)); }
__device__ __forceinline__ u64 pk(float x, float y){ u64 r; asm("mov.b64 %0,{%1,%2};":"=l"(r):"f"(x),"f"(y)); return r; }
__device__ __forceinline__ void fma2(u64& d, u64 a, u64 b){ asm("fma.rn.f32x2 %0,%1,%2,%0;":"+l"(d):"l"(a),"l"(b)); }
__device__ __forceinline__ void unpk(u64 v, float& x, float& y){ asm("mov.b64 {%0,%1},%2;":"=f"(x),"=f"(y):"l"(v)); }
__device__ __forceinline__ float lohi(u64 v){ float x,y; unpk(v,x,y); return x+y; }
__device__ __forceinline__ uint32_t smem_u32(const void* p){
    uint32_t a; asm("{ .reg .u64 t; cvta.to.shared.u64 t, %1; cvt.u32.u64 %0, t; }":"=r"(a):"l"(p)); return a;
}
#define CL_ARRIVE() asm volatile("barrier.cluster.arrive.aligned;" ::: "memory")
#define CL_WAIT()   asm volatile("barrier.cluster.wait.aligned;"   ::: "memory")

// ---- transposing gx GEMM (single-buffer, R7-proven):
// Ct[tt][n][s] = sum_k A[s][tt][k]*B[n][k] + bias0[n] + bias1[n]
__global__ __launch_bounds__(256,2)
void gemm_nt128T(const float* __restrict__ A, int lda,
                 const float* __restrict__ B, int ldb,
                 float* __restrict__ Ct, int K,
                 const float* __restrict__ bias0, const float* __restrict__ bias1)
{
    extern __shared__ __align__(16) float csh[];   // [128][132]
    __shared__ __align__(16) float As[16][136];
    __shared__ __align__(16) float Bs[16][136];
    const int tt = blockIdx.x >> 3;
    const int s0 = (blockIdx.x & 7) * 128;
    const int n0 = blockIdx.y * 128;
    const int tid = threadIdx.x;
    const int ty = tid>>4, tx = tid&15;
    const int row = tid>>1, kq = (tid&1)*8;
    u64 acc[4][8];
    #pragma unroll
    for (int i=0;i<4;i++)
        #pragma unroll
        for (int j=0;j<8;j++) acc[i][j]=0ull;

    for (int k0=0;k0<K;k0+=16){
        const float* ap = A + ((size_t)(s0+row)*T + tt)*lda + k0 + kq;
        float4 a0 = *(const float4*)ap;
        float4 a1 = *(const float4*)(ap+4);
        float4 b0 = *(const float4*)(B + (size_t)(n0+row)*ldb + k0 + kq);
        float4 b1 = *(const float4*)(B + (size_t)(n0+row)*ldb + k0 + kq + 4);
        __syncthreads();
        As[kq+0][row]=a0.x; As[kq+1][row]=a0.y; As[kq+2][row]=a0.z; As[kq+3][row]=a0.w;
        As[kq+4][row]=a1.x; As[kq+5][row]=a1.y; As[kq+6][row]=a1.z; As[kq+7][row]=a1.w;
        Bs[kq+0][row]=b0.x; Bs[kq+1][row]=b0.y; Bs[kq+2][row]=b0.z; Bs[kq+3][row]=b0.w;
        Bs[kq+4][row]=b1.x; Bs[kq+5][row]=b1.y; Bs[kq+6][row]=b1.z; Bs[kq+7][row]=b1.w;
        __syncthreads();
        #pragma unroll
        for (int k=0;k<16;k++){
            ulonglong2 av0 = *(const ulonglong2*)&As[k][tx*8];
            ulonglong2 av1 = *(const ulonglong2*)&As[k][tx*8+4];
            float4 bA = *(const float4*)&Bs[k][ty*8];
            float4 bB = *(const float4*)&Bs[k][ty*8+4];
            u64 bb[8];
            bb[0]=pk(bA.x,bA.x); bb[1]=pk(bA.y,bA.y); bb[2]=pk(bA.z,bA.z); bb[3]=pk(bA.w,bA.w);
            bb[4]=pk(bB.x,bB.x); bb[5]=pk(bB.y,bB.y); bb[6]=pk(bB.z,bB.z); bb[7]=pk(bB.w,bB.w);
            u64 aa[4] = { av0.x, av0.y, av1.x, av1.y };
            #pragma unroll
            for (int i2=0;i2<4;i2++)
                #pragma unroll
                for (int j=0;j<8;j++) fma2(acc[i2][j], aa[i2], bb[j]);
        }
    }
    float bv[8];
    #pragma unroll
    for (int j=0;j<8;j++){
        int n = n0+ty*8+j;
        bv[j] = bias0[n] + bias1[n];
    }
    __syncthreads();
    #pragma unroll
    for (int j=0;j<8;j++){
        float r[8];
        #pragma unroll
        for (int i2=0;i2<4;i2++){ unpk(acc[i2][j], r[2*i2], r[2*i2+1]); }
        #pragma unroll
        for (int v=0;v<8;v++) r[v] += bv[j];
        float* cp = csh + (size_t)(ty*8+j)*132 + tx*8;
        *(float4*)cp     = make_float4(r[0],r[1],r[2],r[3]);
        *(float4*)(cp+4) = make_float4(r[4],r[5],r[6],r[7]);
    }
    __syncthreads();
    {
        int jl = tid>>1, half = (tid&1)*64;
        const float* src = csh + (size_t)jl*132 + half;
        float* dst = Ct + ((size_t)tt*G + n0 + jl)*NS + s0 + half;
        #pragma unroll
        for (int v=0;v<16;v++)
            *(float4*)(dst + v*4) = *(const float4*)(src + v*4);
    }
}

// ---- plain NT gemm (gx1b), C[m][n] layout ----
__global__ __launch_bounds__(256,2)
void gemm_nt128(const float* __restrict__ A, int lda,
                const float* __restrict__ B, int ldb,
                float* __restrict__ C, int ldc, int K,
                const float* __restrict__ bias0, const float* __restrict__ bias1)
{
    __shared__ __align__(16) float As[16][136];
    __shared__ __align__(16) float Bs[16][136];
    const int m0 = blockIdx.x*128, n0 = blockIdx.y*128;
    const int tid = threadIdx.x;
    const int ty = tid>>4, tx = tid&15;
    const int row = tid>>1, kq = (tid&1)*8;
    u64 acc[4][8];
    #pragma unroll
    for (int i=0;i<4;i++)
        #pragma unroll
        for (int j=0;j<8;j++) acc[i][j]=0ull;

    for (int k0=0;k0<K;k0+=16){
        float4 a0 = *(const float4*)(A + (size_t)(m0+row)*lda + k0 + kq);
        float4 a1 = *(const float4*)(A + (size_t)(m0+row)*lda + k0 + kq + 4);
        float4 b0 = *(const float4*)(B + (size_t)(n0+row)*ldb + k0 + kq);
        float4 b1 = *(const float4*)(B + (size_t)(n0+row)*ldb + k0 + kq + 4);
        __syncthreads();
        As[kq+0][row]=a0.x; As[kq+1][row]=a0.y; As[kq+2][row]=a0.z; As[kq+3][row]=a0.w;
        As[kq+4][row]=a1.x; As[kq+5][row]=a1.y; As[kq+6][row]=a1.z; As[kq+7][row]=a1.w;
        Bs[kq+0][row]=b0.x; Bs[kq+1][row]=b0.y; Bs[kq+2][row]=b0.z; Bs[kq+3][row]=b0.w;
        Bs[kq+4][row]=b1.x; Bs[kq+5][row]=b1.y; Bs[kq+6][row]=b1.z; Bs[kq+7][row]=b1.w;
        __syncthreads();
        #pragma unroll
        for (int k=0;k<16;k++){
            ulonglong2 av0 = *(const ulonglong2*)&As[k][ty*8];
            ulonglong2 av1 = *(const ulonglong2*)&As[k][ty*8+4];
            float4 bA = *(const float4*)&Bs[k][tx*8];
            float4 bB = *(const float4*)&Bs[k][tx*8+4];
            u64 bb[8];
            bb[0]=pk(bA.x,bA.x); bb[1]=pk(bA.y,bA.y); bb[2]=pk(bA.z,bA.z); bb[3]=pk(bA.w,bA.w);
            bb[4]=pk(bB.x,bB.x); bb[5]=pk(bB.y,bB.y); bb[6]=pk(bB.z,bB.z); bb[7]=pk(bB.w,bB.w);
            u64 aa[4] = { av0.x, av0.y, av1.x, av1.y };
            #pragma unroll
            for (int i2=0;i2<4;i2++)
                #pragma unroll
                for (int j=0;j<8;j++) fma2(acc[i2][j], aa[i2], bb[j]);
        }
    }
    float bv[8];
    #pragma unroll
    for (int j=0;j<8;j++){
        int n = n0+tx*8+j;
        float v = 0.f;
        if (bias0) v += bias0[n];
        if (bias1) v += bias1[n];
        bv[j]=v;
    }
    #pragma unroll
    for (int i2=0;i2<4;i2++){
        float r0[8], r1[8];
        #pragma unroll
        for (int j=0;j<8;j++){ unpk(acc[i2][j], r0[j], r1[j]); r0[j]+=bv[j]; r1[j]+=bv[j]; }
        float* c0 = C + (size_t)(m0+ty*8+2*i2)*ldc + n0 + tx*8;
        float* c1 = C + (size_t)(m0+ty*8+2*i2+1)*ldc + n0 + tx*8;
        *(float4*)c0     = make_float4(r0[0],r0[1],r0[2],r0[3]);
        *(float4*)(c0+4) = make_float4(r0[4],r0[5],r0[6],r0[7]);
        *(float4*)c1     = make_float4(r1[0],r1[1],r1[2],r1[3]);
        *(float4*)(c1+4) = make_float4(r1[4],r1[5],r1[6],r1[7]);
    }
}

// ---- C[m][n] = sum_k A[m][k]*B[k][n] (+addC), 64x64 tile, 4x4 micro.
__global__ __launch_bounds__(256,1)
void gemm_nn64(const float* __restrict__ A, int lda,
               const float* __restrict__ B, int ldb,
               float* __restrict__ C, int ldc, int K,
               const float* __restrict__ addC)
{
    __shared__ __align__(16) float As[16][68];
    __shared__ __align__(16) float Bs[16][68];
    const int m0 = blockIdx.x*64, n0 = blockIdx.y*64;
    const int tid = threadIdx.x;
    const int ty = tid>>4, tx = tid&15;
    const int arow = tid>>2, akq = (tid&3)*4;
    const int bk = tid>>4, bnq = (tid&15)*4;
    float acc[4][4];
    #pragma unroll
    for (int i=0;i<4;i++)
        #pragma unroll
        for (int j=0;j<4;j++) acc[i][j]=0.f;

    for (int k0=0;k0<K;k0+=16){
        float4 av = *(const float4*)(A + (size_t)(m0+arow)*lda + k0 + akq);
        float4 bv = *(const float4*)(B + (size_t)(k0+bk)*ldb + n0 + bnq);
        __syncthreads();
        As[akq+0][arow]=av.x; As[akq+1][arow]=av.y; As[akq+2][arow]=av.z; As[akq+3][arow]=av.w;
        *(float4*)&Bs[bk][bnq] = bv;
        __syncthreads();
        #pragma unroll
        for (int k=0;k<16;k++){
            float a[4],b[4];
            #pragma unroll
            for (int i=0;i<4;i++){ a[i]=As[k][ty*4+i]; b[i]=Bs[k][tx*4+i]; }
            #pragma unroll
            for (int i=0;i<4;i++)
                #pragma unroll
                for (int j=0;j<4;j++) acc[i][j]+=a[i]*b[j];
        }
    }
    #pragma unroll
    for (int i=0;i<4;i++){
        int m = m0+ty*4+i;
        float* cp = C + (size_t)m*ldc + n0 + tx*4;
        const float* ap = addC ? addC + (size_t)m*ldc + n0 + tx*4 : (const float*)0;
        #pragma unroll
        for (int j=0;j<4;j++){
            float v = acc[i][j];
            if (ap) v += ap[j];
            cp[j] = v;
        }
    }
}

// ---- cluster LSTM recurrence, 768 threads, retiled:
// thread = (1 unit x 4 gates) x SPT stocks. Lanes 0-15 = stock base, lane
// bit4 selects the warp's 2nd unit. Per k-iter: 4 B-LDS + SPT h-LDS for
// 4*SPT*2 FMA2. gx LDGs issued in the cluster-barrier shadow.
// SPC = 16*SPT stocks per cluster. mode = mode0 + blockIdx.y.
template<int SPT>
__global__ __launch_bounds__(768,1) __cluster_dims__(4,1,1)
void lstm_cluster(const float* __restrict__ gx_all, const float* __restrict__ Whh_all,
                  float* __restrict__ outp, int mode0)
{
    constexpr int SPC = 16*SPT;
    constexpr int HSP = 196;
    constexpr int BSP = 196;
    extern __shared__ float sm[];
    float* Bsh = sm;                   // [192][BSP]  rank's 48 units x 4 gates
    float* Hs  = sm + 192*BSP;         // [SPC][HSP]

    const int dir  = blockIdx.y;
    const int mode = mode0 + dir;
    const float* gx  = gx_all  + (size_t)dir*NS*T*G;
    const float* Whh = Whh_all + (size_t)dir*G*H;

    const int tid  = threadIdx.x;
    const int l    = tid & 31;
    const int w    = tid >> 5;          // 0..23
    const int sl0  = l & 15;            // stock lane base
    const int ul   = 2*w + (l>>4);      // local unit 0..47
    uint32_t rank; asm("mov.u32 %0, %%cluster_ctarank;" : "=r"(rank));
    const int cid   = blockIdx.x >> 2;
    const int sbase = cid * SPC;
    const int jsl   = (int)rank * 48;
    const uint32_t hs_base = smem_u32(Hs);

    // stage Whh slice once: local row lr = q*48+u <- global row q*192+jsl+u
    for (int i = tid; i < 192*48; i += 768){
        int lr = i / 48, c4 = i % 48;
        int q = lr / 48, u = lr % 48;
        float4 v = *(const float4*)(Whh + (size_t)(q*192 + jsl + u)*H + c4*4);
        *(float4*)(Bsh + lr*BSP + c4*4) = v;
    }
    for (int i = tid; i < SPC*HSP; i += 768) Hs[i] = 0.f;
    CL_ARRIVE(); CL_WAIT();

    float c[SPT];
    #pragma unroll
    for (int b=0;b<SPT;b++) c[b]=0.f;

    for (int step=0; step<T; ++step){
        const int tt = (mode==1) ? (T-1-step) : step;

        u64 acc[4][SPT];
        #pragma unroll
        for (int q=0;q<4;q++)
            #pragma unroll
            for (int ss=0;ss<SPT;ss++) acc[q][ss]=0ull;

        #pragma unroll 2
        for (int k=0;k<192;k+=4){
            u64 ha[SPT], hb[SPT];
            #pragma unroll
            for (int ss=0;ss<SPT;ss++){
                ulonglong2 hv4 = *(const ulonglong2*)(Hs + (sl0 + 16*ss)*HSP + k);
                ha[ss]=hv4.x; hb[ss]=hv4.y;
            }
            #pragma unroll
            for (int q=0;q<4;q++){
                ulonglong2 bv = *(const ulonglong2*)(Bsh + (q*48 + ul)*BSP + k);
                #pragma unroll
                for (int ss=0;ss<SPT;ss++){
                    fma2(acc[q][ss], ha[ss], bv.x);
                    fma2(acc[q][ss], hb[ss], bv.y);
                }
            }
        }
        float pre[4][SPT];
        #pragma unroll
        for (int q=0;q<4;q++)
            #pragma unroll
            for (int ss=0;ss<SPT;ss++) pre[q][ss] = lohi(acc[q][ss]);

        CL_ARRIVE();                   // my reads of Hs(t-1) done
        // gx loads hidden in the barrier shadow
        float gxr[4][SPT];
        #pragma unroll
        for (int q=0;q<4;q++)
            #pragma unroll
            for (int ss=0;ss<SPT;ss++)
                gxr[q][ss] = gx[((size_t)tt*G + q*192 + jsl + ul)*NS
                                + sbase + sl0 + 16*ss];
        CL_WAIT();                     // all CTAs' reads done -> safe to write

        float hv[SPT];
        #pragma unroll
        for (int ss=0;ss<SPT;ss++){
            float iv = sigm(pre[0][ss] + gxr[0][ss]);
            float fv = sigm(pre[1][ss] + gxr[1][ss]);
            float gv = tanhf(pre[2][ss] + gxr[2][ss]);
            float ov = sigm(pre[3][ss] + gxr[3][ss]);
            float cc = fv*c[ss] + iv*gv;
            c[ss] = cc;
            hv[ss] = ov*tanhf(cc);
        }
        #pragma unroll
        for (int ss=0;ss<SPT;ss++){
            int sl = sl0 + 16*ss;
            uint32_t la = hs_base + (uint32_t)(sl*HSP + jsl + ul)*4u;
            float v = hv[ss];
            Hs[sl*HSP + jsl + ul] = v;
            #pragma unroll
            for (int r=0;r<4;r++){
                if (r == (int)rank) continue;
                uint32_t da; asm("mapa.shared::cluster.u32 %0,%1,%2;":"=r"(da):"r"(la),"r"(r));
                asm volatile("st.shared::cluster.f32 [%0],%1;"::"r"(da),"f"(v));
            }
        }
        CL_ARRIVE();                   // release h(t) writes
        if (mode==0 || mode==1){
            #pragma unroll
            for (int ss=0;ss<SPT;ss++){
                int s = sbase + sl0 + 16*ss;
                outp[((size_t)s*T + tt)*384 + (mode==1?192:0) + jsl + ul] = hv[ss];
            }
        } else if (step==T-1){
            #pragma unroll
            for (int ss=0;ss<SPT;ss++){
                int s = sbase + sl0 + 16*ss;
                outp[(size_t)s*384 + jsl + ul] = hv[ss];
            }
        }
        CL_WAIT();                     // acquire peers' h(t)
    }
}

// ---- layer1 bwd @ t=31 only (h0=c0=0) ----
__global__ void bwd1_last(const float* __restrict__ gxb, float* __restrict__ h2)
{
    int n = blockIdx.x, j = threadIdx.x;
    const float* g = gxb + (size_t)n*G;
    float iv = sigm(g[j]);
    float gv = tanhf(g[2*H+j]);
    float ov = sigm(g[3*H+j]);
    float cc = iv*gv;
    h2[(size_t)n*384 + 192 + j] = ov*tanhf(cc);
}

// ---- dynamic network ----
__global__ void dyn_scalars(const float* __restrict__ x, const float* __restrict__ theta,
                            int* __restrict__ pid, int* __restrict__ off)
{
    int n = blockIdx.x*blockDim.x + threadIdx.x;
    if (n >= NS) return;
    float th  = theta[n];
    float x30 = x[((size_t)n*T + 30)*NF];
    float x31 = x[((size_t)n*T + 31)*NF];
    int p0 = (x30 > th) ? 1 : ((x30 < -th) ? -1 : 0);
    int p1 = (x31 > th) ? 1 : ((x31 < -th) ? -1 : 0);
    pid[n] = (p0+1)*3 + (p1+1);
    off[n] = (p1+1)*3;
}

__global__ __launch_bounds__(256,1)
void dyn_beta(const float* __restrict__ PP, const int* __restrict__ pid,
              const int* __restrict__ off, float* __restrict__ BetaT,
              float* __restrict__ t3)
{
    __shared__ float s_raw[1024];
    __shared__ float s_adj[1024*3];
    __shared__ float s_red[256];
    const int y = blockIdx.x, tid = threadIdx.x;
    const int offy = off[y];
    for (int x=tid; x<NS; x+=256){
        size_t base = ((size_t)x*NS + y)*81 + (size_t)pid[x]*9 + offy;
        float a0=PP[base], a1=PP[base+1], a2=PP[base+2];
        s_adj[x*3+0]=a0; s_adj[x*3+1]=a1; s_adj[x*3+2]=a2;
        float nr = sqrtf(a0*a0+a1*a1+a2*a2);
        s_raw[x] = (nr > 0.38f) ? nr : 0.f;
    }
    __syncthreads();
    float lm = -1e30f;
    for (int x=tid; x<NS; x+=256) lm = fmaxf(lm, s_raw[x]);
    s_red[tid]=lm; __syncthreads();
    for (int o=128;o>0;o>>=1){ if(tid<o) s_red[tid]=fmaxf(s_red[tid],s_red[tid+o]); __syncthreads(); }
    const float mx = s_red[0];
    __syncthreads();
    float ls = 0.f;
    for (int x=tid; x<NS; x+=256){ float e=expf(s_raw[x]-mx); s_raw[x]=e; ls+=e; }
    s_red[tid]=ls; __syncthreads();
    for (int o=128;o>0;o>>=1){ if(tid<o) s_red[tid]+=s_red[tid+o]; __syncthreads(); }
    const float inv = 1.f/s_red[0];
    __syncthreads();
    float t0=0.f,t1=0.f,t2=0.f;
    for (int x=tid; x<NS; x+=256){
        float b = s_raw[x]*inv;
        BetaT[(size_t)y*NS + x] = b;
        t0 += b*s_adj[x*3+0]; t1 += b*s_adj[x*3+1]; t2 += b*s_adj[x*3+2];
    }
    s_red[tid]=t0; __syncthreads();
    for (int o=128;o>0;o>>=1){ if(tid<o) s_red[tid]+=s_red[tid+o]; __syncthreads(); }
    if(tid==0) t3[y*3+0]=s_red[0];
    __syncthreads();
    s_red[tid]=t1; __syncthreads();
    for (int o=128;o>0;o>>=1){ if(tid<o) s_red[tid]+=s_red[tid+o]; __syncthreads(); }
    if(tid==0) t3[y*3+1]=s_red[0];
    __syncthreads();
    s_red[tid]=t2; __syncthreads();
    for (int o=128;o>0;o>>=1){ if(tid<o) s_red[tid]+=s_red[tid+o]; __syncthreads(); }
    if(tid==0) t3[y*3+2]=s_red[0];
}

__global__ void agg_extra(const float* __restrict__ t3, const float* __restrict__ Wa,
                          const float* __restrict__ b, float* __restrict__ E)
{
    int y = blockIdx.x, u = threadIdx.x;
    float v = b[u] + t3[y*3+0]*Wa[u] + t3[y*3+1]*Wa[128+u] + t3[y*3+2]*Wa[256+u];
    E[(size_t)y*128 + u] = v;
}

__global__ void out_kernel(const float* __restrict__ nfeat, const float* __restrict__ n1,
                           const float* __restrict__ n2, const float* __restrict__ W,
                           const float* __restrict__ b, float* __restrict__ out)
{
    int warp = (blockIdx.x*blockDim.x + threadIdx.x)>>5;
    int lane = threadIdx.x & 31;
    if (warp >= NS*2) return;
    int n = warp>>1, o = warp&1;
    float s = 0.f;
    for (int k=lane;k<384;k+=32) s += nfeat[(size_t)n*384+k]*W[k*2+o];
    for (int k=lane;k<128;k+=32) s += n1[(size_t)n*128+k]*W[(384+k)*2+o];
    for (int k=lane;k<128;k+=32) s += n2[(size_t)n*128+k]*W[(512+k)*2+o];
    #pragma unroll
    for (int m=16;m>0;m>>=1) s += __shfl_xor_sync(0xffffffffu, s, m);
    if (lane==0) out[warp] = tanhf(s + b[o]);
}

extern "C" void kernel_launch(void* const* d_in, const int* in_sizes, int n_in,
                              void* d_out, int out_size)
{
    const float* x     = (const float*)d_in[0];
    const float* theta = (const float*)d_in[1];
    const float* PP    = (const float*)d_in[2];
    const float* Wih0  = (const float*)d_in[3];
    const float* Whh0  = (const float*)d_in[4];
    const float* bih0  = (const float*)d_in[5];
    const float* bhh0  = (const float*)d_in[6];
    const float* Wih1  = (const float*)d_in[7];
    const float* Whh1  = (const float*)d_in[8];
    const float* bih1  = (const float*)d_in[9];
    const float* bhh1  = (const float*)d_in[10];
    const float* Wagg1 = (const float*)d_in[11];
    const float* bagg1 = (const float*)d_in[12];
    const float* Wagg2 = (const float*)d_in[13];
    const float* bagg2 = (const float*)d_in[14];
    const float* Wout  = (const float*)d_in[15];
    const float* bout  = (const float*)d_in[16];
    float* out = (float*)d_out;

    float *p_gx0, *p_gx1, *p_gx1b, *p_h1, *p_h2, *p_BetaT, *p_t3, *p_M, *p_E, *p_n1, *p_n2;
    int *p_pid, *p_off;
    cudaGetSymbolAddress((void**)&p_gx0,  g_gx0);
    cudaGetSymbolAddress((void**)&p_gx1,  g_gx1);
    cudaGetSymbolAddress((void**)&p_gx1b, g_gx1b);
    cudaGetSymbolAddress((void**)&p_h1,   g_h1);
    cudaGetSymbolAddress((void**)&p_h2,   g_h2);
    cudaGetSymbolAddress((void**)&p_BetaT,g_BetaT);
    cudaGetSymbolAddress((void**)&p_t3,   g_t3);
    cudaGetSymbolAddress((void**)&p_pid,  g_pid);
    cudaGetSymbolAddress((void**)&p_off,  g_off);
    cudaGetSymbolAddress((void**)&p_M,    g_M);
    cudaGetSymbolAddress((void**)&p_E,    g_E);
    cudaGetSymbolAddress((void**)&p_n1,   g_n1);
    cudaGetSymbolAddress((void**)&p_n2,   g_n2);

    const int SM64 = (192*196 + 64*196)*4;   // 200704 B
    const int SM32 = (192*196 + 32*196)*4;   // 175616 B
    const int CSH  = 128*132*4;              // 67584 B
    cudaFuncSetAttribute(lstm_cluster<4>, cudaFuncAttributeMaxDynamicSharedMemorySize, SM64);
    cudaFuncSetAttribute(lstm_cluster<2>, cudaFuncAttributeMaxDynamicSharedMemorySize, SM32);
    cudaFuncSetAttribute(gemm_nt128T, cudaFuncAttributeMaxDynamicSharedMemorySize, CSH);

    // #1-2: layer0 gx, time-major, both dirs
    for (int d=0; d<2; d++){
        gemm_nt128T<<<dim3(256,6), 256, CSH>>>(x, NF, Wih0 + (size_t)d*G*NF, NF,
                                               p_gx0 + (size_t)d*NS*T*G, NF,
                                               bih0 + d*G, bhh0 + d*G);
    }
    // #3: tiny independent kernel (profile slot alignment)
    dyn_scalars<<<4, 256>>>(x, theta, p_pid, p_off);

    // #4: layer0 recurrence, fwd+bwd — profiled slot
    lstm_cluster<4><<<dim3(64,2), 768, SM64>>>(p_gx0, Whh0, p_h1, 0);

    // #5: dynamic network main
    dyn_beta<<<NS, 256>>>(PP, p_pid, p_off, p_BetaT, p_t3);

    // #6: layer1 fwd gx, time-major
    gemm_nt128T<<<dim3(256,6), 256, CSH>>>(p_h1, 384, Wih1, 384, p_gx1, 384,
                                           bih1, bhh1);
    // #7: layer1 bwd gx at t=31 only ([s][j] layout)
    gemm_nt128<<<dim3(8,6), 256>>>(p_h1 + 31*384, T*384, Wih1 + (size_t)G*384, 384,
                                   p_gx1b, G, 384, bih1 + G, bhh1 + G);

    // #8-9: layer1 recurrence fwd; bwd single step
    lstm_cluster<2><<<dim3(128,1), 768, SM32>>>(p_gx1, Whh1, p_h2, 2);
    bwd1_last<<<NS, H>>>(p_gx1b, p_h2);

    // #10-12: agg layer 1
    agg_extra<<<NS, 128>>>(p_t3, Wagg1 + (size_t)384*128, bagg1, p_E);
    gemm_nn64<<<dim3(16,2), 256>>>(p_h2, 384, Wagg1, 128, p_M, 128, 384, (const float*)0);
    gemm_nn64<<<dim3(16,2), 256>>>(p_BetaT, NS, p_M, 128, p_n1, 128, NS, p_E);

    // #13-15: agg layer 2
    gemm_nn64<<<dim3(16,2), 256>>>(p_n1, 128, Wagg2, 128, p_M, 128, 128, (const float*)0);
    agg_extra<<<NS, 128>>>(p_t3, Wagg2 + (size_t)128*128, bagg2, p_E);
    gemm_nn64<<<dim3(16,2), 256>>>(p_BetaT, NS, p_M, 128, p_n2, 128, NS, p_E);

    // #16: output
    out_kernel<<<256, 256>>>(p_h2, p_n1, p_n2, Wout, bout, out);
}

// round 10
// speedup vs baseline: 1.1922x; 1.0164x over previous
#include <cuda_runtime.h>
#include <math.h>
#include <stdint.h>

#define NS 1024
#define T  32
#define NF 16
#define H  192
#define G  768

typedef unsigned long long u64;

static __device__ float g_gx0[(size_t)2*NS*T*G];   // time-major: [dir][tt][G][NS]
static __device__ float g_gx1[(size_t)NS*T*G];     // time-major: [tt][G][NS]
static __device__ float g_gx1b[(size_t)NS*G];      // [s][G]
static __device__ float g_h1[(size_t)NS*T*384];    // [s][tt][384]
static __device__ float g_h2[(size_t)NS*384];
static __device__ float g_BetaT[(size_t)NS*NS];
static __device__ float g_t3[NS*3];
static __device__ int   g_pid[NS];
static __device__ int   g_off[NS];
static __device__ float g_M[NS*128];
static __device__ float g_E[NS*128];
static __device__ float g_n1[NS*128];
static __device__ float g_n2[NS*128];

__device__ __forceinline__ float sigm(float x){ return 1.f/(1.f+expf(-x)); }
__device__ __forceinline__ u64 pk(float x, float y){ u64 r; asm("mov.b64 %0,{%1,%2};":"=l"(r):"f"(x),"f"(y)); return r; }
__device__ __forceinline__ void fma2(u64& d, u64 a, u64 b){ asm("fma.rn.f32x2 %0,%1,%2,%0;":"+l"(d):"l"(a),"l"(b)); }
__device__ __forceinline__ void unpk(u64 v, float& x, float& y){ asm("mov.b64 {%0,%1},%2;":"=f"(x),"=f"(y):"l"(v)); }
__device__ __forceinline__ float lohi(u64 v){ float x,y; unpk(v,x,y); return x+y; }
__device__ __forceinline__ uint32_t smem_u32(const void* p){
    uint32_t a; asm("{ .reg .u64 t; cvta.to.shared.u64 t, %1; cvt.u32.u64 %0, t; }":"=r"(a):"l"(p)); return a;
}
#define CL_ARRIVE() asm volatile("barrier.cluster.arrive.aligned;" ::: "memory")
#define CL_WAIT()   asm volatile("barrier.cluster.wait.aligned;"   ::: "memory")

// ---- transposing gx GEMM, double-buffered:
// Ct[tt][n][s] = sum_k A[s][tt][k]*B[n][k] + bias0[n] + bias1[n]
__global__ __launch_bounds__(256,2)
void gemm_nt128T(const float* __restrict__ A, int lda,
                 const float* __restrict__ B, int ldb,
                 float* __restrict__ Ct, int K,
                 const float* __restrict__ bias0, const float* __restrict__ bias1)
{
    extern __shared__ __align__(16) float csh[];   // [128][132]
    __shared__ __align__(16) float As[2][16][136];
    __shared__ __align__(16) float Bs[2][16][136];
    const int tt = blockIdx.x >> 3;
    const int s0 = (blockIdx.x & 7) * 128;
    const int n0 = blockIdx.y * 128;
    const int tid = threadIdx.x;
    const int ty = tid>>4, tx = tid&15;
    const int row = tid>>1, kq = (tid&1)*8;
    const float* aBase = A + ((size_t)(s0+row)*T + tt)*lda + kq;
    const float* bBase = B + (size_t)(n0+row)*ldb + kq;
    u64 acc[4][8];
    #pragma unroll
    for (int i=0;i<4;i++)
        #pragma unroll
        for (int j=0;j<8;j++) acc[i][j]=0ull;

    float4 a0 = *(const float4*)(aBase);
    float4 a1 = *(const float4*)(aBase+4);
    float4 b0 = *(const float4*)(bBase);
    float4 b1 = *(const float4*)(bBase+4);
    As[0][kq+0][row]=a0.x; As[0][kq+1][row]=a0.y; As[0][kq+2][row]=a0.z; As[0][kq+3][row]=a0.w;
    As[0][kq+4][row]=a1.x; As[0][kq+5][row]=a1.y; As[0][kq+6][row]=a1.z; As[0][kq+7][row]=a1.w;
    Bs[0][kq+0][row]=b0.x; Bs[0][kq+1][row]=b0.y; Bs[0][kq+2][row]=b0.z; Bs[0][kq+3][row]=b0.w;
    Bs[0][kq+4][row]=b1.x; Bs[0][kq+5][row]=b1.y; Bs[0][kq+6][row]=b1.z; Bs[0][kq+7][row]=b1.w;
    __syncthreads();

    int buf = 0;
    for (int k0=0;k0<K;k0+=16){
        const bool nxt = (k0+16)<K;
        if (nxt){
            a0 = *(const float4*)(aBase + k0+16);
            a1 = *(const float4*)(aBase + k0+20);
            b0 = *(const float4*)(bBase + k0+16);
            b1 = *(const float4*)(bBase + k0+20);
        }
        #pragma unroll
        for (int k=0;k<16;k++){
            ulonglong2 av0 = *(const ulonglong2*)&As[buf][k][tx*8];
            ulonglong2 av1 = *(const ulonglong2*)&As[buf][k][tx*8+4];
            float4 bA = *(const float4*)&Bs[buf][k][ty*8];
            float4 bB = *(const float4*)&Bs[buf][k][ty*8+4];
            u64 bb[8];
            bb[0]=pk(bA.x,bA.x); bb[1]=pk(bA.y,bA.y); bb[2]=pk(bA.z,bA.z); bb[3]=pk(bA.w,bA.w);
            bb[4]=pk(bB.x,bB.x); bb[5]=pk(bB.y,bB.y); bb[6]=pk(bB.z,bB.z); bb[7]=pk(bB.w,bB.w);
            u64 aa[4] = { av0.x, av0.y, av1.x, av1.y };
            #pragma unroll
            for (int i2=0;i2<4;i2++)
                #pragma unroll
                for (int j=0;j<8;j++) fma2(acc[i2][j], aa[i2], bb[j]);
        }
        if (nxt){
            int nb = buf^1;
            As[nb][kq+0][row]=a0.x; As[nb][kq+1][row]=a0.y; As[nb][kq+2][row]=a0.z; As[nb][kq+3][row]=a0.w;
            As[nb][kq+4][row]=a1.x; As[nb][kq+5][row]=a1.y; As[nb][kq+6][row]=a1.z; As[nb][kq+7][row]=a1.w;
            Bs[nb][kq+0][row]=b0.x; Bs[nb][kq+1][row]=b0.y; Bs[nb][kq+2][row]=b0.z; Bs[nb][kq+3][row]=b0.w;
            Bs[nb][kq+4][row]=b1.x; Bs[nb][kq+5][row]=b1.y; Bs[nb][kq+6][row]=b1.z; Bs[nb][kq+7][row]=b1.w;
            __syncthreads();
            buf = nb;
        }
    }
    float bv[8];
    #pragma unroll
    for (int j=0;j<8;j++){
        int n = n0+ty*8+j;
        bv[j] = bias0[n] + bias1[n];
    }
    __syncthreads();
    #pragma unroll
    for (int j=0;j<8;j++){
        float r[8];
        #pragma unroll
        for (int i2=0;i2<4;i2++){ unpk(acc[i2][j], r[2*i2], r[2*i2+1]); }
        #pragma unroll
        for (int v=0;v<8;v++) r[v] += bv[j];
        float* cp = csh + (size_t)(ty*8+j)*132 + tx*8;
        *(float4*)cp     = make_float4(r[0],r[1],r[2],r[3]);
        *(float4*)(cp+4) = make_float4(r[4],r[5],r[6],r[7]);
    }
    __syncthreads();
    {
        int jl = tid>>1, half = (tid&1)*64;
        const float* src = csh + (size_t)jl*132 + half;
        float* dst = Ct + ((size_t)tt*G + n0 + jl)*NS + s0 + half;
        #pragma unroll
        for (int v=0;v<16;v++)
            *(float4*)(dst + v*4) = *(const float4*)(src + v*4);
    }
}

// ---- plain NT gemm (gx1b), C[m][n] layout ----
__global__ __launch_bounds__(256,2)
void gemm_nt128(const float* __restrict__ A, int lda,
                const float* __restrict__ B, int ldb,
                float* __restrict__ C, int ldc, int K,
                const float* __restrict__ bias0, const float* __restrict__ bias1)
{
    __shared__ __align__(16) float As[16][136];
    __shared__ __align__(16) float Bs[16][136];
    const int m0 = blockIdx.x*128, n0 = blockIdx.y*128;
    const int tid = threadIdx.x;
    const int ty = tid>>4, tx = tid&15;
    const int row = tid>>1, kq = (tid&1)*8;
    u64 acc[4][8];
    #pragma unroll
    for (int i=0;i<4;i++)
        #pragma unroll
        for (int j=0;j<8;j++) acc[i][j]=0ull;

    for (int k0=0;k0<K;k0+=16){
        float4 a0 = *(const float4*)(A + (size_t)(m0+row)*lda + k0 + kq);
        float4 a1 = *(const float4*)(A + (size_t)(m0+row)*lda + k0 + kq + 4);
        float4 b0 = *(const float4*)(B + (size_t)(n0+row)*ldb + k0 + kq);
        float4 b1 = *(const float4*)(B + (size_t)(n0+row)*ldb + k0 + kq + 4);
        __syncthreads();
        As[kq+0][row]=a0.x; As[kq+1][row]=a0.y; As[kq+2][row]=a0.z; As[kq+3][row]=a0.w;
        As[kq+4][row]=a1.x; As[kq+5][row]=a1.y; As[kq+6][row]=a1.z; As[kq+7][row]=a1.w;
        Bs[kq+0][row]=b0.x; Bs[kq+1][row]=b0.y; Bs[kq+2][row]=b0.z; Bs[kq+3][row]=b0.w;
        Bs[kq+4][row]=b1.x; Bs[kq+5][row]=b1.y; Bs[kq+6][row]=b1.z; Bs[kq+7][row]=b1.w;
        __syncthreads();
        #pragma unroll
        for (int k=0;k<16;k++){
            ulonglong2 av0 = *(const ulonglong2*)&As[k][ty*8];
            ulonglong2 av1 = *(const ulonglong2*)&As[k][ty*8+4];
            float4 bA = *(const float4*)&Bs[k][tx*8];
            float4 bB = *(const float4*)&Bs[k][tx*8+4];
            u64 bb[8];
            bb[0]=pk(bA.x,bA.x); bb[1]=pk(bA.y,bA.y); bb[2]=pk(bA.z,bA.z); bb[3]=pk(bA.w,bA.w);
            bb[4]=pk(bB.x,bB.x); bb[5]=pk(bB.y,bB.y); bb[6]=pk(bB.z,bB.z); bb[7]=pk(bB.w,bB.w);
            u64 aa[4] = { av0.x, av0.y, av1.x, av1.y };
            #pragma unroll
            for (int i2=0;i2<4;i2++)
                #pragma unroll
                for (int j=0;j<8;j++) fma2(acc[i2][j], aa[i2], bb[j]);
        }
    }
    float bv[8];
    #pragma unroll
    for (int j=0;j<8;j++){
        int n = n0+tx*8+j;
        float v = 0.f;
        if (bias0) v += bias0[n];
        if (bias1) v += bias1[n];
        bv[j]=v;
    }
    #pragma unroll
    for (int i2=0;i2<4;i2++){
        float r0[8], r1[8];
        #pragma unroll
        for (int j=0;j<8;j++){ unpk(acc[i2][j], r0[j], r1[j]); r0[j]+=bv[j]; r1[j]+=bv[j]; }
        float* c0 = C + (size_t)(m0+ty*8+2*i2)*ldc + n0 + tx*8;
        float* c1 = C + (size_t)(m0+ty*8+2*i2+1)*ldc + n0 + tx*8;
        *(float4*)c0     = make_float4(r0[0],r0[1],r0[2],r0[3]);
        *(float4*)(c0+4) = make_float4(r0[4],r0[5],r0[6],r0[7]);
        *(float4*)c1     = make_float4(r1[0],r1[1],r1[2],r1[3]);
        *(float4*)(c1+4) = make_float4(r1[4],r1[5],r1[6],r1[7]);
    }
}

// ---- C[m][n] = sum_k A[m][k]*B[k][n] (+addC), 64x64 tile, 4x4 micro.
__global__ __launch_bounds__(256,1)
void gemm_nn64(const float* __restrict__ A, int lda,
               const float* __restrict__ B, int ldb,
               float* __restrict__ C, int ldc, int K,
               const float* __restrict__ addC)
{
    __shared__ __align__(16) float As[16][68];
    __shared__ __align__(16) float Bs[16][68];
    const int m0 = blockIdx.x*64, n0 = blockIdx.y*64;
    const int tid = threadIdx.x;
    const int ty = tid>>4, tx = tid&15;
    const int arow = tid>>2, akq = (tid&3)*4;
    const int bk = tid>>4, bnq = (tid&15)*4;
    float acc[4][4];
    #pragma unroll
    for (int i=0;i<4;i++)
        #pragma unroll
        for (int j=0;j<4;j++) acc[i][j]=0.f;

    for (int k0=0;k0<K;k0+=16){
        float4 av = *(const float4*)(A + (size_t)(m0+arow)*lda + k0 + akq);
        float4 bv = *(const float4*)(B + (size_t)(k0+bk)*ldb + n0 + bnq);
        __syncthreads();
        As[akq+0][arow]=av.x; As[akq+1][arow]=av.y; As[akq+2][arow]=av.z; As[akq+3][arow]=av.w;
        *(float4*)&Bs[bk][bnq] = bv;
        __syncthreads();
        #pragma unroll
        for (int k=0;k<16;k++){
            float a[4],b[4];
            #pragma unroll
            for (int i=0;i<4;i++){ a[i]=As[k][ty*4+i]; b[i]=Bs[k][tx*4+i]; }
            #pragma unroll
            for (int i=0;i<4;i++)
                #pragma unroll
                for (int j=0;j<4;j++) acc[i][j]+=a[i]*b[j];
        }
    }
    #pragma unroll
    for (int i=0;i<4;i++){
        int m = m0+ty*4+i;
        float* cp = C + (size_t)m*ldc + n0 + tx*4;
        const float* ap = addC ? addC + (size_t)m*ldc + n0 + tx*4 : (const float*)0;
        #pragma unroll
        for (int j=0;j<4;j++){
            float v = acc[i][j];
            if (ap) v += ap[j];
            cp[j] = v;
        }
    }
}

// ---- cluster LSTM (2-barrier, R9-proven): thread = 1 unit x 4 gates x SPT stocks.
template<int SPT>
__global__ __launch_bounds__(768,1) __cluster_dims__(4,1,1)
void lstm_cluster(const float* __restrict__ gx_all, const float* __restrict__ Whh_all,
                  float* __restrict__ outp, int mode0)
{
    constexpr int SPC = 16*SPT;
    constexpr int HSP = 196;
    constexpr int BSP = 196;
    extern __shared__ float sm[];
    float* Bsh = sm;                   // [192][BSP]
    float* Hs  = sm + 192*BSP;         // [SPC][HSP]

    const int dir  = blockIdx.y;
    const int mode = mode0 + dir;
    const float* gx  = gx_all  + (size_t)dir*NS*T*G;
    const float* Whh = Whh_all + (size_t)dir*G*H;

    const int tid  = threadIdx.x;
    const int l    = tid & 31;
    const int w    = tid >> 5;
    const int sl0  = l & 15;
    const int ul   = 2*w + (l>>4);
    uint32_t rank; asm("mov.u32 %0, %%cluster_ctarank;" : "=r"(rank));
    const int cid   = blockIdx.x >> 2;
    const int sbase = cid * SPC;
    const int jsl   = (int)rank * 48;
    const uint32_t hs_base = smem_u32(Hs);

    for (int i = tid; i < 192*48; i += 768){
        int lr = i / 48, c4 = i % 48;
        int q = lr / 48, u = lr % 48;
        float4 v = *(const float4*)(Whh + (size_t)(q*192 + jsl + u)*H + c4*4);
        *(float4*)(Bsh + lr*BSP + c4*4) = v;
    }
    for (int i = tid; i < SPC*HSP; i += 768) Hs[i] = 0.f;
    CL_ARRIVE(); CL_WAIT();

    float c[SPT];
    #pragma unroll
    for (int b=0;b<SPT;b++) c[b]=0.f;

    for (int step=0; step<T; ++step){
        const int tt = (mode==1) ? (T-1-step) : step;

        u64 acc[4][SPT];
        #pragma unroll
        for (int q=0;q<4;q++)
            #pragma unroll
            for (int ss=0;ss<SPT;ss++) acc[q][ss]=0ull;

        #pragma unroll 2
        for (int k=0;k<192;k+=4){
            u64 ha[SPT], hb[SPT];
            #pragma unroll
            for (int ss=0;ss<SPT;ss++){
                ulonglong2 hv4 = *(const ulonglong2*)(Hs + (sl0 + 16*ss)*HSP + k);
                ha[ss]=hv4.x; hb[ss]=hv4.y;
            }
            #pragma unroll
            for (int q=0;q<4;q++){
                ulonglong2 bv = *(const ulonglong2*)(Bsh + (q*48 + ul)*BSP + k);
                #pragma unroll
                for (int ss=0;ss<SPT;ss++){
                    fma2(acc[q][ss], ha[ss], bv.x);
                    fma2(acc[q][ss], hb[ss], bv.y);
                }
            }
        }
        float pre[4][SPT];
        #pragma unroll
        for (int q=0;q<4;q++)
            #pragma unroll
            for (int ss=0;ss<SPT;ss++) pre[q][ss] = lohi(acc[q][ss]);

        CL_ARRIVE();
        float gxr[4][SPT];
        #pragma unroll
        for (int q=0;q<4;q++)
            #pragma unroll
            for (int ss=0;ss<SPT;ss++)
                gxr[q][ss] = gx[((size_t)tt*G + q*192 + jsl + ul)*NS
                                + sbase + sl0 + 16*ss];
        CL_WAIT();

        float hv[SPT];
        #pragma unroll
        for (int ss=0;ss<SPT;ss++){
            float iv = sigm(pre[0][ss] + gxr[0][ss]);
            float fv = sigm(pre[1][ss] + gxr[1][ss]);
            float gv = tanhf(pre[2][ss] + gxr[2][ss]);
            float ov = sigm(pre[3][ss] + gxr[3][ss]);
            float cc = fv*c[ss] + iv*gv;
            c[ss] = cc;
            hv[ss] = ov*tanhf(cc);
        }
        #pragma unroll
        for (int ss=0;ss<SPT;ss++){
            int sl = sl0 + 16*ss;
            uint32_t la = hs_base + (uint32_t)(sl*HSP + jsl + ul)*4u;
            float v = hv[ss];
            Hs[sl*HSP + jsl + ul] = v;
            #pragma unroll
            for (int r=0;r<4;r++){
                if (r == (int)rank) continue;
                uint32_t da; asm("mapa.shared::cluster.u32 %0,%1,%2;":"=r"(da):"r"(la),"r"(r));
                asm volatile("st.shared::cluster.f32 [%0],%1;"::"r"(da),"f"(v));
            }
        }
        CL_ARRIVE();
        if (mode==0 || mode==1){
            #pragma unroll
            for (int ss=0;ss<SPT;ss++){
                int s = sbase + sl0 + 16*ss;
                outp[((size_t)s*T + tt)*384 + (mode==1?192:0) + jsl + ul] = hv[ss];
            }
        } else if (step==T-1){
            #pragma unroll
            for (int ss=0;ss<SPT;ss++){
                int s = sbase + sl0 + 16*ss;
                outp[(size_t)s*384 + jsl + ul] = hv[ss];
            }
        }
        CL_WAIT();
    }
}

// ---- single-barrier LSTM with double-buffered Hs (SPT=2 / SPC=32 only;
// smem = 192*196 + 2*32*196 floats = 196KB). Used for layer-1 fwd (mode 2).
// Read Hs[step&1], write Hs[(step&1)^1]; one arrive/wait per step.
__global__ __launch_bounds__(768,1) __cluster_dims__(4,1,1)
void lstm_cluster_db(const float* __restrict__ gx, const float* __restrict__ Whh,
                     float* __restrict__ outp)
{
    constexpr int SPT = 2;
    constexpr int SPC = 32;
    constexpr int HSP = 196;
    constexpr int BSP = 196;
    extern __shared__ float sm[];
    float* Bsh = sm;                    // [192][BSP]
    float* Hs0 = sm + 192*BSP;          // [2][SPC][HSP]

    const int tid  = threadIdx.x;
    const int l    = tid & 31;
    const int w    = tid >> 5;
    const int sl0  = l & 15;
    const int ul   = 2*w + (l>>4);
    uint32_t rank; asm("mov.u32 %0, %%cluster_ctarank;" : "=r"(rank));
    const int cid   = blockIdx.x >> 2;
    const int sbase = cid * SPC;
    const int jsl   = (int)rank * 48;

    for (int i = tid; i < 192*48; i += 768){
        int lr = i / 48, c4 = i % 48;
        int q = lr / 48, u = lr % 48;
        float4 v = *(const float4*)(Whh + (size_t)(q*192 + jsl + u)*H + c4*4);
        *(float4*)(Bsh + lr*BSP + c4*4) = v;
    }
    for (int i = tid; i < 2*SPC*HSP; i += 768) Hs0[i] = 0.f;
    CL_ARRIVE(); CL_WAIT();

    float c[SPT];
    #pragma unroll
    for (int b=0;b<SPT;b++) c[b]=0.f;

    for (int step=0; step<T; ++step){
        const int tt = step;
        float* Hr = Hs0 + (step&1)*SPC*HSP;
        float* Hw = Hs0 + ((step&1)^1)*SPC*HSP;
        const uint32_t hw_base = smem_u32(Hw);

        u64 acc[4][SPT];
        #pragma unroll
        for (int q=0;q<4;q++)
            #pragma unroll
            for (int ss=0;ss<SPT;ss++) acc[q][ss]=0ull;

        #pragma unroll 2
        for (int k=0;k<192;k+=4){
            u64 ha[SPT], hb[SPT];
            #pragma unroll
            for (int ss=0;ss<SPT;ss++){
                ulonglong2 hv4 = *(const ulonglong2*)(Hr + (sl0 + 16*ss)*HSP + k);
                ha[ss]=hv4.x; hb[ss]=hv4.y;
            }
            #pragma unroll
            for (int q=0;q<4;q++){
                ulonglong2 bv = *(const ulonglong2*)(Bsh + (q*48 + ul)*BSP + k);
                #pragma unroll
                for (int ss=0;ss<SPT;ss++){
                    fma2(acc[q][ss], ha[ss], bv.x);
                    fma2(acc[q][ss], hb[ss], bv.y);
                }
            }
        }
        float gxr[4][SPT];
        #pragma unroll
        for (int q=0;q<4;q++)
            #pragma unroll
            for (int ss=0;ss<SPT;ss++)
                gxr[q][ss] = gx[((size_t)tt*G + q*192 + jsl + ul)*NS
                                + sbase + sl0 + 16*ss];

        float hv[SPT];
        #pragma unroll
        for (int ss=0;ss<SPT;ss++){
            float iv = sigm(lohi(acc[0][ss]) + gxr[0][ss]);
            float fv = sigm(lohi(acc[1][ss]) + gxr[1][ss]);
            float gv = tanhf(lohi(acc[2][ss]) + gxr[2][ss]);
            float ov = sigm(lohi(acc[3][ss]) + gxr[3][ss]);
            float cc = fv*c[ss] + iv*gv;
            c[ss] = cc;
            hv[ss] = ov*tanhf(cc);
        }
        #pragma unroll
        for (int ss=0;ss<SPT;ss++){
            int sl = sl0 + 16*ss;
            uint32_t la = hw_base + (uint32_t)(sl*HSP + jsl + ul)*4u;
            float v = hv[ss];
            Hw[sl*HSP + jsl + ul] = v;
            #pragma unroll
            for (int r=0;r<4;r++){
                if (r == (int)rank) continue;
                uint32_t da; asm("mapa.shared::cluster.u32 %0,%1,%2;":"=r"(da):"r"(la),"r"(r));
                asm volatile("st.shared::cluster.f32 [%0],%1;"::"r"(da),"f"(v));
            }
        }
        CL_ARRIVE();                    // release h(t) writes
        if (step==T-1){
            #pragma unroll
            for (int ss=0;ss<SPT;ss++){
                int s = sbase + sl0 + 16*ss;
                outp[(size_t)s*384 + jsl + ul] = hv[ss];
            }
        }
        CL_WAIT();                      // acquire peers' h(t)
    }
}

// ---- layer1 bwd @ t=31 only (h0=c0=0) ----
__global__ void bwd1_last(const float* __restrict__ gxb, float* __restrict__ h2)
{
    int n = blockIdx.x, j = threadIdx.x;
    const float* g = gxb + (size_t)n*G;
    float iv = sigm(g[j]);
    float gv = tanhf(g[2*H+j]);
    float ov = sigm(g[3*H+j]);
    float cc = iv*gv;
    h2[(size_t)n*384 + 192 + j] = ov*tanhf(cc);
}

// ---- dynamic network ----
__global__ void dyn_scalars(const float* __restrict__ x, const float* __restrict__ theta,
                            int* __restrict__ pid, int* __restrict__ off)
{
    int n = blockIdx.x*blockDim.x + threadIdx.x;
    if (n >= NS) return;
    float th  = theta[n];
    float x30 = x[((size_t)n*T + 30)*NF];
    float x31 = x[((size_t)n*T + 31)*NF];
    int p0 = (x30 > th) ? 1 : ((x30 < -th) ? -1 : 0);
    int p1 = (x31 > th) ? 1 : ((x31 < -th) ? -1 : 0);
    pid[n] = (p0+1)*3 + (p1+1);
    off[n] = (p1+1)*3;
}

__global__ __launch_bounds__(256,1)
void dyn_beta(const float* __restrict__ PP, const int* __restrict__ pid,
              const int* __restrict__ off, float* __restrict__ BetaT,
              float* __restrict__ t3)
{
    __shared__ float s_raw[1024];
    __shared__ float s_adj[1024*3];
    __shared__ float s_red[256];
    const int y = blockIdx.x, tid = threadIdx.x;
    const int offy = off[y];
    for (int x=tid; x<NS; x+=256){
        size_t base = ((size_t)x*NS + y)*81 + (size_t)pid[x]*9 + offy;
        float a0=PP[base], a1=PP[base+1], a2=PP[base+2];
        s_adj[x*3+0]=a0; s_adj[x*3+1]=a1; s_adj[x*3+2]=a2;
        float nr = sqrtf(a0*a0+a1*a1+a2*a2);
        s_raw[x] = (nr > 0.38f) ? nr : 0.f;
    }
    __syncthreads();
    float lm = -1e30f;
    for (int x=tid; x<NS; x+=256) lm = fmaxf(lm, s_raw[x]);
    s_red[tid]=lm; __syncthreads();
    for (int o=128;o>0;o>>=1){ if(tid<o) s_red[tid]=fmaxf(s_red[tid],s_red[tid+o]); __syncthreads(); }
    const float mx = s_red[0];
    __syncthreads();
    float ls = 0.f;
    for (int x=tid; x<NS; x+=256){ float e=expf(s_raw[x]-mx); s_raw[x]=e; ls+=e; }
    s_red[tid]=ls; __syncthreads();
    for (int o=128;o>0;o>>=1){ if(tid<o) s_red[tid]+=s_red[tid+o]; __syncthreads(); }
    const float inv = 1.f/s_red[0];
    __syncthreads();
    float t0=0.f,t1=0.f,t2=0.f;
    for (int x=tid; x<NS; x+=256){
        float b = s_raw[x]*inv;
        BetaT[(size_t)y*NS + x] = b;
        t0 += b*s_adj[x*3+0]; t1 += b*s_adj[x*3+1]; t2 += b*s_adj[x*3+2];
    }
    s_red[tid]=t0; __syncthreads();
    for (int o=128;o>0;o>>=1){ if(tid<o) s_red[tid]+=s_red[tid+o]; __syncthreads(); }
    if(tid==0) t3[y*3+0]=s_red[0];
    __syncthreads();
    s_red[tid]=t1; __syncthreads();
    for (int o=128;o>0;o>>=1){ if(tid<o) s_red[tid]+=s_red[tid+o]; __syncthreads(); }
    if(tid==0) t3[y*3+1]=s_red[0];
    __syncthreads();
    s_red[tid]=t2; __syncthreads();
    for (int o=128;o>0;o>>=1){ if(tid<o) s_red[tid]+=s_red[tid+o]; __syncthreads(); }
    if(tid==0) t3[y*3+2]=s_red[0];
}

__global__ void agg_extra(const float* __restrict__ t3, const float* __restrict__ Wa,
                          const float* __restrict__ b, float* __restrict__ E)
{
    int y = blockIdx.x, u = threadIdx.x;
    float v = b[u] + t3[y*3+0]*Wa[u] + t3[y*3+1]*Wa[128+u] + t3[y*3+2]*Wa[256+u];
    E[(size_t)y*128 + u] = v;
}

__global__ void out_kernel(const float* __restrict__ nfeat, const float* __restrict__ n1,
                           const float* __restrict__ n2, const float* __restrict__ W,
                           const float* __restrict__ b, float* __restrict__ out)
{
    int warp = (blockIdx.x*blockDim.x + threadIdx.x)>>5;
    int lane = threadIdx.x & 31;
    if (warp >= NS*2) return;
    int n = warp>>1, o = warp&1;
    float s = 0.f;
    for (int k=lane;k<384;k+=32) s += nfeat[(size_t)n*384+k]*W[k*2+o];
    for (int k=lane;k<128;k+=32) s += n1[(size_t)n*128+k]*W[(384+k)*2+o];
    for (int k=lane;k<128;k+=32) s += n2[(size_t)n*128+k]*W[(512+k)*2+o];
    #pragma unroll
    for (int m=16;m>0;m>>=1) s += __shfl_xor_sync(0xffffffffu, s, m);
    if (lane==0) out[warp] = tanhf(s + b[o]);
}

extern "C" void kernel_launch(void* const* d_in, const int* in_sizes, int n_in,
                              void* d_out, int out_size)
{
    const float* x     = (const float*)d_in[0];
    const float* theta = (const float*)d_in[1];
    const float* PP    = (const float*)d_in[2];
    const float* Wih0  = (const float*)d_in[3];
    const float* Whh0  = (const float*)d_in[4];
    const float* bih0  = (const float*)d_in[5];
    const float* bhh0  = (const float*)d_in[6];
    const float* Wih1  = (const float*)d_in[7];
    const float* Whh1  = (const float*)d_in[8];
    const float* bih1  = (const float*)d_in[9];
    const float* bhh1  = (const float*)d_in[10];
    const float* Wagg1 = (const float*)d_in[11];
    const float* bagg1 = (const float*)d_in[12];
    const float* Wagg2 = (const float*)d_in[13];
    const float* bagg2 = (const float*)d_in[14];
    const float* Wout  = (const float*)d_in[15];
    const float* bout  = (const float*)d_in[16];
    float* out = (float*)d_out;

    float *p_gx0, *p_gx1, *p_gx1b, *p_h1, *p_h2, *p_BetaT, *p_t3, *p_M, *p_E, *p_n1, *p_n2;
    int *p_pid, *p_off;
    cudaGetSymbolAddress((void**)&p_gx0,  g_gx0);
    cudaGetSymbolAddress((void**)&p_gx1,  g_gx1);
    cudaGetSymbolAddress((void**)&p_gx1b, g_gx1b);
    cudaGetSymbolAddress((void**)&p_h1,   g_h1);
    cudaGetSymbolAddress((void**)&p_h2,   g_h2);
    cudaGetSymbolAddress((void**)&p_BetaT,g_BetaT);
    cudaGetSymbolAddress((void**)&p_t3,   g_t3);
    cudaGetSymbolAddress((void**)&p_pid,  g_pid);
    cudaGetSymbolAddress((void**)&p_off,  g_off);
    cudaGetSymbolAddress((void**)&p_M,    g_M);
    cudaGetSymbolAddress((void**)&p_E,    g_E);
    cudaGetSymbolAddress((void**)&p_n1,   g_n1);
    cudaGetSymbolAddress((void**)&p_n2,   g_n2);

    const int SM64 = (192*196 + 64*196)*4;      // 200704 B (lstm_cluster<4>)
    const int SMDB = (192*196 + 2*32*196)*4;    // 200704 B (lstm_cluster_db)
    const int CSH  = 128*132*4;                 // 67584 B
    cudaFuncSetAttribute(lstm_cluster<4>, cudaFuncAttributeMaxDynamicSharedMemorySize, SM64);
    cudaFuncSetAttribute(lstm_cluster_db, cudaFuncAttributeMaxDynamicSharedMemorySize, SMDB);
    cudaFuncSetAttribute(gemm_nt128T, cudaFuncAttributeMaxDynamicSharedMemorySize, CSH);

    // #1-2: layer0 gx, time-major, both dirs
    for (int d=0; d<2; d++){
        gemm_nt128T<<<dim3(256,6), 256, CSH>>>(x, NF, Wih0 + (size_t)d*G*NF, NF,
                                               p_gx0 + (size_t)d*NS*T*G, NF,
                                               bih0 + d*G, bhh0 + d*G);
    }
    // #3: layer0 recurrence (fwd+bwd)
    lstm_cluster<4><<<dim3(64,2), 768, SM64>>>(p_gx0, Whh0, p_h1, 0);

    // #4: layer1 fwd gx, time-major, K=384 — PROFILED SLOT this round
    gemm_nt128T<<<dim3(256,6), 256, CSH>>>(p_h1, 384, Wih1, 384, p_gx1, 384,
                                           bih1, bhh1);

    // #5-6: dynamic network (independent of lstm chain)
    dyn_scalars<<<4, 256>>>(x, theta, p_pid, p_off);
    dyn_beta<<<NS, 256>>>(PP, p_pid, p_off, p_BetaT, p_t3);

    // #7: layer1 bwd gx at t=31 only ([s][j] layout)
    gemm_nt128<<<dim3(8,6), 256>>>(p_h1 + 31*384, T*384, Wih1 + (size_t)G*384, 384,
                                   p_gx1b, G, 384, bih1 + G, bhh1 + G);

    // #8-9: layer1 recurrence fwd (single-barrier db); bwd single step
    lstm_cluster_db<<<dim3(128,1), 768, SMDB>>>(p_gx1, Whh1, p_h2);
    bwd1_last<<<NS, H>>>(p_gx1b, p_h2);

    // #10-12: agg layer 1
    agg_extra<<<NS, 128>>>(p_t3, Wagg1 + (size_t)384*128, bagg1, p_E);
    gemm_nn64<<<dim3(16,2), 256>>>(p_h2, 384, Wagg1, 128, p_M, 128, 384, (const float*)0);
    gemm_nn64<<<dim3(16,2), 256>>>(p_BetaT, NS, p_M, 128, p_n1, 128, NS, p_E);

    // #13-15: agg layer 2
    gemm_nn64<<<dim3(16,2), 256>>>(p_n1, 128, Wagg2, 128, p_M, 128, 128, (const float*)0);
    agg_extra<<<NS, 128>>>(p_t3, Wagg2 + (size_t)128*128, bagg2, p_E);
    gemm_nn64<<<dim3(16,2), 256>>>(p_BetaT, NS, p_M, 128, p_n2, 128, NS, p_E);

    // #16: output
    out_kernel<<<256, 256>>>(p_h2, p_n1, p_n2, Wout, bout, out);
}

// round 12
// speedup vs baseline: 1.3814x; 1.1587x over previous
#include <cuda_runtime.h>
#include <math.h>
#include <stdint.h>

#define NS 1024
#define T  32
#define NF 16
#define H  192
#define G  768

typedef unsigned long long u64;

static __device__ float g_gx0[(size_t)2*NS*T*G];   // time-major: [dir][tt][G][NS]
static __device__ float g_gx1[(size_t)NS*T*G];     // time-major: [tt][G][NS]
static __device__ float g_gx1b[(size_t)NS*G];      // [s][G]
static __device__ float g_h1[(size_t)NS*T*384];    // TIME-MAJOR: [tt][s][384]
static __device__ float g_h2[(size_t)NS*384];
static __device__ float g_BetaT[(size_t)NS*NS];
static __device__ float g_t3[NS*3];
static __device__ int   g_pid[NS];
static __device__ int   g_off[NS];
static __device__ float g_M[NS*128];
static __device__ float g_E[NS*128];
static __device__ float g_n1[NS*128];
static __device__ float g_n2[NS*128];

__device__ __forceinline__ float sigm(float x){ return 1.f/(1.f+expf(-x)); }
__device__ __forceinline__ u64 pk(float x, float y){ u64 r; asm("mov.b64 %0,{%1,%2};":"=l"(r):"f"(x),"f"(y)); return r; }
__device__ __forceinline__ void fma2(u64& d, u64 a, u64 b){ asm("fma.rn.f32x2 %0,%1,%2,%0;":"+l"(d):"l"(a),"l"(b)); }
__device__ __forceinline__ void unpk(u64 v, float& x, float& y){ asm("mov.b64 {%0,%1},%2;":"=f"(x),"=f"(y):"l"(v)); }
__device__ __forceinline__ float lohi(u64 v){ float x,y; unpk(v,x,y); return x+y; }
__device__ __forceinline__ uint32_t smem_u32(const void* p){
    uint32_t a; asm("{ .reg .u64 t; cvta.to.shared.u64 t, %1; cvt.u32.u64 %0, t; }":"=r"(a):"l"(p)); return a;
}
__device__ __forceinline__ uint32_t tf32r(float x){
    uint32_t r; asm("cvt.rna.tf32.f32 %0,%1;":"=r"(r):"f"(x)); return r;
}
#define CL_ARRIVE() asm volatile("barrier.cluster.arrive.aligned;" ::: "memory")
#define CL_WAIT()   asm volatile("barrier.cluster.wait.aligned;"   ::: "memory")

__device__ __forceinline__ void mma_tf32(float& c0, float& c1, float& c2, float& c3,
                                         uint32_t a0, uint32_t a1, uint32_t a2, uint32_t a3,
                                         uint32_t b0, uint32_t b1){
    asm volatile(
        "mma.sync.aligned.m16n8k8.row.col.f32.tf32.tf32.f32 "
        "{%0,%1,%2,%3}, {%4,%5,%6,%7}, {%8,%9}, {%0,%1,%2,%3};"
        : "+f"(c0), "+f"(c1), "+f"(c2), "+f"(c3)
        : "r"(a0), "r"(a1), "r"(a2), "r"(a3), "r"(b0), "r"(b1));
}

// ---- gx1 via mma.sync tf32: Ct[tt][n][s] = h1t[tt][s][384] @ Wih1[n][384]^T + biases
// grid.x = tt*8 + sblk, grid.y = nblk(6). 256 thr, 8 warps, warp tile 64x32.
__global__ __launch_bounds__(256,2)
void gx1_hmma(const float* __restrict__ A, const float* __restrict__ Bw,
              float* __restrict__ Ct,
              const float* __restrict__ bias0, const float* __restrict__ bias1)
{
    extern __shared__ __align__(16) float csh[];   // [128][132] epilogue
    __shared__ __align__(16) float As[16][136];    // tf32 bits as float
    __shared__ __align__(16) float Bs[16][136];
    __shared__ float bsh[128];
    const int tt = blockIdx.x >> 3;
    const int s0 = (blockIdx.x & 7) * 128;
    const int n0 = blockIdx.y * 128;
    const int tid = threadIdx.x;
    const int w    = tid >> 5;
    const int lane = tid & 31;
    const int gid  = lane >> 2;        // 0..7
    const int tid4 = lane & 3;         // 0..3
    const int m0w  = (w & 1) * 64;
    const int n0w  = (w >> 1) * 32;
    const int row = tid>>1, kq = (tid&1)*8;
    const float* aBase = A + ((size_t)tt*NS + s0 + row)*384 + kq;
    const float* bBase = Bw + (size_t)(n0+row)*384 + kq;

    if (tid < 128) bsh[tid] = bias0[n0+tid] + bias1[n0+tid];

    float acc[4][4][4];
    #pragma unroll
    for (int mi=0;mi<4;mi++)
        #pragma unroll
        for (int ni=0;ni<4;ni++)
            #pragma unroll
            for (int q=0;q<4;q++) acc[mi][ni][q]=0.f;

    for (int k0=0;k0<384;k0+=16){
        float4 a0 = *(const float4*)(aBase + k0);
        float4 a1 = *(const float4*)(aBase + k0 + 4);
        float4 b0 = *(const float4*)(bBase + k0);
        float4 b1 = *(const float4*)(bBase + k0 + 4);
        __syncthreads();
        As[kq+0][row]=__uint_as_float(tf32r(a0.x)); As[kq+1][row]=__uint_as_float(tf32r(a0.y));
        As[kq+2][row]=__uint_as_float(tf32r(a0.z)); As[kq+3][row]=__uint_as_float(tf32r(a0.w));
        As[kq+4][row]=__uint_as_float(tf32r(a1.x)); As[kq+5][row]=__uint_as_float(tf32r(a1.y));
        As[kq+6][row]=__uint_as_float(tf32r(a1.z)); As[kq+7][row]=__uint_as_float(tf32r(a1.w));
        Bs[kq+0][row]=__uint_as_float(tf32r(b0.x)); Bs[kq+1][row]=__uint_as_float(tf32r(b0.y));
        Bs[kq+2][row]=__uint_as_float(tf32r(b0.z)); Bs[kq+3][row]=__uint_as_float(tf32r(b0.w));
        Bs[kq+4][row]=__uint_as_float(tf32r(b1.x)); Bs[kq+5][row]=__uint_as_float(tf32r(b1.y));
        Bs[kq+6][row]=__uint_as_float(tf32r(b1.z)); Bs[kq+7][row]=__uint_as_float(tf32r(b1.w));
        __syncthreads();
        #pragma unroll
        for (int k8=0;k8<16;k8+=8){
            uint32_t af[4][4];
            #pragma unroll
            for (int mi=0;mi<4;mi++){
                int m = m0w + mi*16 + gid;
                af[mi][0] = __float_as_uint(As[k8+tid4  ][m  ]);
                af[mi][1] = __float_as_uint(As[k8+tid4  ][m+8]);
                af[mi][2] = __float_as_uint(As[k8+tid4+4][m  ]);
                af[mi][3] = __float_as_uint(As[k8+tid4+4][m+8]);
            }
            uint32_t bf[4][2];
            #pragma unroll
            for (int ni=0;ni<4;ni++){
                int n = n0w + ni*8 + gid;
                bf[ni][0] = __float_as_uint(Bs[k8+tid4  ][n]);
                bf[ni][1] = __float_as_uint(Bs[k8+tid4+4][n]);
            }
            #pragma unroll
            for (int mi=0;mi<4;mi++)
                #pragma unroll
                for (int ni=0;ni<4;ni++)
                    mma_tf32(acc[mi][ni][0], acc[mi][ni][1], acc[mi][ni][2], acc[mi][ni][3],
                             af[mi][0], af[mi][1], af[mi][2], af[mi][3],
                             bf[ni][0], bf[ni][1]);
        }
    }
    __syncthreads();
    // epilogue: transpose via csh[n_local][m_local] (+bias on n)
    #pragma unroll
    for (int mi=0;mi<4;mi++){
        #pragma unroll
        for (int ni=0;ni<4;ni++){
            int nl = n0w + ni*8 + tid4*2;
            int ml = m0w + mi*16 + gid;
            csh[(size_t)(nl  )*132 + ml  ] = acc[mi][ni][0] + bsh[nl];
            csh[(size_t)(nl+1)*132 + ml  ] = acc[mi][ni][1] + bsh[nl+1];
            csh[(size_t)(nl  )*132 + ml+8] = acc[mi][ni][2] + bsh[nl];
            csh[(size_t)(nl+1)*132 + ml+8] = acc[mi][ni][3] + bsh[nl+1];
        }
    }
    __syncthreads();
    {
        int jl = tid>>1, half = (tid&1)*64;
        const float* src = csh + (size_t)jl*132 + half;
        float* dst = Ct + ((size_t)tt*G + n0 + jl)*NS + s0 + half;
        #pragma unroll
        for (int v=0;v<16;v++)
            *(float4*)(dst + v*4) = *(const float4*)(src + v*4);
    }
}

// ---- transposing gx GEMM (for gx0): Ct[tt][n][s] = A[s][tt][k]*B[n][k]+biases
__global__ __launch_bounds__(256,2)
void gemm_nt128T(const float* __restrict__ A, int lda,
                 const float* __restrict__ B, int ldb,
                 float* __restrict__ Ct, int K,
                 const float* __restrict__ bias0, const float* __restrict__ bias1)
{
    extern __shared__ __align__(16) float csh[];   // [128][132]
    __shared__ __align__(16) float As[16][136];
    __shared__ __align__(16) float Bs[16][136];
    const int tt = blockIdx.x >> 3;
    const int s0 = (blockIdx.x & 7) * 128;
    const int n0 = blockIdx.y * 128;
    const int tid = threadIdx.x;
    const int ty = tid>>4, tx = tid&15;
    const int row = tid>>1, kq = (tid&1)*8;
    u64 acc[4][8];
    #pragma unroll
    for (int i=0;i<4;i++)
        #pragma unroll
        for (int j=0;j<8;j++) acc[i][j]=0ull;

    for (int k0=0;k0<K;k0+=16){
        const float* ap = A + ((size_t)(s0+row)*T + tt)*lda + k0 + kq;
        float4 a0 = *(const float4*)ap;
        float4 a1 = *(const float4*)(ap+4);
        float4 b0 = *(const float4*)(B + (size_t)(n0+row)*ldb + k0 + kq);
        float4 b1 = *(const float4*)(B + (size_t)(n0+row)*ldb + k0 + kq + 4);
        __syncthreads();
        As[kq+0][row]=a0.x; As[kq+1][row]=a0.y; As[kq+2][row]=a0.z; As[kq+3][row]=a0.w;
        As[kq+4][row]=a1.x; As[kq+5][row]=a1.y; As[kq+6][row]=a1.z; As[kq+7][row]=a1.w;
        Bs[kq+0][row]=b0.x; Bs[kq+1][row]=b0.y; Bs[kq+2][row]=b0.z; Bs[kq+3][row]=b0.w;
        Bs[kq+4][row]=b1.x; Bs[kq+5][row]=b1.y; Bs[kq+6][row]=b1.z; Bs[kq+7][row]=b1.w;
        __syncthreads();
        #pragma unroll
        for (int k=0;k<16;k++){
            ulonglong2 av0 = *(const ulonglong2*)&As[k][tx*8];
            ulonglong2 av1 = *(const ulonglong2*)&As[k][tx*8+4];
            float4 bA = *(const float4*)&Bs[k][ty*8];
            float4 bB = *(const float4*)&Bs[k][ty*8+4];
            u64 bb[8];
            bb[0]=pk(bA.x,bA.x); bb[1]=pk(bA.y,bA.y); bb[2]=pk(bA.z,bA.z); bb[3]=pk(bA.w,bA.w);
            bb[4]=pk(bB.x,bB.x); bb[5]=pk(bB.y,bB.y); bb[6]=pk(bB.z,bB.z); bb[7]=pk(bB.w,bB.w);
            u64 aa[4] = { av0.x, av0.y, av1.x, av1.y };
            #pragma unroll
            for (int i2=0;i2<4;i2++)
                #pragma unroll
                for (int j=0;j<8;j++) fma2(acc[i2][j], aa[i2], bb[j]);
        }
    }
    float bv[8];
    #pragma unroll
    for (int j=0;j<8;j++){
        int n = n0+ty*8+j;
        bv[j] = bias0[n] + bias1[n];
    }
    __syncthreads();
    #pragma unroll
    for (int j=0;j<8;j++){
        float r[8];
        #pragma unroll
        for (int i2=0;i2<4;i2++){ unpk(acc[i2][j], r[2*i2], r[2*i2+1]); }
        #pragma unroll
        for (int v=0;v<8;v++) r[v] += bv[j];
        float* cp = csh + (size_t)(ty*8+j)*132 + tx*8;
        *(float4*)cp     = make_float4(r[0],r[1],r[2],r[3]);
        *(float4*)(cp+4) = make_float4(r[4],r[5],r[6],r[7]);
    }
    __syncthreads();
    {
        int jl = tid>>1, half = (tid&1)*64;
        const float* src = csh + (size_t)jl*132 + half;
        float* dst = Ct + ((size_t)tt*G + n0 + jl)*NS + s0 + half;
        #pragma unroll
        for (int v=0;v<16;v++)
            *(float4*)(dst + v*4) = *(const float4*)(src + v*4);
    }
}

// ---- plain NT gemm (gx1b), C[m][n] layout ----
__global__ __launch_bounds__(256,2)
void gemm_nt128(const float* __restrict__ A, int lda,
                const float* __restrict__ B, int ldb,
                float* __restrict__ C, int ldc, int K,
                const float* __restrict__ bias0, const float* __restrict__ bias1)
{
    __shared__ __align__(16) float As[16][136];
    __shared__ __align__(16) float Bs[16][136];
    const int m0 = blockIdx.x*128, n0 = blockIdx.y*128;
    const int tid = threadIdx.x;
    const int ty = tid>>4, tx = tid&15;
    const int row = tid>>1, kq = (tid&1)*8;
    u64 acc[4][8];
    #pragma unroll
    for (int i=0;i<4;i++)
        #pragma unroll
        for (int j=0;j<8;j++) acc[i][j]=0ull;

    for (int k0=0;k0<K;k0+=16){
        float4 a0 = *(const float4*)(A + (size_t)(m0+row)*lda + k0 + kq);
        float4 a1 = *(const float4*)(A + (size_t)(m0+row)*lda + k0 + kq + 4);
        float4 b0 = *(const float4*)(B + (size_t)(n0+row)*ldb + k0 + kq);
        float4 b1 = *(const float4*)(B + (size_t)(n0+row)*ldb + k0 + kq + 4);
        __syncthreads();
        As[kq+0][row]=a0.x; As[kq+1][row]=a0.y; As[kq+2][row]=a0.z; As[kq+3][row]=a0.w;
        As[kq+4][row]=a1.x; As[kq+5][row]=a1.y; As[kq+6][row]=a1.z; As[kq+7][row]=a1.w;
        Bs[kq+0][row]=b0.x; Bs[kq+1][row]=b0.y; Bs[kq+2][row]=b0.z; Bs[kq+3][row]=b0.w;
        Bs[kq+4][row]=b1.x; Bs[kq+5][row]=b1.y; Bs[kq+6][row]=b1.z; Bs[kq+7][row]=b1.w;
        __syncthreads();
        #pragma unroll
        for (int k=0;k<16;k++){
            ulonglong2 av0 = *(const ulonglong2*)&As[k][ty*8];
            ulonglong2 av1 = *(const ulonglong2*)&As[k][ty*8+4];
            float4 bA = *(const float4*)&Bs[k][tx*8];
            float4 bB = *(const float4*)&Bs[k][tx*8+4];
            u64 bb[8];
            bb[0]=pk(bA.x,bA.x); bb[1]=pk(bA.y,bA.y); bb[2]=pk(bA.z,bA.z); bb[3]=pk(bA.w,bA.w);
            bb[4]=pk(bB.x,bB.x); bb[5]=pk(bB.y,bB.y); bb[6]=pk(bB.z,bB.z); bb[7]=pk(bB.w,bB.w);
            u64 aa[4] = { av0.x, av0.y, av1.x, av1.y };
            #pragma unroll
            for (int i2=0;i2<4;i2++)
                #pragma unroll
                for (int j=0;j<8;j++) fma2(acc[i2][j], aa[i2], bb[j]);
        }
    }
    float bv[8];
    #pragma unroll
    for (int j=0;j<8;j++){
        int n = n0+tx*8+j;
        float v = 0.f;
        if (bias0) v += bias0[n];
        if (bias1) v += bias1[n];
        bv[j]=v;
    }
    #pragma unroll
    for (int i2=0;i2<4;i2++){
        float r0[8], r1[8];
        #pragma unroll
        for (int j=0;j<8;j++){ unpk(acc[i2][j], r0[j], r1[j]); r0[j]+=bv[j]; r1[j]+=bv[j]; }
        float* c0 = C + (size_t)(m0+ty*8+2*i2)*ldc + n0 + tx*8;
        float* c1 = C + (size_t)(m0+ty*8+2*i2+1)*ldc + n0 + tx*8;
        *(float4*)c0     = make_float4(r0[0],r0[1],r0[2],r0[3]);
        *(float4*)(c0+4) = make_float4(r0[4],r0[5],r0[6],r0[7]);
        *(float4*)c1     = make_float4(r1[0],r1[1],r1[2],r1[3]);
        *(float4*)(c1+4) = make_float4(r1[4],r1[5],r1[6],r1[7]);
    }
}

// ---- C[m][n] = sum_k A[m][k]*B[k][n] (+addC), 64x64 tile, 4x4 micro.
__global__ __launch_bounds__(256,1)
void gemm_nn64(const float* __restrict__ A, int lda,
               const float* __restrict__ B, int ldb,
               float* __restrict__ C, int ldc, int K,
               const float* __restrict__ addC)
{
    __shared__ __align__(16) float As[16][68];
    __shared__ __align__(16) float Bs[16][68];
    const int m0 = blockIdx.x*64, n0 = blockIdx.y*64;
    const int tid = threadIdx.x;
    const int ty = tid>>4, tx = tid&15;
    const int arow = tid>>2, akq = (tid&3)*4;
    const int bk = tid>>4, bnq = (tid&15)*4;
    float acc[4][4];
    #pragma unroll
    for (int i=0;i<4;i++)
        #pragma unroll
        for (int j=0;j<4;j++) acc[i][j]=0.f;

    for (int k0=0;k0<K;k0+=16){
        float4 av = *(const float4*)(A + (size_t)(m0+arow)*lda + k0 + akq);
        float4 bv = *(const float4*)(B + (size_t)(k0+bk)*ldb + n0 + bnq);
        __syncthreads();
        As[akq+0][arow]=av.x; As[akq+1][arow]=av.y; As[akq+2][arow]=av.z; As[akq+3][arow]=av.w;
        *(float4*)&Bs[bk][bnq] = bv;
        __syncthreads();
        #pragma unroll
        for (int k=0;k<16;k++){
            float a[4],b[4];
            #pragma unroll
            for (int i=0;i<4;i++){ a[i]=As[k][ty*4+i]; b[i]=Bs[k][tx*4+i]; }
            #pragma unroll
            for (int i=0;i<4;i++)
                #pragma unroll
                for (int j=0;j<4;j++) acc[i][j]+=a[i]*b[j];
        }
    }
    #pragma unroll
    for (int i=0;i<4;i++){
        int m = m0+ty*4+i;
        float* cp = C + (size_t)m*ldc + n0 + tx*4;
        const float* ap = addC ? addC + (size_t)m*ldc + n0 + tx*4 : (const float*)0;
        #pragma unroll
        for (int j=0;j<4;j++){
            float v = acc[i][j];
            if (ap) v += ap[j];
            cp[j] = v;
        }
    }
}

// ---- cluster LSTM (2-barrier): thread = 1 unit x 4 gates x SPT stocks.
// h1 output TIME-MAJOR [tt][s][384].
template<int SPT>
__global__ __launch_bounds__(768,1) __cluster_dims__(4,1,1)
void lstm_cluster(const float* __restrict__ gx_all, const float* __restrict__ Whh_all,
                  float* __restrict__ outp, int mode0)
{
    constexpr int SPC = 16*SPT;
    constexpr int HSP = 196;
    constexpr int BSP = 196;
    extern __shared__ float sm[];
    float* Bsh = sm;                   // [192][BSP]
    float* Hs  = sm + 192*BSP;         // [SPC][HSP]

    const int dir  = blockIdx.y;
    const int mode = mode0 + dir;
    const float* gx  = gx_all  + (size_t)dir*NS*T*G;
    const float* Whh = Whh_all + (size_t)dir*G*H;

    const int tid  = threadIdx.x;
    const int l    = tid & 31;
    const int w    = tid >> 5;
    const int sl0  = l & 15;
    const int ul   = 2*w + (l>>4);
    uint32_t rank; asm("mov.u32 %0, %%cluster_ctarank;" : "=r"(rank));
    const int cid   = blockIdx.x >> 2;
    const int sbase = cid * SPC;
    const int jsl   = (int)rank * 48;
    const uint32_t hs_base = smem_u32(Hs);

    for (int i = tid; i < 192*48; i += 768){
        int lr = i / 48, c4 = i % 48;
        int q = lr / 48, u = lr % 48;
        float4 v = *(const float4*)(Whh + (size_t)(q*192 + jsl + u)*H + c4*4);
        *(float4*)(Bsh + lr*BSP + c4*4) = v;
    }
    for (int i = tid; i < SPC*HSP; i += 768) Hs[i] = 0.f;
    CL_ARRIVE(); CL_WAIT();

    float c[SPT];
    #pragma unroll
    for (int b=0;b<SPT;b++) c[b]=0.f;

    for (int step=0; step<T; ++step){
        const int tt = (mode==1) ? (T-1-step) : step;

        u64 acc[4][SPT];
        #pragma unroll
        for (int q=0;q<4;q++)
            #pragma unroll
            for (int ss=0;ss<SPT;ss++) acc[q][ss]=0ull;

        #pragma unroll 2
        for (int k=0;k<192;k+=4){
            u64 ha[SPT], hb[SPT];
            #pragma unroll
            for (int ss=0;ss<SPT;ss++){
                ulonglong2 hv4 = *(const ulonglong2*)(Hs + (sl0 + 16*ss)*HSP + k);
                ha[ss]=hv4.x; hb[ss]=hv4.y;
            }
            #pragma unroll
            for (int q=0;q<4;q++){
                ulonglong2 bv = *(const ulonglong2*)(Bsh + (q*48 + ul)*BSP + k);
                #pragma unroll
                for (int ss=0;ss<SPT;ss++){
                    fma2(acc[q][ss], ha[ss], bv.x);
                    fma2(acc[q][ss], hb[ss], bv.y);
                }
            }
        }
        float pre[4][SPT];
        #pragma unroll
        for (int q=0;q<4;q++)
            #pragma unroll
            for (int ss=0;ss<SPT;ss++) pre[q][ss] = lohi(acc[q][ss]);

        CL_ARRIVE();
        float gxr[4][SPT];
        #pragma unroll
        for (int q=0;q<4;q++)
            #pragma unroll
            for (int ss=0;ss<SPT;ss++)
                gxr[q][ss] = gx[((size_t)tt*G + q*192 + jsl + ul)*NS
                                + sbase + sl0 + 16*ss];
        CL_WAIT();

        float hv[SPT];
        #pragma unroll
        for (int ss=0;ss<SPT;ss++){
            float iv = sigm(pre[0][ss] + gxr[0][ss]);
            float fv = sigm(pre[1][ss] + gxr[1][ss]);
            float gv = tanhf(pre[2][ss] + gxr[2][ss]);
            float ov = sigm(pre[3][ss] + gxr[3][ss]);
            float cc = fv*c[ss] + iv*gv;
            c[ss] = cc;
            hv[ss] = ov*tanhf(cc);
        }
        #pragma unroll
        for (int ss=0;ss<SPT;ss++){
            int sl = sl0 + 16*ss;
            uint32_t la = hs_base + (uint32_t)(sl*HSP + jsl + ul)*4u;
            float v = hv[ss];
            Hs[sl*HSP + jsl + ul] = v;
            #pragma unroll
            for (int r=0;r<4;r++){
                if (r == (int)rank) continue;
                uint32_t da; asm("mapa.shared::cluster.u32 %0,%1,%2;":"=r"(da):"r"(la),"r"(r));
                asm volatile("st.shared::cluster.f32 [%0],%1;"::"r"(da),"f"(v));
            }
        }
        CL_ARRIVE();
        if (mode==0 || mode==1){
            #pragma unroll
            for (int ss=0;ss<SPT;ss++){
                int s = sbase + sl0 + 16*ss;
                outp[((size_t)tt*NS + s)*384 + (mode==1?192:0) + jsl + ul] = hv[ss];
            }
        } else if (step==T-1){
            #pragma unroll
            for (int ss=0;ss<SPT;ss++){
                int s = sbase + sl0 + 16*ss;
                outp[(size_t)s*384 + jsl + ul] = hv[ss];
            }
        }
        CL_WAIT();
    }
}

// ---- single-barrier LSTM with double-buffered Hs (layer-1 fwd) ----
__global__ __launch_bounds__(768,1) __cluster_dims__(4,1,1)
void lstm_cluster_db(const float* __restrict__ gx, const float* __restrict__ Whh,
                     float* __restrict__ outp)
{
    constexpr int SPT = 2;
    constexpr int SPC = 32;
    constexpr int HSP = 196;
    constexpr int BSP = 196;
    extern __shared__ float sm[];
    float* Bsh = sm;
    float* Hs0 = sm + 192*BSP;

    const int tid  = threadIdx.x;
    const int l    = tid & 31;
    const int w    = tid >> 5;
    const int sl0  = l & 15;
    const int ul   = 2*w + (l>>4);
    uint32_t rank; asm("mov.u32 %0, %%cluster_ctarank;" : "=r"(rank));
    const int cid   = blockIdx.x >> 2;
    const int sbase = cid * SPC;
    const int jsl   = (int)rank * 48;

    for (int i = tid; i < 192*48; i += 768){
        int lr = i / 48, c4 = i % 48;
        int q = lr / 48, u = lr % 48;
        float4 v = *(const float4*)(Whh + (size_t)(q*192 + jsl + u)*H + c4*4);
        *(float4*)(Bsh + lr*BSP + c4*4) = v;
    }
    for (int i = tid; i < 2*SPC*HSP; i += 768) Hs0[i] = 0.f;
    CL_ARRIVE(); CL_WAIT();

    float c[SPT];
    #pragma unroll
    for (int b=0;b<SPT;b++) c[b]=0.f;

    for (int step=0; step<T; ++step){
        const int tt = step;
        float* Hr = Hs0 + (step&1)*SPC*HSP;
        float* Hw = Hs0 + ((step&1)^1)*SPC*HSP;
        const uint32_t hw_base = smem_u32(Hw);

        u64 acc[4][SPT];
        #pragma unroll
        for (int q=0;q<4;q++)
            #pragma unroll
            for (int ss=0;ss<SPT;ss++) acc[q][ss]=0ull;

        #pragma unroll 2
        for (int k=0;k<192;k+=4){
            u64 ha[SPT], hb[SPT];
            #pragma unroll
            for (int ss=0;ss<SPT;ss++){
                ulonglong2 hv4 = *(const ulonglong2*)(Hr + (sl0 + 16*ss)*HSP + k);
                ha[ss]=hv4.x; hb[ss]=hv4.y;
            }
            #pragma unroll
            for (int q=0;q<4;q++){
                ulonglong2 bv = *(const ulonglong2*)(Bsh + (q*48 + ul)*BSP + k);
                #pragma unroll
                for (int ss=0;ss<SPT;ss++){
                    fma2(acc[q][ss], ha[ss], bv.x);
                    fma2(acc[q][ss], hb[ss], bv.y);
                }
            }
        }
        float gxr[4][SPT];
        #pragma unroll
        for (int q=0;q<4;q++)
            #pragma unroll
            for (int ss=0;ss<SPT;ss++)
                gxr[q][ss] = gx[((size_t)tt*G + q*192 + jsl + ul)*NS
                                + sbase + sl0 + 16*ss];

        float hv[SPT];
        #pragma unroll
        for (int ss=0;ss<SPT;ss++){
            float iv = sigm(lohi(acc[0][ss]) + gxr[0][ss]);
            float fv = sigm(lohi(acc[1][ss]) + gxr[1][ss]);
            float gv = tanhf(lohi(acc[2][ss]) + gxr[2][ss]);
            float ov = sigm(lohi(acc[3][ss]) + gxr[3][ss]);
            float cc = fv*c[ss] + iv*gv;
            c[ss] = cc;
            hv[ss] = ov*tanhf(cc);
        }
        #pragma unroll
        for (int ss=0;ss<SPT;ss++){
            int sl = sl0 + 16*ss;
            uint32_t la = hw_base + (uint32_t)(sl*HSP + jsl + ul)*4u;
            float v = hv[ss];
            Hw[sl*HSP + jsl + ul] = v;
            #pragma unroll
            for (int r=0;r<4;r++){
                if (r == (int)rank) continue;
                uint32_t da; asm("mapa.shared::cluster.u32 %0,%1,%2;":"=r"(da):"r"(la),"r"(r));
                asm volatile("st.shared::cluster.f32 [%0],%1;"::"r"(da),"f"(v));
            }
        }
        CL_ARRIVE();
        if (step==T-1){
            #pragma unroll
            for (int ss=0;ss<SPT;ss++){
                int s = sbase + sl0 + 16*ss;
                outp[(size_t)s*384 + jsl + ul] = hv[ss];
            }
        }
        CL_WAIT();
    }
}

// ---- layer1 bwd @ t=31 only (h0=c0=0) ----
__global__ void bwd1_last(const float* __restrict__ gxb, float* __restrict__ h2)
{
    int n = blockIdx.x, j = threadIdx.x;
    const float* g = gxb + (size_t)n*G;
    float iv = sigm(g[j]);
    float gv = tanhf(g[2*H+j]);
    float ov = sigm(g[3*H+j]);
    float cc = iv*gv;
    h2[(size_t)n*384 + 192 + j] = ov*tanhf(cc);
}

// ---- dynamic network ----
__global__ void dyn_scalars(const float* __restrict__ x, const float* __restrict__ theta,
                            int* __restrict__ pid, int* __restrict__ off)
{
    int n = blockIdx.x*blockDim.x + threadIdx.x;
    if (n >= NS) return;
    float th  = theta[n];
    float x30 = x[((size_t)n*T + 30)*NF];
    float x31 = x[((size_t)n*T + 31)*NF];
    int p0 = (x30 > th) ? 1 : ((x30 < -th) ? -1 : 0);
    int p1 = (x31 > th) ? 1 : ((x31 < -th) ? -1 : 0);
    pid[n] = (p0+1)*3 + (p1+1);
    off[n] = (p1+1)*3;
}

__global__ __launch_bounds__(256,1)
void dyn_beta(const float* __restrict__ PP, const int* __restrict__ pid,
              const int* __restrict__ off, float* __restrict__ BetaT,
              float* __restrict__ t3)
{
    __shared__ float s_raw[1024];
    __shared__ float s_adj[1024*3];
    __shared__ float s_red[256];
    const int y = blockIdx.x, tid = threadIdx.x;
    const int offy = off[y];
    for (int x=tid; x<NS; x+=256){
        size_t base = ((size_t)x*NS + y)*81 + (size_t)pid[x]*9 + offy;
        float a0=PP[base], a1=PP[base+1], a2=PP[base+2];
        s_adj[x*3+0]=a0; s_adj[x*3+1]=a1; s_adj[x*3+2]=a2;
        float nr = sqrtf(a0*a0+a1*a1+a2*a2);
        s_raw[x] = (nr > 0.38f) ? nr : 0.f;
    }
    __syncthreads();
    float lm = -1e30f;
    for (int x=tid; x<NS; x+=256) lm = fmaxf(lm, s_raw[x]);
    s_red[tid]=lm; __syncthreads();
    for (int o=128;o>0;o>>=1){ if(tid<o) s_red[tid]=fmaxf(s_red[tid],s_red[tid+o]); __syncthreads(); }
    const float mx = s_red[0];
    __syncthreads();
    float ls = 0.f;
    for (int x=tid; x<NS; x+=256){ float e=expf(s_raw[x]-mx); s_raw[x]=e; ls+=e; }
    s_red[tid]=ls; __syncthreads();
    for (int o=128;o>0;o>>=1){ if(tid<o) s_red[tid]+=s_red[tid+o]; __syncthreads(); }
    const float inv = 1.f/s_red[0];
    __syncthreads();
    float t0=0.f,t1=0.f,t2=0.f;
    for (int x=tid; x<NS; x+=256){
        float b = s_raw[x]*inv;
        BetaT[(size_t)y*NS + x] = b;
        t0 += b*s_adj[x*3+0]; t1 += b*s_adj[x*3+1]; t2 += b*s_adj[x*3+2];
    }
    s_red[tid]=t0; __syncthreads();
    for (int o=128;o>0;o>>=1){ if(tid<o) s_red[tid]+=s_red[tid+o]; __syncthreads(); }
    if(tid==0) t3[y*3+0]=s_red[0];
    __syncthreads();
    s_red[tid]=t1; __syncthreads();
    for (int o=128;o>0;o>>=1){ if(tid<o) s_red[tid]+=s_red[tid+o]; __syncthreads(); }
    if(tid==0) t3[y*3+1]=s_red[0];
    __syncthreads();
    s_red[tid]=t2; __syncthreads();
    for (int o=128;o>0;o>>=1){ if(tid<o) s_red[tid]+=s_red[tid+o]; __syncthreads(); }
    if(tid==0) t3[y*3+2]=s_red[0];
}

__global__ void agg_extra(const float* __restrict__ t3, const float* __restrict__ Wa,
                          const float* __restrict__ b, float* __restrict__ E)
{
    int y = blockIdx.x, u = threadIdx.x;
    float v = b[u] + t3[y*3+0]*Wa[u] + t3[y*3+1]*Wa[128+u] + t3[y*3+2]*Wa[256+u];
    E[(size_t)y*128 + u] = v;
}

__global__ void out_kernel(const float* __restrict__ nfeat, const float* __restrict__ n1,
                           const float* __restrict__ n2, const float* __restrict__ W,
                           const float* __restrict__ b, float* __restrict__ out)
{
    int warp = (blockIdx.x*blockDim.x + threadIdx.x)>>5;
    int lane = threadIdx.x & 31;
    if (warp >= NS*2) return;
    int n = warp>>1, o = warp&1;
    float s = 0.f;
    for (int k=lane;k<384;k+=32) s += nfeat[(size_t)n*384+k]*W[k*2+o];
    for (int k=lane;k<128;k+=32) s += n1[(size_t)n*128+k]*W[(384+k)*2+o];
    for (int k=lane;k<128;k+=32) s += n2[(size_t)n*128+k]*W[(512+k)*2+o];
    #pragma unroll
    for (int m=16;m>0;m>>=1) s += __shfl_xor_sync(0xffffffffu, s, m);
    if (lane==0) out[warp] = tanhf(s + b[o]);
}

extern "C" void kernel_launch(void* const* d_in, const int* in_sizes, int n_in,
                              void* d_out, int out_size)
{
    const float* x     = (const float*)d_in[0];
    const float* theta = (const float*)d_in[1];
    const float* PP    = (const float*)d_in[2];
    const float* Wih0  = (const float*)d_in[3];
    const float* Whh0  = (const float*)d_in[4];
    const float* bih0  = (const float*)d_in[5];
    const float* bhh0  = (const float*)d_in[6];
    const float* Wih1  = (const float*)d_in[7];
    const float* Whh1  = (const float*)d_in[8];
    const float* bih1  = (const float*)d_in[9];
    const float* bhh1  = (const float*)d_in[10];
    const float* Wagg1 = (const float*)d_in[11];
    const float* bagg1 = (const float*)d_in[12];
    const float* Wagg2 = (const float*)d_in[13];
    const float* bagg2 = (const float*)d_in[14];
    const float* Wout  = (const float*)d_in[15];
    const float* bout  = (const float*)d_in[16];
    float* out = (float*)d_out;

    float *p_gx0, *p_gx1, *p_gx1b, *p_h1, *p_h2, *p_BetaT, *p_t3, *p_M, *p_E, *p_n1, *p_n2;
    int *p_pid, *p_off;
    cudaGetSymbolAddress((void**)&p_gx0,  g_gx0);
    cudaGetSymbolAddress((void**)&p_gx1,  g_gx1);
    cudaGetSymbolAddress((void**)&p_gx1b, g_gx1b);
    cudaGetSymbolAddress((void**)&p_h1,   g_h1);
    cudaGetSymbolAddress((void**)&p_h2,   g_h2);
    cudaGetSymbolAddress((void**)&p_BetaT,g_BetaT);
    cudaGetSymbolAddress((void**)&p_t3,   g_t3);
    cudaGetSymbolAddress((void**)&p_pid,  g_pid);
    cudaGetSymbolAddress((void**)&p_off,  g_off);
    cudaGetSymbolAddress((void**)&p_M,    g_M);
    cudaGetSymbolAddress((void**)&p_E,    g_E);
    cudaGetSymbolAddress((void**)&p_n1,   g_n1);
    cudaGetSymbolAddress((void**)&p_n2,   g_n2);

    const int SM64 = (192*196 + 64*196)*4;      // lstm_cluster<4>
    const int SMDB = (192*196 + 2*32*196)*4;    // lstm_cluster_db
    const int CSH  = 128*132*4;                 // epilogue smem (gemm_nt128T / gx1_hmma)
    cudaFuncSetAttribute(lstm_cluster<4>, cudaFuncAttributeMaxDynamicSharedMemorySize, SM64);
    cudaFuncSetAttribute(lstm_cluster_db, cudaFuncAttributeMaxDynamicSharedMemorySize, SMDB);
    cudaFuncSetAttribute(gemm_nt128T, cudaFuncAttributeMaxDynamicSharedMemorySize, CSH);
    cudaFuncSetAttribute(gx1_hmma, cudaFuncAttributeMaxDynamicSharedMemorySize, CSH);

    // #1-2: layer0 gx, time-major, both dirs
    for (int d=0; d<2; d++){
        gemm_nt128T<<<dim3(256,6), 256, CSH>>>(x, NF, Wih0 + (size_t)d*G*NF, NF,
                                               p_gx0 + (size_t)d*NS*T*G, NF,
                                               bih0 + d*G, bhh0 + d*G);
    }
    // #3: layer0 recurrence (fwd+bwd) -> h1 time-major [tt][s][384]
    lstm_cluster<4><<<dim3(64,2), 768, SM64>>>(p_gx0, Whh0, p_h1, 0);

    // #4: layer1 fwd gx via mma.sync tf32 — PROFILED SLOT
    gx1_hmma<<<dim3(256,6), 256, CSH>>>(p_h1, Wih1, p_gx1, bih1, bhh1);

    // #5-6: dynamic network
    dyn_scalars<<<4, 256>>>(x, theta, p_pid, p_off);
    dyn_beta<<<NS, 256>>>(PP, p_pid, p_off, p_BetaT, p_t3);

    // #7: layer1 bwd gx at t=31 (rows = s contiguous in time-major h1)
    gemm_nt128<<<dim3(8,6), 256>>>(p_h1 + (size_t)31*NS*384, 384,
                                   Wih1 + (size_t)G*384, 384,
                                   p_gx1b, G, 384, bih1 + G, bhh1 + G);

    // #8-9: layer1 recurrence fwd; bwd single step
    lstm_cluster_db<<<dim3(128,1), 768, SMDB>>>(p_gx1, Whh1, p_h2);
    bwd1_last<<<NS, H>>>(p_gx1b, p_h2);

    // #10-12: agg layer 1
    agg_extra<<<NS, 128>>>(p_t3, Wagg1 + (size_t)384*128, bagg1, p_E);
    gemm_nn64<<<dim3(16,2), 256>>>(p_h2, 384, Wagg1, 128, p_M, 128, 384, (const float*)0);
    gemm_nn64<<<dim3(16,2), 256>>>(p_BetaT, NS, p_M, 128, p_n1, 128, NS, p_E);

    // #13-15: agg layer 2
    gemm_nn64<<<dim3(16,2), 256>>>(p_n1, 128, Wagg2, 128, p_M, 128, 128, (const float*)0);
    agg_extra<<<NS, 128>>>(p_t3, Wagg2 + (size_t)128*128, bagg2, p_E);
    gemm_nn64<<<dim3(16,2), 256>>>(p_BetaT, NS, p_M, 128, p_n2, 128, NS, p_E);

    // #16: output
    out_kernel<<<256, 256>>>(p_h2, p_n1, p_n2, Wout, bout, out);
}

// round 13
// speedup vs baseline: 2.0069x; 1.4528x over previous
#include <cuda_runtime.h>
#include <math.h>
#include <stdint.h>

#define NS 1024
#define T  32
#define NF 16
#define H  192
#define G  768

typedef unsigned long long u64;

static __device__ float g_gx0[(size_t)2*NS*T*G];   // time-major: [dir][tt][G][NS]
static __device__ float g_gx1[(size_t)NS*T*G];     // time-major: [tt][G][NS]
static __device__ float g_gx1b[(size_t)NS*G];      // [s][G]
static __device__ float g_h1[(size_t)NS*T*384];    // TIME-MAJOR: [tt][s][384]
static __device__ float g_h2[(size_t)NS*384];
static __device__ float g_BetaT[(size_t)NS*NS];
static __device__ float g_t3[NS*3];
static __device__ int   g_pid[NS];
static __device__ int   g_off[NS];
static __device__ float g_M[NS*128];
static __device__ float g_E[NS*128];
static __device__ float g_n1[NS*128];
static __device__ float g_n2[NS*128];

__device__ __forceinline__ float sigm(float x){ return 1.f/(1.f+expf(-x)); }
__device__ __forceinline__ u64 pk(float x, float y){ u64 r; asm("mov.b64 %0,{%1,%2};":"=l"(r):"f"(x),"f"(y)); return r; }
__device__ __forceinline__ void fma2(u64& d, u64 a, u64 b){ asm("fma.rn.f32x2 %0,%1,%2,%0;":"+l"(d):"l"(a),"l"(b)); }
__device__ __forceinline__ void unpk(u64 v, float& x, float& y){ asm("mov.b64 {%0,%1},%2;":"=f"(x),"=f"(y):"l"(v)); }
__device__ __forceinline__ float lohi(u64 v){ float x,y; unpk(v,x,y); return x+y; }
__device__ __forceinline__ uint32_t smem_u32(const void* p){
    uint32_t a; asm("{ .reg .u64 t; cvta.to.shared.u64 t, %1; cvt.u32.u64 %0, t; }":"=r"(a):"l"(p)); return a;
}
__device__ __forceinline__ uint32_t tf32r(float x){
    uint32_t r; asm("cvt.rna.tf32.f32 %0,%1;":"=r"(r):"f"(x)); return r;
}
#define CL_ARRIVE() asm volatile("barrier.cluster.arrive.aligned;" ::: "memory")
#define CL_WAIT()   asm volatile("barrier.cluster.wait.aligned;"   ::: "memory")

__device__ __forceinline__ void mma_tf32(float& c0, float& c1, float& c2, float& c3,
                                         uint32_t a0, uint32_t a1, uint32_t a2, uint32_t a3,
                                         uint32_t b0, uint32_t b1){
    asm volatile(
        "mma.sync.aligned.m16n8k8.row.col.f32.tf32.tf32.f32 "
        "{%0,%1,%2,%3}, {%4,%5,%6,%7}, {%8,%9}, {%0,%1,%2,%3};"
        : "+f"(c0), "+f"(c1), "+f"(c2), "+f"(c3)
        : "r"(a0), "r"(a1), "r"(a2), "r"(a3), "r"(b0), "r"(b1));
}

// ---- gx1 via mma.sync tf32 (R12-proven) ----
__global__ __launch_bounds__(256,2)
void gx1_hmma(const float* __restrict__ A, const float* __restrict__ Bw,
              float* __restrict__ Ct,
              const float* __restrict__ bias0, const float* __restrict__ bias1)
{
    extern __shared__ __align__(16) float csh[];   // [128][132]
    __shared__ __align__(16) float As[16][136];
    __shared__ __align__(16) float Bs[16][136];
    __shared__ float bsh[128];
    const int tt = blockIdx.x >> 3;
    const int s0 = (blockIdx.x & 7) * 128;
    const int n0 = blockIdx.y * 128;
    const int tid = threadIdx.x;
    const int w    = tid >> 5;
    const int lane = tid & 31;
    const int gid  = lane >> 2;
    const int tid4 = lane & 3;
    const int m0w  = (w & 1) * 64;
    const int n0w  = (w >> 1) * 32;
    const int row = tid>>1, kq = (tid&1)*8;
    const float* aBase = A + ((size_t)tt*NS + s0 + row)*384 + kq;
    const float* bBase = Bw + (size_t)(n0+row)*384 + kq;

    if (tid < 128) bsh[tid] = bias0[n0+tid] + bias1[n0+tid];

    float acc[4][4][4];
    #pragma unroll
    for (int mi=0;mi<4;mi++)
        #pragma unroll
        for (int ni=0;ni<4;ni++)
            #pragma unroll
            for (int q=0;q<4;q++) acc[mi][ni][q]=0.f;

    for (int k0=0;k0<384;k0+=16){
        float4 a0 = *(const float4*)(aBase + k0);
        float4 a1 = *(const float4*)(aBase + k0 + 4);
        float4 b0 = *(const float4*)(bBase + k0);
        float4 b1 = *(const float4*)(bBase + k0 + 4);
        __syncthreads();
        As[kq+0][row]=__uint_as_float(tf32r(a0.x)); As[kq+1][row]=__uint_as_float(tf32r(a0.y));
        As[kq+2][row]=__uint_as_float(tf32r(a0.z)); As[kq+3][row]=__uint_as_float(tf32r(a0.w));
        As[kq+4][row]=__uint_as_float(tf32r(a1.x)); As[kq+5][row]=__uint_as_float(tf32r(a1.y));
        As[kq+6][row]=__uint_as_float(tf32r(a1.z)); As[kq+7][row]=__uint_as_float(tf32r(a1.w));
        Bs[kq+0][row]=__uint_as_float(tf32r(b0.x)); Bs[kq+1][row]=__uint_as_float(tf32r(b0.y));
        Bs[kq+2][row]=__uint_as_float(tf32r(b0.z)); Bs[kq+3][row]=__uint_as_float(tf32r(b0.w));
        Bs[kq+4][row]=__uint_as_float(tf32r(b1.x)); Bs[kq+5][row]=__uint_as_float(tf32r(b1.y));
        Bs[kq+6][row]=__uint_as_float(tf32r(b1.z)); Bs[kq+7][row]=__uint_as_float(tf32r(b1.w));
        __syncthreads();
        #pragma unroll
        for (int k8=0;k8<16;k8+=8){
            uint32_t af[4][4];
            #pragma unroll
            for (int mi=0;mi<4;mi++){
                int m = m0w + mi*16 + gid;
                af[mi][0] = __float_as_uint(As[k8+tid4  ][m  ]);
                af[mi][1] = __float_as_uint(As[k8+tid4  ][m+8]);
                af[mi][2] = __float_as_uint(As[k8+tid4+4][m  ]);
                af[mi][3] = __float_as_uint(As[k8+tid4+4][m+8]);
            }
            uint32_t bf[4][2];
            #pragma unroll
            for (int ni=0;ni<4;ni++){
                int n = n0w + ni*8 + gid;
                bf[ni][0] = __float_as_uint(Bs[k8+tid4  ][n]);
                bf[ni][1] = __float_as_uint(Bs[k8+tid4+4][n]);
            }
            #pragma unroll
            for (int mi=0;mi<4;mi++)
                #pragma unroll
                for (int ni=0;ni<4;ni++)
                    mma_tf32(acc[mi][ni][0], acc[mi][ni][1], acc[mi][ni][2], acc[mi][ni][3],
                             af[mi][0], af[mi][1], af[mi][2], af[mi][3],
                             bf[ni][0], bf[ni][1]);
        }
    }
    __syncthreads();
    #pragma unroll
    for (int mi=0;mi<4;mi++){
        #pragma unroll
        for (int ni=0;ni<4;ni++){
            int nl = n0w + ni*8 + tid4*2;
            int ml = m0w + mi*16 + gid;
            csh[(size_t)(nl  )*132 + ml  ] = acc[mi][ni][0] + bsh[nl];
            csh[(size_t)(nl+1)*132 + ml  ] = acc[mi][ni][1] + bsh[nl+1];
            csh[(size_t)(nl  )*132 + ml+8] = acc[mi][ni][2] + bsh[nl];
            csh[(size_t)(nl+1)*132 + ml+8] = acc[mi][ni][3] + bsh[nl+1];
        }
    }
    __syncthreads();
    {
        int jl = tid>>1, half = (tid&1)*64;
        const float* src = csh + (size_t)jl*132 + half;
        float* dst = Ct + ((size_t)tt*G + n0 + jl)*NS + s0 + half;
        #pragma unroll
        for (int v=0;v<16;v++)
            *(float4*)(dst + v*4) = *(const float4*)(src + v*4);
    }
}

// ---- cluster LSTM with tensor-core matvec. MW=2: SPC=64 (layer0 fwd/bwd);
// MW=1: SPC=32 (layer1 fwd, mode 2). 24 warps = MW(m) x NW(n). Bsh holds the
// rank's 192 gate-rows gate-interleaved (col = ul*4+q) as tf32 bits; Hs holds
// h as tf32 bits (full fp32 h goes to gmem). 2-barrier cluster protocol.
template<int MW>
__global__ __launch_bounds__(768,1) __cluster_dims__(4,1,1)
void lstm_mma(const float* __restrict__ gx_all, const float* __restrict__ Whh_all,
              float* __restrict__ outp, int mode0)
{
    constexpr int SPC = MW*32;
    constexpr int NW  = 24/MW;
    constexpr int NI  = MW;        // n8 tiles per warp
    constexpr int HSP = 196;
    constexpr int BSP = 196;
    extern __shared__ float sm[];
    float* Bsh = sm;               // [192][BSP] tf32 bits, row = ul*4+q
    float* Hs  = sm + 192*BSP;     // [SPC][HSP] tf32 bits

    const int dir  = blockIdx.y;
    const int mode = mode0 + dir;
    const float* gx  = gx_all  + (size_t)dir*NS*T*G;
    const float* Whh = Whh_all + (size_t)dir*G*H;

    const int tid  = threadIdx.x;
    const int w    = tid >> 5;
    const int lane = tid & 31;
    const int gid  = lane >> 2;
    const int tid4 = lane & 3;
    const int mw   = w % MW;
    const int nw   = w / MW;
    const bool ev  = ((tid4 & 1) == 0);
    uint32_t rank; asm("mov.u32 %0, %%cluster_ctarank;" : "=r"(rank));
    const int cid   = blockIdx.x >> 2;
    const int sbase = cid * SPC;
    const int jsl   = (int)rank * 48;
    const uint32_t hs_base = smem_u32(Hs);

    // stage Whh gate-interleaved as tf32: Bsh[ul*4+q][k] = Whh[q*192+jsl+ul][k]
    for (int i = tid; i < 192*48; i += 768){
        int lr = i / 48, c4 = i % 48;
        int ul = lr >> 2, q = lr & 3;
        float4 v = *(const float4*)(Whh + (size_t)(q*192 + jsl + ul)*H + c4*4);
        float* bp = Bsh + lr*BSP + c4*4;
        bp[0]=__uint_as_float(tf32r(v.x)); bp[1]=__uint_as_float(tf32r(v.y));
        bp[2]=__uint_as_float(tf32r(v.z)); bp[3]=__uint_as_float(tf32r(v.w));
    }
    for (int i = tid; i < SPC*HSP; i += 768) Hs[i] = 0.f;
    CL_ARRIVE(); CL_WAIT();

    // per-thread cell state: one (stock,unit) per (mi,ni) tile
    float cst[2][NI];
    #pragma unroll
    for (int a=0;a<2;a++)
        #pragma unroll
        for (int b=0;b<NI;b++) cst[a][b]=0.f;

    // this thread's (stock,unit) per tile
    int sl_t = mw*32 + gid + (ev ? 0 : 8);   // + mi*16
    // unit: ul = 2*(nw*NI + ni) + (tid4>>1)

    for (int step=0; step<T; ++step){
        const int tt = (mode==1) ? (T-1-step) : step;

        float acc[2][NI][4];
        #pragma unroll
        for (int mi=0;mi<2;mi++)
            #pragma unroll
            for (int ni=0;ni<NI;ni++)
                #pragma unroll
                for (int q=0;q<4;q++) acc[mi][ni][q]=0.f;

        #pragma unroll 2
        for (int k8=0;k8<192;k8+=8){
            uint32_t af[2][4];
            #pragma unroll
            for (int mi=0;mi<2;mi++){
                int m = mw*32 + mi*16 + gid;
                af[mi][0] = __float_as_uint(Hs[(m  )*HSP + k8+tid4  ]);
                af[mi][1] = __float_as_uint(Hs[(m+8)*HSP + k8+tid4  ]);
                af[mi][2] = __float_as_uint(Hs[(m  )*HSP + k8+tid4+4]);
                af[mi][3] = __float_as_uint(Hs[(m+8)*HSP + k8+tid4+4]);
            }
            uint32_t bf[NI][2];
            #pragma unroll
            for (int ni=0;ni<NI;ni++){
                int n = (nw*NI + ni)*8 + gid;
                bf[ni][0] = __float_as_uint(Bsh[n*BSP + k8+tid4  ]);
                bf[ni][1] = __float_as_uint(Bsh[n*BSP + k8+tid4+4]);
            }
            #pragma unroll
            for (int mi=0;mi<2;mi++)
                #pragma unroll
                for (int ni=0;ni<NI;ni++)
                    mma_tf32(acc[mi][ni][0], acc[mi][ni][1], acc[mi][ni][2], acc[mi][ni][3],
                             af[mi][0], af[mi][1], af[mi][2], af[mi][3],
                             bf[ni][0], bf[ni][1]);
        }

        CL_ARRIVE();                  // my reads of Hs(t-1) done
        // gx loads in the barrier shadow
        float gxr[2][NI][4];
        #pragma unroll
        for (int mi=0;mi<2;mi++){
            int s = sbase + sl_t + mi*16;
            #pragma unroll
            for (int ni=0;ni<NI;ni++){
                int ul = 2*(nw*NI + ni) + (tid4>>1);
                #pragma unroll
                for (int q=0;q<4;q++)
                    gxr[mi][ni][q] = gx[((size_t)tt*G + q*192 + jsl + ul)*NS + s];
            }
        }
        CL_WAIT();                    // all reads done -> safe to write Hs

        #pragma unroll
        for (int mi=0;mi<2;mi++){
            #pragma unroll
            for (int ni=0;ni<NI;ni++){
                float c0=acc[mi][ni][0], c1=acc[mi][ni][1];
                float c2=acc[mi][ni][2], c3=acc[mi][ni][3];
                float s0 = ev ? c2 : c0;
                float s1 = ev ? c3 : c1;
                float r0 = __shfl_xor_sync(0xffffffffu, s0, 1);
                float r1 = __shfl_xor_sync(0xffffffffu, s1, 1);
                float pi = (ev ? c0 : r0) + gxr[mi][ni][0];
                float pf = (ev ? c1 : r1) + gxr[mi][ni][1];
                float pg = (ev ? r0 : c2) + gxr[mi][ni][2];
                float po = (ev ? r1 : c3) + gxr[mi][ni][3];
                float iv = sigm(pi), fv = sigm(pf);
                float gv = tanhf(pg), ov = sigm(po);
                float cc = fv*cst[mi][ni] + iv*gv;
                cst[mi][ni] = cc;
                float hh = ov*tanhf(cc);
                int sl = sl_t + mi*16;
                int ul = 2*(nw*NI + ni) + (tid4>>1);
                float ht = __uint_as_float(tf32r(hh));
                uint32_t la = hs_base + (uint32_t)(sl*HSP + jsl + ul)*4u;
                Hs[sl*HSP + jsl + ul] = ht;
                #pragma unroll
                for (int r=0;r<4;r++){
                    if (r == (int)rank) continue;
                    uint32_t da; asm("mapa.shared::cluster.u32 %0,%1,%2;":"=r"(da):"r"(la),"r"(r));
                    asm volatile("st.shared::cluster.f32 [%0],%1;"::"r"(da),"f"(ht));
                }
                int s = sbase + sl;
                if (mode==0)      outp[((size_t)tt*NS + s)*384 + jsl + ul] = hh;
                else if (mode==1) outp[((size_t)tt*NS + s)*384 + 192 + jsl + ul] = hh;
                else if (step==T-1) outp[(size_t)s*384 + jsl + ul] = hh;
            }
        }
        CL_ARRIVE();                  // release h(t)
        CL_WAIT();                    // acquire peers' h(t)
    }
}

// ---- transposing gx GEMM (gx0): Ct[tt][n][s] = A[s][tt][k]*B[n][k]+biases
__global__ __launch_bounds__(256,2)
void gemm_nt128T(const float* __restrict__ A, int lda,
                 const float* __restrict__ B, int ldb,
                 float* __restrict__ Ct, int K,
                 const float* __restrict__ bias0, const float* __restrict__ bias1)
{
    extern __shared__ __align__(16) float csh[];   // [128][132]
    __shared__ __align__(16) float As[16][136];
    __shared__ __align__(16) float Bs[16][136];
    const int tt = blockIdx.x >> 3;
    const int s0 = (blockIdx.x & 7) * 128;
    const int n0 = blockIdx.y * 128;
    const int tid = threadIdx.x;
    const int ty = tid>>4, tx = tid&15;
    const int row = tid>>1, kq = (tid&1)*8;
    u64 acc[4][8];
    #pragma unroll
    for (int i=0;i<4;i++)
        #pragma unroll
        for (int j=0;j<8;j++) acc[i][j]=0ull;

    for (int k0=0;k0<K;k0+=16){
        const float* ap = A + ((size_t)(s0+row)*T + tt)*lda + k0 + kq;
        float4 a0 = *(const float4*)ap;
        float4 a1 = *(const float4*)(ap+4);
        float4 b0 = *(const float4*)(B + (size_t)(n0+row)*ldb + k0 + kq);
        float4 b1 = *(const float4*)(B + (size_t)(n0+row)*ldb + k0 + kq + 4);
        __syncthreads();
        As[kq+0][row]=a0.x; As[kq+1][row]=a0.y; As[kq+2][row]=a0.z; As[kq+3][row]=a0.w;
        As[kq+4][row]=a1.x; As[kq+5][row]=a1.y; As[kq+6][row]=a1.z; As[kq+7][row]=a1.w;
        Bs[kq+0][row]=b0.x; Bs[kq+1][row]=b0.y; Bs[kq+2][row]=b0.z; Bs[kq+3][row]=b0.w;
        Bs[kq+4][row]=b1.x; Bs[kq+5][row]=b1.y; Bs[kq+6][row]=b1.z; Bs[kq+7][row]=b1.w;
        __syncthreads();
        #pragma unroll
        for (int k=0;k<16;k++){
            ulonglong2 av0 = *(const ulonglong2*)&As[k][tx*8];
            ulonglong2 av1 = *(const ulonglong2*)&As[k][tx*8+4];
            float4 bA = *(const float4*)&Bs[k][ty*8];
            float4 bB = *(const float4*)&Bs[k][ty*8+4];
            u64 bb[8];
            bb[0]=pk(bA.x,bA.x); bb[1]=pk(bA.y,bA.y); bb[2]=pk(bA.z,bA.z); bb[3]=pk(bA.w,bA.w);
            bb[4]=pk(bB.x,bB.x); bb[5]=pk(bB.y,bB.y); bb[6]=pk(bB.z,bB.z); bb[7]=pk(bB.w,bB.w);
            u64 aa[4] = { av0.x, av0.y, av1.x, av1.y };
            #pragma unroll
            for (int i2=0;i2<4;i2++)
                #pragma unroll
                for (int j=0;j<8;j++) fma2(acc[i2][j], aa[i2], bb[j]);
        }
    }
    float bv[8];
    #pragma unroll
    for (int j=0;j<8;j++){
        int n = n0+ty*8+j;
        bv[j] = bias0[n] + bias1[n];
    }
    __syncthreads();
    #pragma unroll
    for (int j=0;j<8;j++){
        float r[8];
        #pragma unroll
        for (int i2=0;i2<4;i2++){ unpk(acc[i2][j], r[2*i2], r[2*i2+1]); }
        #pragma unroll
        for (int v=0;v<8;v++) r[v] += bv[j];
        float* cp = csh + (size_t)(ty*8+j)*132 + tx*8;
        *(float4*)cp     = make_float4(r[0],r[1],r[2],r[3]);
        *(float4*)(cp+4) = make_float4(r[4],r[5],r[6],r[7]);
    }
    __syncthreads();
    {
        int jl = tid>>1, half = (tid&1)*64;
        const float* src = csh + (size_t)jl*132 + half;
        float* dst = Ct + ((size_t)tt*G + n0 + jl)*NS + s0 + half;
        #pragma unroll
        for (int v=0;v<16;v++)
            *(float4*)(dst + v*4) = *(const float4*)(src + v*4);
    }
}

// ---- plain NT gemm (gx1b), C[m][n] layout ----
__global__ __launch_bounds__(256,2)
void gemm_nt128(const float* __restrict__ A, int lda,
                const float* __restrict__ B, int ldb,
                float* __restrict__ C, int ldc, int K,
                const float* __restrict__ bias0, const float* __restrict__ bias1)
{
    __shared__ __align__(16) float As[16][136];
    __shared__ __align__(16) float Bs[16][136];
    const int m0 = blockIdx.x*128, n0 = blockIdx.y*128;
    const int tid = threadIdx.x;
    const int ty = tid>>4, tx = tid&15;
    const int row = tid>>1, kq = (tid&1)*8;
    u64 acc[4][8];
    #pragma unroll
    for (int i=0;i<4;i++)
        #pragma unroll
        for (int j=0;j<8;j++) acc[i][j]=0ull;

    for (int k0=0;k0<K;k0+=16){
        float4 a0 = *(const float4*)(A + (size_t)(m0+row)*lda + k0 + kq);
        float4 a1 = *(const float4*)(A + (size_t)(m0+row)*lda + k0 + kq + 4);
        float4 b0 = *(const float4*)(B + (size_t)(n0+row)*ldb + k0 + kq);
        float4 b1 = *(const float4*)(B + (size_t)(n0+row)*ldb + k0 + kq + 4);
        __syncthreads();
        As[kq+0][row]=a0.x; As[kq+1][row]=a0.y; As[kq+2][row]=a0.z; As[kq+3][row]=a0.w;
        As[kq+4][row]=a1.x; As[kq+5][row]=a1.y; As[kq+6][row]=a1.z; As[kq+7][row]=a1.w;
        Bs[kq+0][row]=b0.x; Bs[kq+1][row]=b0.y; Bs[kq+2][row]=b0.z; Bs[kq+3][row]=b0.w;
        Bs[kq+4][row]=b1.x; Bs[kq+5][row]=b1.y; Bs[kq+6][row]=b1.z; Bs[kq+7][row]=b1.w;
        __syncthreads();
        #pragma unroll
        for (int k=0;k<16;k++){
            ulonglong2 av0 = *(const ulonglong2*)&As[k][ty*8];
            ulonglong2 av1 = *(const ulonglong2*)&As[k][ty*8+4];
            float4 bA = *(const float4*)&Bs[k][tx*8];
            float4 bB = *(const float4*)&Bs[k][tx*8+4];
            u64 bb[8];
            bb[0]=pk(bA.x,bA.x); bb[1]=pk(bA.y,bA.y); bb[2]=pk(bA.z,bA.z); bb[3]=pk(bA.w,bA.w);
            bb[4]=pk(bB.x,bB.x); bb[5]=pk(bB.y,bB.y); bb[6]=pk(bB.z,bB.z); bb[7]=pk(bB.w,bB.w);
            u64 aa[4] = { av0.x, av0.y, av1.x, av1.y };
            #pragma unroll
            for (int i2=0;i2<4;i2++)
                #pragma unroll
                for (int j=0;j<8;j++) fma2(acc[i2][j], aa[i2], bb[j]);
        }
    }
    float bv[8];
    #pragma unroll
    for (int j=0;j<8;j++){
        int n = n0+tx*8+j;
        float v = 0.f;
        if (bias0) v += bias0[n];
        if (bias1) v += bias1[n];
        bv[j]=v;
    }
    #pragma unroll
    for (int i2=0;i2<4;i2++){
        float r0[8], r1[8];
        #pragma unroll
        for (int j=0;j<8;j++){ unpk(acc[i2][j], r0[j], r1[j]); r0[j]+=bv[j]; r1[j]+=bv[j]; }
        float* c0 = C + (size_t)(m0+ty*8+2*i2)*ldc + n0 + tx*8;
        float* c1 = C + (size_t)(m0+ty*8+2*i2+1)*ldc + n0 + tx*8;
        *(float4*)c0     = make_float4(r0[0],r0[1],r0[2],r0[3]);
        *(float4*)(c0+4) = make_float4(r0[4],r0[5],r0[6],r0[7]);
        *(float4*)c1     = make_float4(r1[0],r1[1],r1[2],r1[3]);
        *(float4*)(c1+4) = make_float4(r1[4],r1[5],r1[6],r1[7]);
    }
}

// ---- C[m][n] = sum_k A[m][k]*B[k][n] (+addC), 64x64 tile, 4x4 micro.
__global__ __launch_bounds__(256,1)
void gemm_nn64(const float* __restrict__ A, int lda,
               const float* __restrict__ B, int ldb,
               float* __restrict__ C, int ldc, int K,
               const float* __restrict__ addC)
{
    __shared__ __align__(16) float As[16][68];
    __shared__ __align__(16) float Bs[16][68];
    const int m0 = blockIdx.x*64, n0 = blockIdx.y*64;
    const int tid = threadIdx.x;
    const int ty = tid>>4, tx = tid&15;
    const int arow = tid>>2, akq = (tid&3)*4;
    const int bk = tid>>4, bnq = (tid&15)*4;
    float acc[4][4];
    #pragma unroll
    for (int i=0;i<4;i++)
        #pragma unroll
        for (int j=0;j<4;j++) acc[i][j]=0.f;

    for (int k0=0;k0<K;k0+=16){
        float4 av = *(const float4*)(A + (size_t)(m0+arow)*lda + k0 + akq);
        float4 bv = *(const float4*)(B + (size_t)(k0+bk)*ldb + n0 + bnq);
        __syncthreads();
        As[akq+0][arow]=av.x; As[akq+1][arow]=av.y; As[akq+2][arow]=av.z; As[akq+3][arow]=av.w;
        *(float4*)&Bs[bk][bnq] = bv;
        __syncthreads();
        #pragma unroll
        for (int k=0;k<16;k++){
            float a[4],b[4];
            #pragma unroll
            for (int i=0;i<4;i++){ a[i]=As[k][ty*4+i]; b[i]=Bs[k][tx*4+i]; }
            #pragma unroll
            for (int i=0;i<4;i++)
                #pragma unroll
                for (int j=0;j<4;j++) acc[i][j]+=a[i]*b[j];
        }
    }
    #pragma unroll
    for (int i=0;i<4;i++){
        int m = m0+ty*4+i;
        float* cp = C + (size_t)m*ldc + n0 + tx*4;
        const float* ap = addC ? addC + (size_t)m*ldc + n0 + tx*4 : (const float*)0;
        #pragma unroll
        for (int j=0;j<4;j++){
            float v = acc[i][j];
            if (ap) v += ap[j];
            cp[j] = v;
        }
    }
}

// ---- layer1 bwd @ t=31 only (h0=c0=0) ----
__global__ void bwd1_last(const float* __restrict__ gxb, float* __restrict__ h2)
{
    int n = blockIdx.x, j = threadIdx.x;
    const float* g = gxb + (size_t)n*G;
    float iv = sigm(g[j]);
    float gv = tanhf(g[2*H+j]);
    float ov = sigm(g[3*H+j]);
    float cc = iv*gv;
    h2[(size_t)n*384 + 192 + j] = ov*tanhf(cc);
}

// ---- dynamic network ----
__global__ void dyn_scalars(const float* __restrict__ x, const float* __restrict__ theta,
                            int* __restrict__ pid, int* __restrict__ off)
{
    int n = blockIdx.x*blockDim.x + threadIdx.x;
    if (n >= NS) return;
    float th  = theta[n];
    float x30 = x[((size_t)n*T + 30)*NF];
    float x31 = x[((size_t)n*T + 31)*NF];
    int p0 = (x30 > th) ? 1 : ((x30 < -th) ? -1 : 0);
    int p1 = (x31 > th) ? 1 : ((x31 < -th) ? -1 : 0);
    pid[n] = (p0+1)*3 + (p1+1);
    off[n] = (p1+1)*3;
}

__global__ __launch_bounds__(256,1)
void dyn_beta(const float* __restrict__ PP, const int* __restrict__ pid,
              const int* __restrict__ off, float* __restrict__ BetaT,
              float* __restrict__ t3)
{
    __shared__ float s_raw[1024];
    __shared__ float s_adj[1024*3];
    __shared__ float s_red[256];
    const int y = blockIdx.x, tid = threadIdx.x;
    const int offy = off[y];
    for (int x=tid; x<NS; x+=256){
        size_t base = ((size_t)x*NS + y)*81 + (size_t)pid[x]*9 + offy;
        float a0=PP[base], a1=PP[base+1], a2=PP[base+2];
        s_adj[x*3+0]=a0; s_adj[x*3+1]=a1; s_adj[x*3+2]=a2;
        float nr = sqrtf(a0*a0+a1*a1+a2*a2);
        s_raw[x] = (nr > 0.38f) ? nr : 0.f;
    }
    __syncthreads();
    float lm = -1e30f;
    for (int x=tid; x<NS; x+=256) lm = fmaxf(lm, s_raw[x]);
    s_red[tid]=lm; __syncthreads();
    for (int o=128;o>0;o>>=1){ if(tid<o) s_red[tid]=fmaxf(s_red[tid],s_red[tid+o]); __syncthreads(); }
    const float mx = s_red[0];
    __syncthreads();
    float ls = 0.f;
    for (int x=tid; x<NS; x+=256){ float e=expf(s_raw[x]-mx); s_raw[x]=e; ls+=e; }
    s_red[tid]=ls; __syncthreads();
    for (int o=128;o>0;o>>=1){ if(tid<o) s_red[tid]+=s_red[tid+o]; __syncthreads(); }
    const float inv = 1.f/s_red[0];
    __syncthreads();
    float t0=0.f,t1=0.f,t2=0.f;
    for (int x=tid; x<NS; x+=256){
        float b = s_raw[x]*inv;
        BetaT[(size_t)y*NS + x] = b;
        t0 += b*s_adj[x*3+0]; t1 += b*s_adj[x*3+1]; t2 += b*s_adj[x*3+2];
    }
    s_red[tid]=t0; __syncthreads();
    for (int o=128;o>0;o>>=1){ if(tid<o) s_red[tid]+=s_red[tid+o]; __syncthreads(); }
    if(tid==0) t3[y*3+0]=s_red[0];
    __syncthreads();
    s_red[tid]=t1; __syncthreads();
    for (int o=128;o>0;o>>=1){ if(tid<o) s_red[tid]+=s_red[tid+o]; __syncthreads(); }
    if(tid==0) t3[y*3+1]=s_red[0];
    __syncthreads();
    s_red[tid]=t2; __syncthreads();
    for (int o=128;o>0;o>>=1){ if(tid<o) s_red[tid]+=s_red[tid+o]; __syncthreads(); }
    if(tid==0) t3[y*3+2]=s_red[0];
}

__global__ void agg_extra(const float* __restrict__ t3, const float* __restrict__ Wa,
                          const float* __restrict__ b, float* __restrict__ E)
{
    int y = blockIdx.x, u = threadIdx.x;
    float v = b[u] + t3[y*3+0]*Wa[u] + t3[y*3+1]*Wa[128+u] + t3[y*3+2]*Wa[256+u];
    E[(size_t)y*128 + u] = v;
}

__global__ void out_kernel(const float* __restrict__ nfeat, const float* __restrict__ n1,
                           const float* __restrict__ n2, const float* __restrict__ W,
                           const float* __restrict__ b, float* __restrict__ out)
{
    int warp = (blockIdx.x*blockDim.x + threadIdx.x)>>5;
    int lane = threadIdx.x & 31;
    if (warp >= NS*2) return;
    int n = warp>>1, o = warp&1;
    float s = 0.f;
    for (int k=lane;k<384;k+=32) s += nfeat[(size_t)n*384+k]*W[k*2+o];
    for (int k=lane;k<128;k+=32) s += n1[(size_t)n*128+k]*W[(384+k)*2+o];
    for (int k=lane;k<128;k+=32) s += n2[(size_t)n*128+k]*W[(512+k)*2+o];
    #pragma unroll
    for (int m=16;m>0;m>>=1) s += __shfl_xor_sync(0xffffffffu, s, m);
    if (lane==0) out[warp] = tanhf(s + b[o]);
}

extern "C" void kernel_launch(void* const* d_in, const int* in_sizes, int n_in,
                              void* d_out, int out_size)
{
    const float* x     = (const float*)d_in[0];
    const float* theta = (const float*)d_in[1];
    const float* PP    = (const float*)d_in[2];
    const float* Wih0  = (const float*)d_in[3];
    const float* Whh0  = (const float*)d_in[4];
    const float* bih0  = (const float*)d_in[5];
    const float* bhh0  = (const float*)d_in[6];
    const float* Wih1  = (const float*)d_in[7];
    const float* Whh1  = (const float*)d_in[8];
    const float* bih1  = (const float*)d_in[9];
    const float* bhh1  = (const float*)d_in[10];
    const float* Wagg1 = (const float*)d_in[11];
    const float* bagg1 = (const float*)d_in[12];
    const float* Wagg2 = (const float*)d_in[13];
    const float* bagg2 = (const float*)d_in[14];
    const float* Wout  = (const float*)d_in[15];
    const float* bout  = (const float*)d_in[16];
    float* out = (float*)d_out;

    float *p_gx0, *p_gx1, *p_gx1b, *p_h1, *p_h2, *p_BetaT, *p_t3, *p_M, *p_E, *p_n1, *p_n2;
    int *p_pid, *p_off;
    cudaGetSymbolAddress((void**)&p_gx0,  g_gx0);
    cudaGetSymbolAddress((void**)&p_gx1,  g_gx1);
    cudaGetSymbolAddress((void**)&p_gx1b, g_gx1b);
    cudaGetSymbolAddress((void**)&p_h1,   g_h1);
    cudaGetSymbolAddress((void**)&p_h2,   g_h2);
    cudaGetSymbolAddress((void**)&p_BetaT,g_BetaT);
    cudaGetSymbolAddress((void**)&p_t3,   g_t3);
    cudaGetSymbolAddress((void**)&p_pid,  g_pid);
    cudaGetSymbolAddress((void**)&p_off,  g_off);
    cudaGetSymbolAddress((void**)&p_M,    g_M);
    cudaGetSymbolAddress((void**)&p_E,    g_E);
    cudaGetSymbolAddress((void**)&p_n1,   g_n1);
    cudaGetSymbolAddress((void**)&p_n2,   g_n2);

    const int SM64 = (192*196 + 64*196)*4;      // lstm_mma<2>
    const int SM32 = (192*196 + 32*196)*4;      // lstm_mma<1>
    const int CSH  = 128*132*4;
    cudaFuncSetAttribute(lstm_mma<2>, cudaFuncAttributeMaxDynamicSharedMemorySize, SM64);
    cudaFuncSetAttribute(lstm_mma<1>, cudaFuncAttributeMaxDynamicSharedMemorySize, SM32);
    cudaFuncSetAttribute(gemm_nt128T, cudaFuncAttributeMaxDynamicSharedMemorySize, CSH);
    cudaFuncSetAttribute(gx1_hmma, cudaFuncAttributeMaxDynamicSharedMemorySize, CSH);

    // #1-2: layer0 gx, time-major, both dirs
    for (int d=0; d<2; d++){
        gemm_nt128T<<<dim3(256,6), 256, CSH>>>(x, NF, Wih0 + (size_t)d*G*NF, NF,
                                               p_gx0 + (size_t)d*NS*T*G, NF,
                                               bih0 + d*G, bhh0 + d*G);
    }
    // #3: layer0 recurrence (fwd+bwd), tensor-core matvec — PROFILED region
    lstm_mma<2><<<dim3(64,2), 768, SM64>>>(p_gx0, Whh0, p_h1, 0);

    // #4: layer1 fwd gx via mma.sync tf32
    gx1_hmma<<<dim3(256,6), 256, CSH>>>(p_h1, Wih1, p_gx1, bih1, bhh1);

    // #5-6: dynamic network
    dyn_scalars<<<4, 256>>>(x, theta, p_pid, p_off);
    dyn_beta<<<NS, 256>>>(PP, p_pid, p_off, p_BetaT, p_t3);

    // #7: layer1 bwd gx at t=31 (rows = s contiguous in time-major h1)
    gemm_nt128<<<dim3(8,6), 256>>>(p_h1 + (size_t)31*NS*384, 384,
                                   Wih1 + (size_t)G*384, 384,
                                   p_gx1b, G, 384, bih1 + G, bhh1 + G);

    // #8-9: layer1 recurrence fwd (tensor-core); bwd single step
    lstm_mma<1><<<dim3(128,1), 768, SM32>>>(p_gx1, Whh1, p_h2, 2);
    bwd1_last<<<NS, H>>>(p_gx1b, p_h2);

    // #10-12: agg layer 1
    agg_extra<<<NS, 128>>>(p_t3, Wagg1 + (size_t)384*128, bagg1, p_E);
    gemm_nn64<<<dim3(16,2), 256>>>(p_h2, 384, Wagg1, 128, p_M, 128, 384, (const float*)0);
    gemm_nn64<<<dim3(16,2), 256>>>(p_BetaT, NS, p_M, 128, p_n1, 128, NS, p_E);

    // #13-15: agg layer 2
    gemm_nn64<<<dim3(16,2), 256>>>(p_n1, 128, Wagg2, 128, p_M, 128, 128, (const float*)0);
    agg_extra<<<NS, 128>>>(p_t3, Wagg2 + (size_t)128*128, bagg2, p_E);
    gemm_nn64<<<dim3(16,2), 256>>>(p_BetaT, NS, p_M, 128, p_n2, 128, NS, p_E);

    // #16: output
    out_kernel<<<256, 256>>>(p_h2, p_n1, p_n2, Wout, bout, out);
}

// round 14
// speedup vs baseline: 2.0682x; 1.0306x over previous
#include <cuda_runtime.h>
#include <math.h>
#include <stdint.h>

#define NS 1024
#define T  32
#define NF 16
#define H  192
#define G  768

typedef unsigned long long u64;

static __device__ float g_gx0[(size_t)2*NS*T*G];   // time-major: [dir][tt][G][NS]
static __device__ float g_gx1[(size_t)NS*T*G];     // time-major: [tt][G][NS]
static __device__ float g_gx1b[(size_t)NS*G];      // [s][G]
static __device__ float g_h1[(size_t)NS*T*384];    // TIME-MAJOR: [tt][s][384]
static __device__ float g_h2[(size_t)NS*384];
static __device__ float g_BetaT[(size_t)NS*NS];
static __device__ float g_t3[NS*3];
static __device__ int   g_pid[NS];
static __device__ int   g_off[NS];
static __device__ float g_M[NS*128];
static __device__ float g_E[NS*128];
static __device__ float g_n1[NS*128];
static __device__ float g_n2[NS*128];

__device__ __forceinline__ float sigm(float x){ return 1.f/(1.f+expf(-x)); }
__device__ __forceinline__ u64 pk(float x, float y){ u64 r; asm("mov.b64 %0,{%1,%2};":"=l"(r):"f"(x),"f"(y)); return r; }
__device__ __forceinline__ void fma2(u64& d, u64 a, u64 b){ asm("fma.rn.f32x2 %0,%1,%2,%0;":"+l"(d):"l"(a),"l"(b)); }
__device__ __forceinline__ void unpk(u64 v, float& x, float& y){ asm("mov.b64 {%0,%1},%2;":"=f"(x),"=f"(y):"l"(v)); }
__device__ __forceinline__ float lohi(u64 v){ float x,y; unpk(v,x,y); return x+y; }
__device__ __forceinline__ uint32_t smem_u32(const void* p){
    uint32_t a; asm("{ .reg .u64 t; cvta.to.shared.u64 t, %1; cvt.u32.u64 %0, t; }":"=r"(a):"l"(p)); return a;
}
__device__ __forceinline__ uint32_t tf32r(float x){
    uint32_t r; asm("cvt.rna.tf32.f32 %0,%1;":"=r"(r):"f"(x)); return r;
}
#define CL_ARRIVE() asm volatile("barrier.cluster.arrive.aligned;" ::: "memory")
#define CL_WAIT()   asm volatile("barrier.cluster.wait.aligned;"   ::: "memory")

__device__ __forceinline__ void mma_tf32(float& c0, float& c1, float& c2, float& c3,
                                         uint32_t a0, uint32_t a1, uint32_t a2, uint32_t a3,
                                         uint32_t b0, uint32_t b1){
    asm volatile(
        "mma.sync.aligned.m16n8k8.row.col.f32.tf32.tf32.f32 "
        "{%0,%1,%2,%3}, {%4,%5,%6,%7}, {%8,%9}, {%0,%1,%2,%3};"
        : "+f"(c0), "+f"(c1), "+f"(c2), "+f"(c3)
        : "r"(a0), "r"(a1), "r"(a2), "r"(a3), "r"(b0), "r"(b1));
}

// ---- generic gx GEMM via mma.sync tf32, double-buffered smem tiles.
// Ct[tt][n][s] = A_row(s) @ B[n][0:K]^T + bias0[n]+bias1[n]
// A row address: A + (s0+row)*rstride + tt*tmul (+k). B: ldb == K.
// grid.x = tt*8 + sblk, grid.y = nblk(6). 256 thr, 8 warps, warp tile 64x32.
__global__ __launch_bounds__(256,2)
void gx_hmma(const float* __restrict__ A, int rstride, size_t tmul,
             const float* __restrict__ Bw, float* __restrict__ Ct, int K,
             const float* __restrict__ bias0, const float* __restrict__ bias1)
{
    extern __shared__ __align__(16) float dyn[];
    // buffers: buf b -> As at dyn + b*4352, Bs at + 2176  (16*136 = 2176)
    float* csh = dyn;                 // [128][132] reused for epilogue
    __shared__ float bsh[128];
    const int tt = blockIdx.x >> 3;
    const int s0 = (blockIdx.x & 7) * 128;
    const int n0 = blockIdx.y * 128;
    const int tid = threadIdx.x;
    const int w    = tid >> 5;
    const int lane = tid & 31;
    const int gid  = lane >> 2;
    const int tid4 = lane & 3;
    const int m0w  = (w & 1) * 64;
    const int n0w  = (w >> 1) * 32;
    const int row = tid>>1, kq = (tid&1)*8;
    const float* aBase = A + (size_t)(s0+row)*rstride + (size_t)tt*tmul + kq;
    const float* bBase = Bw + (size_t)(n0+row)*K + kq;

    if (tid < 128) bsh[tid] = bias0[n0+tid] + bias1[n0+tid];

    float acc[4][4][4];
    #pragma unroll
    for (int mi=0;mi<4;mi++)
        #pragma unroll
        for (int ni=0;ni<4;ni++)
            #pragma unroll
            for (int q=0;q<4;q++) acc[mi][ni][q]=0.f;

    float4 a0 = *(const float4*)(aBase);
    float4 a1 = *(const float4*)(aBase + 4);
    float4 b0 = *(const float4*)(bBase);
    float4 b1 = *(const float4*)(bBase + 4);
    {
        float* As = dyn; float* Bs = dyn + 2176;
        As[(kq+0)*136+row]=__uint_as_float(tf32r(a0.x)); As[(kq+1)*136+row]=__uint_as_float(tf32r(a0.y));
        As[(kq+2)*136+row]=__uint_as_float(tf32r(a0.z)); As[(kq+3)*136+row]=__uint_as_float(tf32r(a0.w));
        As[(kq+4)*136+row]=__uint_as_float(tf32r(a1.x)); As[(kq+5)*136+row]=__uint_as_float(tf32r(a1.y));
        As[(kq+6)*136+row]=__uint_as_float(tf32r(a1.z)); As[(kq+7)*136+row]=__uint_as_float(tf32r(a1.w));
        Bs[(kq+0)*136+row]=__uint_as_float(tf32r(b0.x)); Bs[(kq+1)*136+row]=__uint_as_float(tf32r(b0.y));
        Bs[(kq+2)*136+row]=__uint_as_float(tf32r(b0.z)); Bs[(kq+3)*136+row]=__uint_as_float(tf32r(b0.w));
        Bs[(kq+4)*136+row]=__uint_as_float(tf32r(b1.x)); Bs[(kq+5)*136+row]=__uint_as_float(tf32r(b1.y));
        Bs[(kq+6)*136+row]=__uint_as_float(tf32r(b1.z)); Bs[(kq+7)*136+row]=__uint_as_float(tf32r(b1.w));
    }
    __syncthreads();

    int buf = 0;
    for (int k0=0;k0<K;k0+=16){
        const bool nxt = (k0+16)<K;
        if (nxt){
            a0 = *(const float4*)(aBase + k0+16);
            a1 = *(const float4*)(aBase + k0+20);
            b0 = *(const float4*)(bBase + k0+16);
            b1 = *(const float4*)(bBase + k0+20);
        }
        const float* As = dyn + buf*4352;
        const float* Bs = As + 2176;
        #pragma unroll
        for (int k8=0;k8<16;k8+=8){
            uint32_t af[4][4];
            #pragma unroll
            for (int mi=0;mi<4;mi++){
                int m = m0w + mi*16 + gid;
                af[mi][0] = __float_as_uint(As[(k8+tid4  )*136 + m  ]);
                af[mi][1] = __float_as_uint(As[(k8+tid4  )*136 + m+8]);
                af[mi][2] = __float_as_uint(As[(k8+tid4+4)*136 + m  ]);
                af[mi][3] = __float_as_uint(As[(k8+tid4+4)*136 + m+8]);
            }
            uint32_t bf[4][2];
            #pragma unroll
            for (int ni=0;ni<4;ni++){
                int n = n0w + ni*8 + gid;
                bf[ni][0] = __float_as_uint(Bs[(k8+tid4  )*136 + n]);
                bf[ni][1] = __float_as_uint(Bs[(k8+tid4+4)*136 + n]);
            }
            #pragma unroll
            for (int mi=0;mi<4;mi++)
                #pragma unroll
                for (int ni=0;ni<4;ni++)
                    mma_tf32(acc[mi][ni][0], acc[mi][ni][1], acc[mi][ni][2], acc[mi][ni][3],
                             af[mi][0], af[mi][1], af[mi][2], af[mi][3],
                             bf[ni][0], bf[ni][1]);
        }
        if (nxt){
            float* An = dyn + (buf^1)*4352;
            float* Bn = An + 2176;
            An[(kq+0)*136+row]=__uint_as_float(tf32r(a0.x)); An[(kq+1)*136+row]=__uint_as_float(tf32r(a0.y));
            An[(kq+2)*136+row]=__uint_as_float(tf32r(a0.z)); An[(kq+3)*136+row]=__uint_as_float(tf32r(a0.w));
            An[(kq+4)*136+row]=__uint_as_float(tf32r(a1.x)); An[(kq+5)*136+row]=__uint_as_float(tf32r(a1.y));
            An[(kq+6)*136+row]=__uint_as_float(tf32r(a1.z)); An[(kq+7)*136+row]=__uint_as_float(tf32r(a1.w));
            Bn[(kq+0)*136+row]=__uint_as_float(tf32r(b0.x)); Bn[(kq+1)*136+row]=__uint_as_float(tf32r(b0.y));
            Bn[(kq+2)*136+row]=__uint_as_float(tf32r(b0.z)); Bn[(kq+3)*136+row]=__uint_as_float(tf32r(b0.w));
            Bn[(kq+4)*136+row]=__uint_as_float(tf32r(b1.x)); Bn[(kq+5)*136+row]=__uint_as_float(tf32r(b1.y));
            Bn[(kq+6)*136+row]=__uint_as_float(tf32r(b1.z)); Bn[(kq+7)*136+row]=__uint_as_float(tf32r(b1.w));
            __syncthreads();
            buf ^= 1;
        }
    }
    __syncthreads();
    // epilogue: transpose via csh[n_local][m_local] (+bias on n)
    #pragma unroll
    for (int mi=0;mi<4;mi++){
        #pragma unroll
        for (int ni=0;ni<4;ni++){
            int nl = n0w + ni*8 + tid4*2;
            int ml = m0w + mi*16 + gid;
            csh[(size_t)(nl  )*132 + ml  ] = acc[mi][ni][0] + bsh[nl];
            csh[(size_t)(nl+1)*132 + ml  ] = acc[mi][ni][1] + bsh[nl+1];
            csh[(size_t)(nl  )*132 + ml+8] = acc[mi][ni][2] + bsh[nl];
            csh[(size_t)(nl+1)*132 + ml+8] = acc[mi][ni][3] + bsh[nl+1];
        }
    }
    __syncthreads();
    {
        int jl = tid>>1, half = (tid&1)*64;
        const float* src = csh + (size_t)jl*132 + half;
        float* dst = Ct + ((size_t)tt*G + n0 + jl)*NS + s0 + half;
        #pragma unroll
        for (int v=0;v<16;v++)
            *(float4*)(dst + v*4) = *(const float4*)(src + v*4);
    }
}

// ---- cluster LSTM with tensor-core matvec, MW=2 (SPC=64), 2-barrier.
__global__ __launch_bounds__(768,1) __cluster_dims__(4,1,1)
void lstm_mma2(const float* __restrict__ gx_all, const float* __restrict__ Whh_all,
               float* __restrict__ outp)
{
    constexpr int MW = 2, SPC = 64, NI = 2, HSP = 196, BSP = 196;
    extern __shared__ float sm[];
    float* Bsh = sm;               // [192][BSP] tf32 bits, row = ul*4+q
    float* Hs  = sm + 192*BSP;     // [SPC][HSP] tf32 bits

    const int dir  = blockIdx.y;        // 0 = fwd, 1 = bwd
    const float* gx  = gx_all  + (size_t)dir*NS*T*G;
    const float* Whh = Whh_all + (size_t)dir*G*H;

    const int tid  = threadIdx.x;
    const int w    = tid >> 5;
    const int lane = tid & 31;
    const int gid  = lane >> 2;
    const int tid4 = lane & 3;
    const int mw   = w % MW;
    const int nw   = w / MW;
    const bool ev  = ((tid4 & 1) == 0);
    uint32_t rank; asm("mov.u32 %0, %%cluster_ctarank;" : "=r"(rank));
    const int cid   = blockIdx.x >> 2;
    const int sbase = cid * SPC;
    const int jsl   = (int)rank * 48;
    const uint32_t hs_base = smem_u32(Hs);

    for (int i = tid; i < 192*48; i += 768){
        int lr = i / 48, c4 = i % 48;
        int ul = lr >> 2, q = lr & 3;
        float4 v = *(const float4*)(Whh + (size_t)(q*192 + jsl + ul)*H + c4*4);
        float* bp = Bsh + lr*BSP + c4*4;
        bp[0]=__uint_as_float(tf32r(v.x)); bp[1]=__uint_as_float(tf32r(v.y));
        bp[2]=__uint_as_float(tf32r(v.z)); bp[3]=__uint_as_float(tf32r(v.w));
    }
    for (int i = tid; i < SPC*HSP; i += 768) Hs[i] = 0.f;
    CL_ARRIVE(); CL_WAIT();

    float cst[2][NI];
    #pragma unroll
    for (int a=0;a<2;a++)
        #pragma unroll
        for (int b=0;b<NI;b++) cst[a][b]=0.f;

    int sl_t = mw*32 + gid + (ev ? 0 : 8);

    for (int step=0; step<T; ++step){
        const int tt = (dir==1) ? (T-1-step) : step;

        float acc[2][NI][4];
        #pragma unroll
        for (int mi=0;mi<2;mi++)
            #pragma unroll
            for (int ni=0;ni<NI;ni++)
                #pragma unroll
                for (int q=0;q<4;q++) acc[mi][ni][q]=0.f;

        #pragma unroll 2
        for (int k8=0;k8<192;k8+=8){
            uint32_t af[2][4];
            #pragma unroll
            for (int mi=0;mi<2;mi++){
                int m = mw*32 + mi*16 + gid;
                af[mi][0] = __float_as_uint(Hs[(m  )*HSP + k8+tid4  ]);
                af[mi][1] = __float_as_uint(Hs[(m+8)*HSP + k8+tid4  ]);
                af[mi][2] = __float_as_uint(Hs[(m  )*HSP + k8+tid4+4]);
                af[mi][3] = __float_as_uint(Hs[(m+8)*HSP + k8+tid4+4]);
            }
            uint32_t bf[NI][2];
            #pragma unroll
            for (int ni=0;ni<NI;ni++){
                int n = (nw*NI + ni)*8 + gid;
                bf[ni][0] = __float_as_uint(Bsh[n*BSP + k8+tid4  ]);
                bf[ni][1] = __float_as_uint(Bsh[n*BSP + k8+tid4+4]);
            }
            #pragma unroll
            for (int mi=0;mi<2;mi++)
                #pragma unroll
                for (int ni=0;ni<NI;ni++)
                    mma_tf32(acc[mi][ni][0], acc[mi][ni][1], acc[mi][ni][2], acc[mi][ni][3],
                             af[mi][0], af[mi][1], af[mi][2], af[mi][3],
                             bf[ni][0], bf[ni][1]);
        }

        CL_ARRIVE();
        float gxr[2][NI][4];
        #pragma unroll
        for (int mi=0;mi<2;mi++){
            int s = sbase + sl_t + mi*16;
            #pragma unroll
            for (int ni=0;ni<NI;ni++){
                int ul = 2*(nw*NI + ni) + (tid4>>1);
                #pragma unroll
                for (int q=0;q<4;q++)
                    gxr[mi][ni][q] = gx[((size_t)tt*G + q*192 + jsl + ul)*NS + s];
            }
        }
        CL_WAIT();

        float hout[2][NI];
        #pragma unroll
        for (int mi=0;mi<2;mi++){
            #pragma unroll
            for (int ni=0;ni<NI;ni++){
                float c0=acc[mi][ni][0], c1=acc[mi][ni][1];
                float c2=acc[mi][ni][2], c3=acc[mi][ni][3];
                float s0 = ev ? c2 : c0;
                float s1 = ev ? c3 : c1;
                float r0 = __shfl_xor_sync(0xffffffffu, s0, 1);
                float r1 = __shfl_xor_sync(0xffffffffu, s1, 1);
                float pi = (ev ? c0 : r0) + gxr[mi][ni][0];
                float pf = (ev ? c1 : r1) + gxr[mi][ni][1];
                float pg = (ev ? r0 : c2) + gxr[mi][ni][2];
                float po = (ev ? r1 : c3) + gxr[mi][ni][3];
                float iv = sigm(pi), fv = sigm(pf);
                float gv = tanhf(pg), ov = sigm(po);
                float cc = fv*cst[mi][ni] + iv*gv;
                cst[mi][ni] = cc;
                float hh = ov*tanhf(cc);
                hout[mi][ni] = hh;
                int sl = sl_t + mi*16;
                int ul = 2*(nw*NI + ni) + (tid4>>1);
                float ht = __uint_as_float(tf32r(hh));
                uint32_t la = hs_base + (uint32_t)(sl*HSP + jsl + ul)*4u;
                Hs[sl*HSP + jsl + ul] = ht;
                #pragma unroll
                for (int r=0;r<4;r++){
                    if (r == (int)rank) continue;
                    uint32_t da; asm("mapa.shared::cluster.u32 %0,%1,%2;":"=r"(da):"r"(la),"r"(r));
                    asm volatile("st.shared::cluster.f32 [%0],%1;"::"r"(da),"f"(ht));
                }
            }
        }
        CL_ARRIVE();
        // output stores hidden in barrier shadow
        #pragma unroll
        for (int mi=0;mi<2;mi++){
            int s = sbase + sl_t + mi*16;
            #pragma unroll
            for (int ni=0;ni<NI;ni++){
                int ul = 2*(nw*NI + ni) + (tid4>>1);
                outp[((size_t)tt*NS + s)*384 + dir*192 + jsl + ul] = hout[mi][ni];
            }
        }
        CL_WAIT();
    }
}

// ---- layer1 fwd LSTM, MW=1 (SPC=32), double-buffered Hs, single barrier/step.
__global__ __launch_bounds__(768,1) __cluster_dims__(4,1,1)
void lstm_mma1_db(const float* __restrict__ gx, const float* __restrict__ Whh,
                  float* __restrict__ outp)
{
    constexpr int SPC = 32, HSP = 196, BSP = 196;
    extern __shared__ float sm[];
    float* Bsh = sm;               // [192][BSP]
    float* Hs0 = sm + 192*BSP;     // [2][SPC][HSP]

    const int tid  = threadIdx.x;
    const int w    = tid >> 5;
    const int lane = tid & 31;
    const int gid  = lane >> 2;
    const int tid4 = lane & 3;
    const int nw   = w;            // 24 n-warps, MW=1
    const bool ev  = ((tid4 & 1) == 0);
    uint32_t rank; asm("mov.u32 %0, %%cluster_ctarank;" : "=r"(rank));
    const int cid   = blockIdx.x >> 2;
    const int sbase = cid * SPC;
    const int jsl   = (int)rank * 48;
    const uint32_t hb0 = smem_u32(Hs0);
    const uint32_t hb1 = smem_u32(Hs0 + SPC*HSP);

    for (int i = tid; i < 192*48; i += 768){
        int lr = i / 48, c4 = i % 48;
        int ul = lr >> 2, q = lr & 3;
        float4 v = *(const float4*)(Whh + (size_t)(q*192 + jsl + ul)*H + c4*4);
        float* bp = Bsh + lr*BSP + c4*4;
        bp[0]=__uint_as_float(tf32r(v.x)); bp[1]=__uint_as_float(tf32r(v.y));
        bp[2]=__uint_as_float(tf32r(v.z)); bp[3]=__uint_as_float(tf32r(v.w));
    }
    for (int i = tid; i < 2*SPC*HSP; i += 768) Hs0[i] = 0.f;
    CL_ARRIVE(); CL_WAIT();

    float cst[2];
    cst[0]=0.f; cst[1]=0.f;
    int sl_t = gid + (ev ? 0 : 8);
    const int ul = 2*nw + (tid4>>1);

    for (int step=0; step<T; ++step){
        const int tt = step;
        const float* Hr = Hs0 + (step&1)*SPC*HSP;
        float* Hw = Hs0 + ((step&1)^1)*SPC*HSP;
        const uint32_t hw_base = (step&1) ? hb0 : hb1;

        // gx prefetch (overlaps mma loop)
        float gxr[2][4];
        #pragma unroll
        for (int mi=0;mi<2;mi++){
            int s = sbase + sl_t + mi*16;
            #pragma unroll
            for (int q=0;q<4;q++)
                gxr[mi][q] = gx[((size_t)tt*G + q*192 + jsl + ul)*NS + s];
        }

        float acc[2][4];
        #pragma unroll
        for (int mi=0;mi<2;mi++)
            #pragma unroll
            for (int q=0;q<4;q++) acc[mi][q]=0.f;

        #pragma unroll 2
        for (int k8=0;k8<192;k8+=8){
            uint32_t af[2][4];
            #pragma unroll
            for (int mi=0;mi<2;mi++){
                int m = mi*16 + gid;
                af[mi][0] = __float_as_uint(Hr[(m  )*HSP + k8+tid4  ]);
                af[mi][1] = __float_as_uint(Hr[(m+8)*HSP + k8+tid4  ]);
                af[mi][2] = __float_as_uint(Hr[(m  )*HSP + k8+tid4+4]);
                af[mi][3] = __float_as_uint(Hr[(m+8)*HSP + k8+tid4+4]);
            }
            uint32_t bf[2];
            {
                int n = nw*8 + gid;
                bf[0] = __float_as_uint(Bsh[n*BSP + k8+tid4  ]);
                bf[1] = __float_as_uint(Bsh[n*BSP + k8+tid4+4]);
            }
            #pragma unroll
            for (int mi=0;mi<2;mi++)
                mma_tf32(acc[mi][0], acc[mi][1], acc[mi][2], acc[mi][3],
                         af[mi][0], af[mi][1], af[mi][2], af[mi][3],
                         bf[0], bf[1]);
        }

        float hout[2];
        #pragma unroll
        for (int mi=0;mi<2;mi++){
            float c0=acc[mi][0], c1=acc[mi][1], c2=acc[mi][2], c3=acc[mi][3];
            float s0 = ev ? c2 : c0;
            float s1 = ev ? c3 : c1;
            float r0 = __shfl_xor_sync(0xffffffffu, s0, 1);
            float r1 = __shfl_xor_sync(0xffffffffu, s1, 1);
            float pi = (ev ? c0 : r0) + gxr[mi][0];
            float pf = (ev ? c1 : r1) + gxr[mi][1];
            float pg = (ev ? r0 : c2) + gxr[mi][2];
            float po = (ev ? r1 : c3) + gxr[mi][3];
            float iv = sigm(pi), fv = sigm(pf);
            float gv = tanhf(pg), ov = sigm(po);
            float cc = fv*cst[mi] + iv*gv;
            cst[mi] = cc;
            float hh = ov*tanhf(cc);
            hout[mi] = hh;
            int sl = sl_t + mi*16;
            float ht = __uint_as_float(tf32r(hh));
            uint32_t la = hw_base + (uint32_t)(sl*HSP + jsl + ul)*4u;
            Hw[sl*HSP + jsl + ul] = ht;
            #pragma unroll
            for (int r=0;r<4;r++){
                if (r == (int)rank) continue;
                uint32_t da; asm("mapa.shared::cluster.u32 %0,%1,%2;":"=r"(da):"r"(la),"r"(r));
                asm volatile("st.shared::cluster.f32 [%0],%1;"::"r"(da),"f"(ht));
            }
        }
        CL_ARRIVE();
        if (step==T-1){
            #pragma unroll
            for (int mi=0;mi<2;mi++){
                int s = sbase + sl_t + mi*16;
                outp[(size_t)s*384 + jsl + ul] = hout[mi];
            }
        }
        CL_WAIT();
    }
}

// ---- plain NT gemm (gx1b), C[m][n] layout ----
__global__ __launch_bounds__(256,2)
void gemm_nt128(const float* __restrict__ A, int lda,
                const float* __restrict__ B, int ldb,
                float* __restrict__ C, int ldc, int K,
                const float* __restrict__ bias0, const float* __restrict__ bias1)
{
    __shared__ __align__(16) float As[16][136];
    __shared__ __align__(16) float Bs[16][136];
    const int m0 = blockIdx.x*128, n0 = blockIdx.y*128;
    const int tid = threadIdx.x;
    const int ty = tid>>4, tx = tid&15;
    const int row = tid>>1, kq = (tid&1)*8;
    u64 acc[4][8];
    #pragma unroll
    for (int i=0;i<4;i++)
        #pragma unroll
        for (int j=0;j<8;j++) acc[i][j]=0ull;

    for (int k0=0;k0<K;k0+=16){
        float4 a0 = *(const float4*)(A + (size_t)(m0+row)*lda + k0 + kq);
        float4 a1 = *(const float4*)(A + (size_t)(m0+row)*lda + k0 + kq + 4);
        float4 b0 = *(const float4*)(B + (size_t)(n0+row)*ldb + k0 + kq);
        float4 b1 = *(const float4*)(B + (size_t)(n0+row)*ldb + k0 + kq + 4);
        __syncthreads();
        As[kq+0][row]=a0.x; As[kq+1][row]=a0.y; As[kq+2][row]=a0.z; As[kq+3][row]=a0.w;
        As[kq+4][row]=a1.x; As[kq+5][row]=a1.y; As[kq+6][row]=a1.z; As[kq+7][row]=a1.w;
        Bs[kq+0][row]=b0.x; Bs[kq+1][row]=b0.y; Bs[kq+2][row]=b0.z; Bs[kq+3][row]=b0.w;
        Bs[kq+4][row]=b1.x; Bs[kq+5][row]=b1.y; Bs[kq+6][row]=b1.z; Bs[kq+7][row]=b1.w;
        __syncthreads();
        #pragma unroll
        for (int k=0;k<16;k++){
            ulonglong2 av0 = *(const ulonglong2*)&As[k][ty*8];
            ulonglong2 av1 = *(const ulonglong2*)&As[k][ty*8+4];
            float4 bA = *(const float4*)&Bs[k][tx*8];
            float4 bB = *(const float4*)&Bs[k][tx*8+4];
            u64 bb[8];
            bb[0]=pk(bA.x,bA.x); bb[1]=pk(bA.y,bA.y); bb[2]=pk(bA.z,bA.z); bb[3]=pk(bA.w,bA.w);
            bb[4]=pk(bB.x,bB.x); bb[5]=pk(bB.y,bB.y); bb[6]=pk(bB.z,bB.z); bb[7]=pk(bB.w,bB.w);
            u64 aa[4] = { av0.x, av0.y, av1.x, av1.y };
            #pragma unroll
            for (int i2=0;i2<4;i2++)
                #pragma unroll
                for (int j=0;j<8;j++) fma2(acc[i2][j], aa[i2], bb[j]);
        }
    }
    float bv[8];
    #pragma unroll
    for (int j=0;j<8;j++){
        int n = n0+tx*8+j;
        float v = 0.f;
        if (bias0) v += bias0[n];
        if (bias1) v += bias1[n];
        bv[j]=v;
    }
    #pragma unroll
    for (int i2=0;i2<4;i2++){
        float r0[8], r1[8];
        #pragma unroll
        for (int j=0;j<8;j++){ unpk(acc[i2][j], r0[j], r1[j]); r0[j]+=bv[j]; r1[j]+=bv[j]; }
        float* c0 = C + (size_t)(m0+ty*8+2*i2)*ldc + n0 + tx*8;
        float* c1 = C + (size_t)(m0+ty*8+2*i2+1)*ldc + n0 + tx*8;
        *(float4*)c0     = make_float4(r0[0],r0[1],r0[2],r0[3]);
        *(float4*)(c0+4) = make_float4(r0[4],r0[5],r0[6],r0[7]);
        *(float4*)c1     = make_float4(r1[0],r1[1],r1[2],r1[3]);
        *(float4*)(c1+4) = make_float4(r1[4],r1[5],r1[6],r1[7]);
    }
}

// ---- C[m][n] = sum_k A[m][k]*B[k][n] (+addC), 64x64 tile, 4x4 micro.
__global__ __launch_bounds__(256,1)
void gemm_nn64(const float* __restrict__ A, int lda,
               const float* __restrict__ B, int ldb,
               float* __restrict__ C, int ldc, int K,
               const float* __restrict__ addC)
{
    __shared__ __align__(16) float As[16][68];
    __shared__ __align__(16) float Bs[16][68];
    const int m0 = blockIdx.x*64, n0 = blockIdx.y*64;
    const int tid = threadIdx.x;
    const int ty = tid>>4, tx = tid&15;
    const int arow = tid>>2, akq = (tid&3)*4;
    const int bk = tid>>4, bnq = (tid&15)*4;
    float acc[4][4];
    #pragma unroll
    for (int i=0;i<4;i++)
        #pragma unroll
        for (int j=0;j<4;j++) acc[i][j]=0.f;

    for (int k0=0;k0<K;k0+=16){
        float4 av = *(const float4*)(A + (size_t)(m0+arow)*lda + k0 + akq);
        float4 bv = *(const float4*)(B + (size_t)(k0+bk)*ldb + n0 + bnq);
        __syncthreads();
        As[akq+0][arow]=av.x; As[akq+1][arow]=av.y; As[akq+2][arow]=av.z; As[akq+3][arow]=av.w;
        *(float4*)&Bs[bk][bnq] = bv;
        __syncthreads();
        #pragma unroll
        for (int k=0;k<16;k++){
            float a[4],b[4];
            #pragma unroll
            for (int i=0;i<4;i++){ a[i]=As[k][ty*4+i]; b[i]=Bs[k][tx*4+i]; }
            #pragma unroll
            for (int i=0;i<4;i++)
                #pragma unroll
                for (int j=0;j<4;j++) acc[i][j]+=a[i]*b[j];
        }
    }
    #pragma unroll
    for (int i=0;i<4;i++){
        int m = m0+ty*4+i;
        float* cp = C + (size_t)m*ldc + n0 + tx*4;
        const float* ap = addC ? addC + (size_t)m*ldc + n0 + tx*4 : (const float*)0;
        #pragma unroll
        for (int j=0;j<4;j++){
            float v = acc[i][j];
            if (ap) v += ap[j];
            cp[j] = v;
        }
    }
}

// ---- layer1 bwd @ t=31 only (h0=c0=0) ----
__global__ void bwd1_last(const float* __restrict__ gxb, float* __restrict__ h2)
{
    int n = blockIdx.x, j = threadIdx.x;
    const float* g = gxb + (size_t)n*G;
    float iv = sigm(g[j]);
    float gv = tanhf(g[2*H+j]);
    float ov = sigm(g[3*H+j]);
    float cc = iv*gv;
    h2[(size_t)n*384 + 192 + j] = ov*tanhf(cc);
}

// ---- dynamic network ----
__global__ void dyn_scalars(const float* __restrict__ x, const float* __restrict__ theta,
                            int* __restrict__ pid, int* __restrict__ off)
{
    int n = blockIdx.x*blockDim.x + threadIdx.x;
    if (n >= NS) return;
    float th  = theta[n];
    float x30 = x[((size_t)n*T + 30)*NF];
    float x31 = x[((size_t)n*T + 31)*NF];
    int p0 = (x30 > th) ? 1 : ((x30 < -th) ? -1 : 0);
    int p1 = (x31 > th) ? 1 : ((x31 < -th) ? -1 : 0);
    pid[n] = (p0+1)*3 + (p1+1);
    off[n] = (p1+1)*3;
}

__global__ __launch_bounds__(256,1)
void dyn_beta(const float* __restrict__ PP, const int* __restrict__ pid,
              const int* __restrict__ off, float* __restrict__ BetaT,
              float* __restrict__ t3)
{
    __shared__ float s_raw[1024];
    __shared__ float s_adj[1024*3];
    __shared__ float s_red[256];
    const int y = blockIdx.x, tid = threadIdx.x;
    const int offy = off[y];
    for (int x=tid; x<NS; x+=256){
        size_t base = ((size_t)x*NS + y)*81 + (size_t)pid[x]*9 + offy;
        float a0=PP[base], a1=PP[base+1], a2=PP[base+2];
        s_adj[x*3+0]=a0; s_adj[x*3+1]=a1; s_adj[x*3+2]=a2;
        float nr = sqrtf(a0*a0+a1*a1+a2*a2);
        s_raw[x] = (nr > 0.38f) ? nr : 0.f;
    }
    __syncthreads();
    float lm = -1e30f;
    for (int x=tid; x<NS; x+=256) lm = fmaxf(lm, s_raw[x]);
    s_red[tid]=lm; __syncthreads();
    for (int o=128;o>0;o>>=1){ if(tid<o) s_red[tid]=fmaxf(s_red[tid],s_red[tid+o]); __syncthreads(); }
    const float mx = s_red[0];
    __syncthreads();
    float ls = 0.f;
    for (int x=tid; x<NS; x+=256){ float e=expf(s_raw[x]-mx); s_raw[x]=e; ls+=e; }
    s_red[tid]=ls; __syncthreads();
    for (int o=128;o>0;o>>=1){ if(tid<o) s_red[tid]+=s_red[tid+o]; __syncthreads(); }
    const float inv = 1.f/s_red[0];
    __syncthreads();
    float t0=0.f,t1=0.f,t2=0.f;
    for (int x=tid; x<NS; x+=256){
        float b = s_raw[x]*inv;
        BetaT[(size_t)y*NS + x] = b;
        t0 += b*s_adj[x*3+0]; t1 += b*s_adj[x*3+1]; t2 += b*s_adj[x*3+2];
    }
    s_red[tid]=t0; __syncthreads();
    for (int o=128;o>0;o>>=1){ if(tid<o) s_red[tid]+=s_red[tid+o]; __syncthreads(); }
    if(tid==0) t3[y*3+0]=s_red[0];
    __syncthreads();
    s_red[tid]=t1; __syncthreads();
    for (int o=128;o>0;o>>=1){ if(tid<o) s_red[tid]+=s_red[tid+o]; __syncthreads(); }
    if(tid==0) t3[y*3+1]=s_red[0];
    __syncthreads();
    s_red[tid]=t2; __syncthreads();
    for (int o=128;o>0;o>>=1){ if(tid<o) s_red[tid]+=s_red[tid+o]; __syncthreads(); }
    if(tid==0) t3[y*3+2]=s_red[0];
}

__global__ void agg_extra(const float* __restrict__ t3, const float* __restrict__ Wa,
                          const float* __restrict__ b, float* __restrict__ E)
{
    int y = blockIdx.x, u = threadIdx.x;
    float v = b[u] + t3[y*3+0]*Wa[u] + t3[y*3+1]*Wa[128+u] + t3[y*3+2]*Wa[256+u];
    E[(size_t)y*128 + u] = v;
}

__global__ void out_kernel(const float* __restrict__ nfeat, const float* __restrict__ n1,
                           const float* __restrict__ n2, const float* __restrict__ W,
                           const float* __restrict__ b, float* __restrict__ out)
{
    int warp = (blockIdx.x*blockDim.x + threadIdx.x)>>5;
    int lane = threadIdx.x & 31;
    if (warp >= NS*2) return;
    int n = warp>>1, o = warp&1;
    float s = 0.f;
    for (int k=lane;k<384;k+=32) s += nfeat[(size_t)n*384+k]*W[k*2+o];
    for (int k=lane;k<128;k+=32) s += n1[(size_t)n*128+k]*W[(384+k)*2+o];
    for (int k=lane;k<128;k+=32) s += n2[(size_t)n*128+k]*W[(512+k)*2+o];
    #pragma unroll
    for (int m=16;m>0;m>>=1) s += __shfl_xor_sync(0xffffffffu, s, m);
    if (lane==0) out[warp] = tanhf(s + b[o]);
}

extern "C" void kernel_launch(void* const* d_in, const int* in_sizes, int n_in,
                              void* d_out, int out_size)
{
    const float* x     = (const float*)d_in[0];
    const float* theta = (const float*)d_in[1];
    const float* PP    = (const float*)d_in[2];
    const float* Wih0  = (const float*)d_in[3];
    const float* Whh0  = (const float*)d_in[4];
    const float* bih0  = (const float*)d_in[5];
    const float* bhh0  = (const float*)d_in[6];
    const float* Wih1  = (const float*)d_in[7];
    const float* Whh1  = (const float*)d_in[8];
    const float* bih1  = (const float*)d_in[9];
    const float* bhh1  = (const float*)d_in[10];
    const float* Wagg1 = (const float*)d_in[11];
    const float* bagg1 = (const float*)d_in[12];
    const float* Wagg2 = (const float*)d_in[13];
    const float* bagg2 = (const float*)d_in[14];
    const float* Wout  = (const float*)d_in[15];
    const float* bout  = (const float*)d_in[16];
    float* out = (float*)d_out;

    float *p_gx0, *p_gx1, *p_gx1b, *p_h1, *p_h2, *p_BetaT, *p_t3, *p_M, *p_E, *p_n1, *p_n2;
    int *p_pid, *p_off;
    cudaGetSymbolAddress((void**)&p_gx0,  g_gx0);
    cudaGetSymbolAddress((void**)&p_gx1,  g_gx1);
    cudaGetSymbolAddress((void**)&p_gx1b, g_gx1b);
    cudaGetSymbolAddress((void**)&p_h1,   g_h1);
    cudaGetSymbolAddress((void**)&p_h2,   g_h2);
    cudaGetSymbolAddress((void**)&p_BetaT,g_BetaT);
    cudaGetSymbolAddress((void**)&p_t3,   g_t3);
    cudaGetSymbolAddress((void**)&p_pid,  g_pid);
    cudaGetSymbolAddress((void**)&p_off,  g_off);
    cudaGetSymbolAddress((void**)&p_M,    g_M);
    cudaGetSymbolAddress((void**)&p_E,    g_E);
    cudaGetSymbolAddress((void**)&p_n1,   g_n1);
    cudaGetSymbolAddress((void**)&p_n2,   g_n2);

    const int SM64 = (192*196 + 64*196)*4;      // lstm_mma2
    const int SMDB = (192*196 + 2*32*196)*4;    // lstm_mma1_db
    const int GSH  = 128*132*4;                 // gx_hmma (union: 4 tiles 34816 < 67584)
    cudaFuncSetAttribute(lstm_mma2,    cudaFuncAttributeMaxDynamicSharedMemorySize, SM64);
    cudaFuncSetAttribute(lstm_mma1_db, cudaFuncAttributeMaxDynamicSharedMemorySize, SMDB);
    cudaFuncSetAttribute(gx_hmma,      cudaFuncAttributeMaxDynamicSharedMemorySize, GSH);

    // #1-2: layer0 gx via hmma, time-major, both dirs (K=16)
    for (int d=0; d<2; d++){
        gx_hmma<<<dim3(256,6), 256, GSH>>>(x, T*NF, (size_t)NF,
                                           Wih0 + (size_t)d*G*NF,
                                           p_gx0 + (size_t)d*NS*T*G, NF,
                                           bih0 + d*G, bhh0 + d*G);
    }
    // #3: tiny kernel to align profile slot
    dyn_scalars<<<4, 256>>>(x, theta, p_pid, p_off);

    // #4: layer0 recurrence (fwd+bwd), tensor-core — PROFILED SLOT
    lstm_mma2<<<dim3(64,2), 768, SM64>>>(p_gx0, Whh0, p_h1);

    // #5: layer1 fwd gx via hmma (K=384)
    gx_hmma<<<dim3(256,6), 256, GSH>>>(p_h1, 384, (size_t)NS*384,
                                       Wih1, p_gx1, 384, bih1, bhh1);

    // #6: dynamic network main
    dyn_beta<<<NS, 256>>>(PP, p_pid, p_off, p_BetaT, p_t3);

    // #7: layer1 bwd gx at t=31 (rows = s contiguous in time-major h1)
    gemm_nt128<<<dim3(8,6), 256>>>(p_h1 + (size_t)31*NS*384, 384,
                                   Wih1 + (size_t)G*384, 384,
                                   p_gx1b, G, 384, bih1 + G, bhh1 + G);

    // #8-9: layer1 recurrence fwd (single-barrier db); bwd single step
    lstm_mma1_db<<<dim3(128,1), 768, SMDB>>>(p_gx1, Whh1, p_h2);
    bwd1_last<<<NS, H>>>(p_gx1b, p_h2);

    // #10-12: agg layer 1
    agg_extra<<<NS, 128>>>(p_t3, Wagg1 + (size_t)384*128, bagg1, p_E);
    gemm_nn64<<<dim3(16,2), 256>>>(p_h2, 384, Wagg1, 128, p_M, 128, 384, (const float*)0);
    gemm_nn64<<<dim3(16,2), 256>>>(p_BetaT, NS, p_M, 128, p_n1, 128, NS, p_E);

    // #13-15: agg layer 2
    gemm_nn64<<<dim3(16,2), 256>>>(p_n1, 128, Wagg2, 128, p_M, 128, 128, (const float*)0);
    agg_extra<<<NS, 128>>>(p_t3, Wagg2 + (size_t)128*128, bagg2, p_E);
    gemm_nn64<<<dim3(16,2), 256>>>(p_BetaT, NS, p_M, 128, p_n2, 128, NS, p_E);

    // #16: output
    out_kernel<<<256, 256>>>(p_h2, p_n1, p_n2, Wout, bout, out);
}

// round 15
// speedup vs baseline: 2.2361x; 1.0812x over previous
#include <cuda_runtime.h>
#include <math.h>
#include <stdint.h>

#define NS 1024
#define T  32
#define NF 16
#define H  192
#define G  768

typedef unsigned long long u64;

static __device__ float g_gx1[(size_t)NS*T*G];     // time-major: [tt][G][NS]
static __device__ float g_gx1b[(size_t)NS*G];      // [s][G]
static __device__ float g_h1[(size_t)NS*T*384];    // TIME-MAJOR: [tt][s][384]
static __device__ float g_h2[(size_t)NS*384];
static __device__ float g_BetaT[(size_t)NS*NS];
static __device__ float g_t3[NS*3];
static __device__ int   g_pid[NS];
static __device__ int   g_off[NS];
static __device__ float g_M[NS*128];
static __device__ float g_E[NS*128];
static __device__ float g_n1[NS*128];
static __device__ float g_n2[NS*128];

__device__ __forceinline__ float sigm(float x){ return 1.f/(1.f+expf(-x)); }
__device__ __forceinline__ u64 pk(float x, float y){ u64 r; asm("mov.b64 %0,{%1,%2};":"=l"(r):"f"(x),"f"(y)); return r; }
__device__ __forceinline__ void fma2(u64& d, u64 a, u64 b){ asm("fma.rn.f32x2 %0,%1,%2,%0;":"+l"(d):"l"(a),"l"(b)); }
__device__ __forceinline__ void unpk(u64 v, float& x, float& y){ asm("mov.b64 {%0,%1},%2;":"=f"(x),"=f"(y):"l"(v)); }
__device__ __forceinline__ float lohi(u64 v){ float x,y; unpk(v,x,y); return x+y; }
__device__ __forceinline__ uint32_t smem_u32(const void* p){
    uint32_t a; asm("{ .reg .u64 t; cvta.to.shared.u64 t, %1; cvt.u32.u64 %0, t; }":"=r"(a):"l"(p)); return a;
}
__device__ __forceinline__ uint32_t tf32r(float x){
    uint32_t r; asm("cvt.rna.tf32.f32 %0,%1;":"=r"(r):"f"(x)); return r;
}
#define CL_ARRIVE() asm volatile("barrier.cluster.arrive.aligned;" ::: "memory")
#define CL_WAIT()   asm volatile("barrier.cluster.wait.aligned;"   ::: "memory")

__device__ __forceinline__ void mma_tf32(float& c0, float& c1, float& c2, float& c3,
                                         uint32_t a0, uint32_t a1, uint32_t a2, uint32_t a3,
                                         uint32_t b0, uint32_t b1){
    asm volatile(
        "mma.sync.aligned.m16n8k8.row.col.f32.tf32.tf32.f32 "
        "{%0,%1,%2,%3}, {%4,%5,%6,%7}, {%8,%9}, {%0,%1,%2,%3};"
        : "+f"(c0), "+f"(c1), "+f"(c2), "+f"(c3)
        : "r"(a0), "r"(a1), "r"(a2), "r"(a3), "r"(b0), "r"(b1));
}

// ---- generic gx GEMM via mma.sync tf32, double-buffered (R14-proven).
__global__ __launch_bounds__(256,2)
void gx_hmma(const float* __restrict__ A, int rstride, size_t tmul,
             const float* __restrict__ Bw, float* __restrict__ Ct, int K,
             const float* __restrict__ bias0, const float* __restrict__ bias1)
{
    extern __shared__ __align__(16) float dyn[];
    float* csh = dyn;                 // [128][132] reused for epilogue
    __shared__ float bsh[128];
    const int tt = blockIdx.x >> 3;
    const int s0 = (blockIdx.x & 7) * 128;
    const int n0 = blockIdx.y * 128;
    const int tid = threadIdx.x;
    const int w    = tid >> 5;
    const int lane = tid & 31;
    const int gid  = lane >> 2;
    const int tid4 = lane & 3;
    const int m0w  = (w & 1) * 64;
    const int n0w  = (w >> 1) * 32;
    const int row = tid>>1, kq = (tid&1)*8;
    const float* aBase = A + (size_t)(s0+row)*rstride + (size_t)tt*tmul + kq;
    const float* bBase = Bw + (size_t)(n0+row)*K + kq;

    if (tid < 128) bsh[tid] = bias0[n0+tid] + bias1[n0+tid];

    float acc[4][4][4];
    #pragma unroll
    for (int mi=0;mi<4;mi++)
        #pragma unroll
        for (int ni=0;ni<4;ni++)
            #pragma unroll
            for (int q=0;q<4;q++) acc[mi][ni][q]=0.f;

    float4 a0 = *(const float4*)(aBase);
    float4 a1 = *(const float4*)(aBase + 4);
    float4 b0 = *(const float4*)(bBase);
    float4 b1 = *(const float4*)(bBase + 4);
    {
        float* As = dyn; float* Bs = dyn + 2176;
        As[(kq+0)*136+row]=__uint_as_float(tf32r(a0.x)); As[(kq+1)*136+row]=__uint_as_float(tf32r(a0.y));
        As[(kq+2)*136+row]=__uint_as_float(tf32r(a0.z)); As[(kq+3)*136+row]=__uint_as_float(tf32r(a0.w));
        As[(kq+4)*136+row]=__uint_as_float(tf32r(a1.x)); As[(kq+5)*136+row]=__uint_as_float(tf32r(a1.y));
        As[(kq+6)*136+row]=__uint_as_float(tf32r(a1.z)); As[(kq+7)*136+row]=__uint_as_float(tf32r(a1.w));
        Bs[(kq+0)*136+row]=__uint_as_float(tf32r(b0.x)); Bs[(kq+1)*136+row]=__uint_as_float(tf32r(b0.y));
        Bs[(kq+2)*136+row]=__uint_as_float(tf32r(b0.z)); Bs[(kq+3)*136+row]=__uint_as_float(tf32r(b0.w));
        Bs[(kq+4)*136+row]=__uint_as_float(tf32r(b1.x)); Bs[(kq+5)*136+row]=__uint_as_float(tf32r(b1.y));
        Bs[(kq+6)*136+row]=__uint_as_float(tf32r(b1.z)); Bs[(kq+7)*136+row]=__uint_as_float(tf32r(b1.w));
    }
    __syncthreads();

    int buf = 0;
    for (int k0=0;k0<K;k0+=16){
        const bool nxt = (k0+16)<K;
        if (nxt){
            a0 = *(const float4*)(aBase + k0+16);
            a1 = *(const float4*)(aBase + k0+20);
            b0 = *(const float4*)(bBase + k0+16);
            b1 = *(const float4*)(bBase + k0+20);
        }
        const float* As = dyn + buf*4352;
        const float* Bs = As + 2176;
        #pragma unroll
        for (int k8=0;k8<16;k8+=8){
            uint32_t af[4][4];
            #pragma unroll
            for (int mi=0;mi<4;mi++){
                int m = m0w + mi*16 + gid;
                af[mi][0] = __float_as_uint(As[(k8+tid4  )*136 + m  ]);
                af[mi][1] = __float_as_uint(As[(k8+tid4  )*136 + m+8]);
                af[mi][2] = __float_as_uint(As[(k8+tid4+4)*136 + m  ]);
                af[mi][3] = __float_as_uint(As[(k8+tid4+4)*136 + m+8]);
            }
            uint32_t bf[4][2];
            #pragma unroll
            for (int ni=0;ni<4;ni++){
                int n = n0w + ni*8 + gid;
                bf[ni][0] = __float_as_uint(Bs[(k8+tid4  )*136 + n]);
                bf[ni][1] = __float_as_uint(Bs[(k8+tid4+4)*136 + n]);
            }
            #pragma unroll
            for (int mi=0;mi<4;mi++)
                #pragma unroll
                for (int ni=0;ni<4;ni++)
                    mma_tf32(acc[mi][ni][0], acc[mi][ni][1], acc[mi][ni][2], acc[mi][ni][3],
                             af[mi][0], af[mi][1], af[mi][2], af[mi][3],
                             bf[ni][0], bf[ni][1]);
        }
        if (nxt){
            float* An = dyn + (buf^1)*4352;
            float* Bn = An + 2176;
            An[(kq+0)*136+row]=__uint_as_float(tf32r(a0.x)); An[(kq+1)*136+row]=__uint_as_float(tf32r(a0.y));
            An[(kq+2)*136+row]=__uint_as_float(tf32r(a0.z)); An[(kq+3)*136+row]=__uint_as_float(tf32r(a0.w));
            An[(kq+4)*136+row]=__uint_as_float(tf32r(a1.x)); An[(kq+5)*136+row]=__uint_as_float(tf32r(a1.y));
            An[(kq+6)*136+row]=__uint_as_float(tf32r(a1.z)); An[(kq+7)*136+row]=__uint_as_float(tf32r(a1.w));
            Bn[(kq+0)*136+row]=__uint_as_float(tf32r(b0.x)); Bn[(kq+1)*136+row]=__uint_as_float(tf32r(b0.y));
            Bn[(kq+2)*136+row]=__uint_as_float(tf32r(b0.z)); Bn[(kq+3)*136+row]=__uint_as_float(tf32r(b0.w));
            Bn[(kq+4)*136+row]=__uint_as_float(tf32r(b1.x)); Bn[(kq+5)*136+row]=__uint_as_float(tf32r(b1.y));
            Bn[(kq+6)*136+row]=__uint_as_float(tf32r(b1.z)); Bn[(kq+7)*136+row]=__uint_as_float(tf32r(b1.w));
            __syncthreads();
            buf ^= 1;
        }
    }
    __syncthreads();
    #pragma unroll
    for (int mi=0;mi<4;mi++){
        #pragma unroll
        for (int ni=0;ni<4;ni++){
            int nl = n0w + ni*8 + tid4*2;
            int ml = m0w + mi*16 + gid;
            csh[(size_t)(nl  )*132 + ml  ] = acc[mi][ni][0] + bsh[nl];
            csh[(size_t)(nl+1)*132 + ml  ] = acc[mi][ni][1] + bsh[nl+1];
            csh[(size_t)(nl  )*132 + ml+8] = acc[mi][ni][2] + bsh[nl];
            csh[(size_t)(nl+1)*132 + ml+8] = acc[mi][ni][3] + bsh[nl+1];
        }
    }
    __syncthreads();
    {
        int jl = tid>>1, half = (tid&1)*64;
        const float* src = csh + (size_t)jl*132 + half;
        float* dst = Ct + ((size_t)tt*G + n0 + jl)*NS + s0 + half;
        #pragma unroll
        for (int v=0;v<16;v++)
            *(float4*)(dst + v*4) = *(const float4*)(src + v*4);
    }
}

// ---- FUSED layer-0 LSTM: input GEMM (x @ Wih^T, K=16) fused as an extra
// accumulating mma into the recurrence. MW=2, SPC=64, 2-barrier cluster.
__global__ __launch_bounds__(768,1) __cluster_dims__(4,1,1)
void lstm_mma2f(const float* __restrict__ x,
                const float* __restrict__ Wih_all, const float* __restrict__ bih_all,
                const float* __restrict__ bhh_all, const float* __restrict__ Whh_all,
                float* __restrict__ outp)
{
    constexpr int MW = 2, SPC = 64, NI = 2, HSP = 196, BSP = 196;
    constexpr int WSP = 20, XSP = 20;
    extern __shared__ float sm[];
    float* Bsh = sm;                       // [192][BSP] Whh tf32, row = ul*4+q
    float* Hs  = Bsh + 192*BSP;            // [SPC][HSP] h tf32
    float* ws  = Hs + SPC*HSP;             // [192][WSP] Wih tf32, row = ul*4+q
    float* xs  = ws + 192*WSP;             // [SPC][XSP] x step-slice tf32

    const int dir  = blockIdx.y;           // 0 = fwd, 1 = bwd
    const float* Whh = Whh_all + (size_t)dir*G*H;
    const float* Wih = Wih_all + (size_t)dir*G*NF;

    const int tid  = threadIdx.x;
    const int w    = tid >> 5;
    const int lane = tid & 31;
    const int gid  = lane >> 2;
    const int tid4 = lane & 3;
    const int mw   = w % MW;
    const int nw   = w / MW;
    const bool ev  = ((tid4 & 1) == 0);
    uint32_t rank; asm("mov.u32 %0, %%cluster_ctarank;" : "=r"(rank));
    const int cid   = blockIdx.x >> 2;
    const int sbase = cid * SPC;
    const int jsl   = (int)rank * 48;
    const uint32_t hs_base = smem_u32(Hs);

    for (int i = tid; i < 192*48; i += 768){
        int lr = i / 48, c4 = i % 48;
        int ul = lr >> 2, q = lr & 3;
        float4 v = *(const float4*)(Whh + (size_t)(q*192 + jsl + ul)*H + c4*4);
        float* bp = Bsh + lr*BSP + c4*4;
        bp[0]=__uint_as_float(tf32r(v.x)); bp[1]=__uint_as_float(tf32r(v.y));
        bp[2]=__uint_as_float(tf32r(v.z)); bp[3]=__uint_as_float(tf32r(v.w));
    }
    for (int i = tid; i < 192*16; i += 768){
        int lr = i >> 4, k = i & 15;
        int ul = lr >> 2, q = lr & 3;
        ws[lr*WSP + k] = __uint_as_float(tf32r(Wih[(size_t)(q*192 + jsl + ul)*NF + k]));
    }
    for (int i = tid; i < SPC*HSP; i += 768) Hs[i] = 0.f;

    // per-thread gate biases for units ul(ni)
    float bq[NI][4];
    #pragma unroll
    for (int ni=0;ni<NI;ni++){
        int ul = 2*(nw*NI + ni) + (tid4>>1);
        #pragma unroll
        for (int q=0;q<4;q++){
            size_t idx = (size_t)dir*G + q*192 + jsl + ul;
            bq[ni][q] = bih_all[idx] + bhh_all[idx];
        }
    }
    CL_ARRIVE(); CL_WAIT();

    float cst[2][NI];
    #pragma unroll
    for (int a=0;a<2;a++)
        #pragma unroll
        for (int b=0;b<NI;b++) cst[a][b]=0.f;

    int sl_t = mw*32 + gid + (ev ? 0 : 8);

    for (int step=0; step<T; ++step){
        const int tt = (dir==1) ? (T-1-step) : step;

        // stage x step slice: xs[sl][f] = tf32(x[sbase+sl][tt][f])
        for (int i = tid; i < SPC*NF; i += 768){
            int sl = i >> 4, f = i & 15;
            xs[sl*XSP + f] = __uint_as_float(tf32r(
                x[((size_t)(sbase+sl)*T + tt)*NF + f]));
        }
        __syncthreads();

        float acc[2][NI][4];
        #pragma unroll
        for (int mi=0;mi<2;mi++)
            #pragma unroll
            for (int ni=0;ni<NI;ni++)
                #pragma unroll
                for (int q=0;q<4;q++) acc[mi][ni][q]=0.f;

        // input GEMM: 2 k8 iterations over K=16
        #pragma unroll
        for (int k8=0;k8<16;k8+=8){
            uint32_t af[2][4];
            #pragma unroll
            for (int mi=0;mi<2;mi++){
                int m = mw*32 + mi*16 + gid;
                af[mi][0] = __float_as_uint(xs[(m  )*XSP + k8+tid4  ]);
                af[mi][1] = __float_as_uint(xs[(m+8)*XSP + k8+tid4  ]);
                af[mi][2] = __float_as_uint(xs[(m  )*XSP + k8+tid4+4]);
                af[mi][3] = __float_as_uint(xs[(m+8)*XSP + k8+tid4+4]);
            }
            uint32_t bf[NI][2];
            #pragma unroll
            for (int ni=0;ni<NI;ni++){
                int n = (nw*NI + ni)*8 + gid;
                bf[ni][0] = __float_as_uint(ws[n*WSP + k8+tid4  ]);
                bf[ni][1] = __float_as_uint(ws[n*WSP + k8+tid4+4]);
            }
            #pragma unroll
            for (int mi=0;mi<2;mi++)
                #pragma unroll
                for (int ni=0;ni<NI;ni++)
                    mma_tf32(acc[mi][ni][0], acc[mi][ni][1], acc[mi][ni][2], acc[mi][ni][3],
                             af[mi][0], af[mi][1], af[mi][2], af[mi][3],
                             bf[ni][0], bf[ni][1]);
        }

        // recurrence matvec: K=192 over Hs
        #pragma unroll 2
        for (int k8=0;k8<192;k8+=8){
            uint32_t af[2][4];
            #pragma unroll
            for (int mi=0;mi<2;mi++){
                int m = mw*32 + mi*16 + gid;
                af[mi][0] = __float_as_uint(Hs[(m  )*HSP + k8+tid4  ]);
                af[mi][1] = __float_as_uint(Hs[(m+8)*HSP + k8+tid4  ]);
                af[mi][2] = __float_as_uint(Hs[(m  )*HSP + k8+tid4+4]);
                af[mi][3] = __float_as_uint(Hs[(m+8)*HSP + k8+tid4+4]);
            }
            uint32_t bf[NI][2];
            #pragma unroll
            for (int ni=0;ni<NI;ni++){
                int n = (nw*NI + ni)*8 + gid;
                bf[ni][0] = __float_as_uint(Bsh[n*BSP + k8+tid4  ]);
                bf[ni][1] = __float_as_uint(Bsh[n*BSP + k8+tid4+4]);
            }
            #pragma unroll
            for (int mi=0;mi<2;mi++)
                #pragma unroll
                for (int ni=0;ni<NI;ni++)
                    mma_tf32(acc[mi][ni][0], acc[mi][ni][1], acc[mi][ni][2], acc[mi][ni][3],
                             af[mi][0], af[mi][1], af[mi][2], af[mi][3],
                             bf[ni][0], bf[ni][1]);
        }

        CL_ARRIVE();                  // my reads of Hs(t-1) (and xs) done
        CL_WAIT();                    // all CTAs' reads done -> safe to write Hs

        float hout[2][NI];
        #pragma unroll
        for (int mi=0;mi<2;mi++){
            #pragma unroll
            for (int ni=0;ni<NI;ni++){
                float c0=acc[mi][ni][0], c1=acc[mi][ni][1];
                float c2=acc[mi][ni][2], c3=acc[mi][ni][3];
                float s0 = ev ? c2 : c0;
                float s1 = ev ? c3 : c1;
                float r0 = __shfl_xor_sync(0xffffffffu, s0, 1);
                float r1 = __shfl_xor_sync(0xffffffffu, s1, 1);
                float pi = (ev ? c0 : r0) + bq[ni][0];
                float pf = (ev ? c1 : r1) + bq[ni][1];
                float pg = (ev ? r0 : c2) + bq[ni][2];
                float po = (ev ? r1 : c3) + bq[ni][3];
                float iv = sigm(pi), fv = sigm(pf);
                float gv = tanhf(pg), ov = sigm(po);
                float cc = fv*cst[mi][ni] + iv*gv;
                cst[mi][ni] = cc;
                float hh = ov*tanhf(cc);
                hout[mi][ni] = hh;
                int sl = sl_t + mi*16;
                int ul = 2*(nw*NI + ni) + (tid4>>1);
                float ht = __uint_as_float(tf32r(hh));
                uint32_t la = hs_base + (uint32_t)(sl*HSP + jsl + ul)*4u;
                Hs[sl*HSP + jsl + ul] = ht;
                #pragma unroll
                for (int r=0;r<4;r++){
                    if (r == (int)rank) continue;
                    uint32_t da; asm("mapa.shared::cluster.u32 %0,%1,%2;":"=r"(da):"r"(la),"r"(r));
                    asm volatile("st.shared::cluster.f32 [%0],%1;"::"r"(da),"f"(ht));
                }
            }
        }
        CL_ARRIVE();                  // release h(t)
        #pragma unroll
        for (int mi=0;mi<2;mi++){
            int s = sbase + sl_t + mi*16;
            #pragma unroll
            for (int ni=0;ni<NI;ni++){
                int ul = 2*(nw*NI + ni) + (tid4>>1);
                outp[((size_t)tt*NS + s)*384 + dir*192 + jsl + ul] = hout[mi][ni];
            }
        }
        CL_WAIT();                    // acquire peers' h(t)
    }
}

// ---- layer1 fwd LSTM, MW=1 (SPC=32), double-buffered Hs, 1 barrier/step.
__global__ __launch_bounds__(768,1) __cluster_dims__(4,1,1)
void lstm_mma1_db(const float* __restrict__ gx, const float* __restrict__ Whh,
                  float* __restrict__ outp)
{
    constexpr int SPC = 32, HSP = 196, BSP = 196;
    extern __shared__ float sm[];
    float* Bsh = sm;               // [192][BSP]
    float* Hs0 = sm + 192*BSP;     // [2][SPC][HSP]

    const int tid  = threadIdx.x;
    const int w    = tid >> 5;
    const int lane = tid & 31;
    const int gid  = lane >> 2;
    const int tid4 = lane & 3;
    const int nw   = w;
    const bool ev  = ((tid4 & 1) == 0);
    uint32_t rank; asm("mov.u32 %0, %%cluster_ctarank;" : "=r"(rank));
    const int cid   = blockIdx.x >> 2;
    const int sbase = cid * SPC;
    const int jsl   = (int)rank * 48;
    const uint32_t hb0 = smem_u32(Hs0);
    const uint32_t hb1 = smem_u32(Hs0 + SPC*HSP);

    for (int i = tid; i < 192*48; i += 768){
        int lr = i / 48, c4 = i % 48;
        int ul = lr >> 2, q = lr & 3;
        float4 v = *(const float4*)(Whh + (size_t)(q*192 + jsl + ul)*H + c4*4);
        float* bp = Bsh + lr*BSP + c4*4;
        bp[0]=__uint_as_float(tf32r(v.x)); bp[1]=__uint_as_float(tf32r(v.y));
        bp[2]=__uint_as_float(tf32r(v.z)); bp[3]=__uint_as_float(tf32r(v.w));
    }
    for (int i = tid; i < 2*SPC*HSP; i += 768) Hs0[i] = 0.f;
    CL_ARRIVE(); CL_WAIT();

    float cst[2];
    cst[0]=0.f; cst[1]=0.f;
    int sl_t = gid + (ev ? 0 : 8);
    const int ul = 2*nw + (tid4>>1);

    for (int step=0; step<T; ++step){
        const int tt = step;
        const float* Hr = Hs0 + (step&1)*SPC*HSP;
        float* Hw = Hs0 + ((step&1)^1)*SPC*HSP;
        const uint32_t hw_base = (step&1) ? hb0 : hb1;

        float gxr[2][4];
        #pragma unroll
        for (int mi=0;mi<2;mi++){
            int s = sbase + sl_t + mi*16;
            #pragma unroll
            for (int q=0;q<4;q++)
                gxr[mi][q] = gx[((size_t)tt*G + q*192 + jsl + ul)*NS + s];
        }

        float acc[2][4];
        #pragma unroll
        for (int mi=0;mi<2;mi++)
            #pragma unroll
            for (int q=0;q<4;q++) acc[mi][q]=0.f;

        #pragma unroll 2
        for (int k8=0;k8<192;k8+=8){
            uint32_t af[2][4];
            #pragma unroll
            for (int mi=0;mi<2;mi++){
                int m = mi*16 + gid;
                af[mi][0] = __float_as_uint(Hr[(m  )*HSP + k8+tid4  ]);
                af[mi][1] = __float_as_uint(Hr[(m+8)*HSP + k8+tid4  ]);
                af[mi][2] = __float_as_uint(Hr[(m  )*HSP + k8+tid4+4]);
                af[mi][3] = __float_as_uint(Hr[(m+8)*HSP + k8+tid4+4]);
            }
            uint32_t bf[2];
            {
                int n = nw*8 + gid;
                bf[0] = __float_as_uint(Bsh[n*BSP + k8+tid4  ]);
                bf[1] = __float_as_uint(Bsh[n*BSP + k8+tid4+4]);
            }
            #pragma unroll
            for (int mi=0;mi<2;mi++)
                mma_tf32(acc[mi][0], acc[mi][1], acc[mi][2], acc[mi][3],
                         af[mi][0], af[mi][1], af[mi][2], af[mi][3],
                         bf[0], bf[1]);
        }

        float hout[2];
        #pragma unroll
        for (int mi=0;mi<2;mi++){
            float c0=acc[mi][0], c1=acc[mi][1], c2=acc[mi][2], c3=acc[mi][3];
            float s0 = ev ? c2 : c0;
            float s1 = ev ? c3 : c1;
            float r0 = __shfl_xor_sync(0xffffffffu, s0, 1);
            float r1 = __shfl_xor_sync(0xffffffffu, s1, 1);
            float pi = (ev ? c0 : r0) + gxr[mi][0];
            float pf = (ev ? c1 : r1) + gxr[mi][1];
            float pg = (ev ? r0 : c2) + gxr[mi][2];
            float po = (ev ? r1 : c3) + gxr[mi][3];
            float iv = sigm(pi), fv = sigm(pf);
            float gv = tanhf(pg), ov = sigm(po);
            float cc = fv*cst[mi] + iv*gv;
            cst[mi] = cc;
            float hh = ov*tanhf(cc);
            hout[mi] = hh;
            int sl = sl_t + mi*16;
            float ht = __uint_as_float(tf32r(hh));
            uint32_t la = hw_base + (uint32_t)(sl*HSP + jsl + ul)*4u;
            Hw[sl*HSP + jsl + ul] = ht;
            #pragma unroll
            for (int r=0;r<4;r++){
                if (r == (int)rank) continue;
                uint32_t da; asm("mapa.shared::cluster.u32 %0,%1,%2;":"=r"(da):"r"(la),"r"(r));
                asm volatile("st.shared::cluster.f32 [%0],%1;"::"r"(da),"f"(ht));
            }
        }
        CL_ARRIVE();
        if (step==T-1){
            #pragma unroll
            for (int mi=0;mi<2;mi++){
                int s = sbase + sl_t + mi*16;
                outp[(size_t)s*384 + jsl + ul] = hout[mi];
            }
        }
        CL_WAIT();
    }
}

// ---- plain NT gemm (gx1b), C[m][n] layout ----
__global__ __launch_bounds__(256,2)
void gemm_nt128(const float* __restrict__ A, int lda,
                const float* __restrict__ B, int ldb,
                float* __restrict__ C, int ldc, int K,
                const float* __restrict__ bias0, const float* __restrict__ bias1)
{
    __shared__ __align__(16) float As[16][136];
    __shared__ __align__(16) float Bs[16][136];
    const int m0 = blockIdx.x*128, n0 = blockIdx.y*128;
    const int tid = threadIdx.x;
    const int ty = tid>>4, tx = tid&15;
    const int row = tid>>1, kq = (tid&1)*8;
    u64 acc[4][8];
    #pragma unroll
    for (int i=0;i<4;i++)
        #pragma unroll
        for (int j=0;j<8;j++) acc[i][j]=0ull;

    for (int k0=0;k0<K;k0+=16){
        float4 a0 = *(const float4*)(A + (size_t)(m0+row)*lda + k0 + kq);
        float4 a1 = *(const float4*)(A + (size_t)(m0+row)*lda + k0 + kq + 4);
        float4 b0 = *(const float4*)(B + (size_t)(n0+row)*ldb + k0 + kq);
        float4 b1 = *(const float4*)(B + (size_t)(n0+row)*ldb + k0 + kq + 4);
        __syncthreads();
        As[kq+0][row]=a0.x; As[kq+1][row]=a0.y; As[kq+2][row]=a0.z; As[kq+3][row]=a0.w;
        As[kq+4][row]=a1.x; As[kq+5][row]=a1.y; As[kq+6][row]=a1.z; As[kq+7][row]=a1.w;
        Bs[kq+0][row]=b0.x; Bs[kq+1][row]=b0.y; Bs[kq+2][row]=b0.z; Bs[kq+3][row]=b0.w;
        Bs[kq+4][row]=b1.x; Bs[kq+5][row]=b1.y; Bs[kq+6][row]=b1.z; Bs[kq+7][row]=b1.w;
        __syncthreads();
        #pragma unroll
        for (int k=0;k<16;k++){
            ulonglong2 av0 = *(const ulonglong2*)&As[k][ty*8];
            ulonglong2 av1 = *(const ulonglong2*)&As[k][ty*8+4];
            float4 bA = *(const float4*)&Bs[k][tx*8];
            float4 bB = *(const float4*)&Bs[k][tx*8+4];
            u64 bb[8];
            bb[0]=pk(bA.x,bA.x); bb[1]=pk(bA.y,bA.y); bb[2]=pk(bA.z,bA.z); bb[3]=pk(bA.w,bA.w);
            bb[4]=pk(bB.x,bB.x); bb[5]=pk(bB.y,bB.y); bb[6]=pk(bB.z,bB.z); bb[7]=pk(bB.w,bB.w);
            u64 aa[4] = { av0.x, av0.y, av1.x, av1.y };
            #pragma unroll
            for (int i2=0;i2<4;i2++)
                #pragma unroll
                for (int j=0;j<8;j++) fma2(acc[i2][j], aa[i2], bb[j]);
        }
    }
    float bv[8];
    #pragma unroll
    for (int j=0;j<8;j++){
        int n = n0+tx*8+j;
        float v = 0.f;
        if (bias0) v += bias0[n];
        if (bias1) v += bias1[n];
        bv[j]=v;
    }
    #pragma unroll
    for (int i2=0;i2<4;i2++){
        float r0[8], r1[8];
        #pragma unroll
        for (int j=0;j<8;j++){ unpk(acc[i2][j], r0[j], r1[j]); r0[j]+=bv[j]; r1[j]+=bv[j]; }
        float* c0 = C + (size_t)(m0+ty*8+2*i2)*ldc + n0 + tx*8;
        float* c1 = C + (size_t)(m0+ty*8+2*i2+1)*ldc + n0 + tx*8;
        *(float4*)c0     = make_float4(r0[0],r0[1],r0[2],r0[3]);
        *(float4*)(c0+4) = make_float4(r0[4],r0[5],r0[6],r0[7]);
        *(float4*)c1     = make_float4(r1[0],r1[1],r1[2],r1[3]);
        *(float4*)(c1+4) = make_float4(r1[4],r1[5],r1[6],r1[7]);
    }
}

// ---- C[m][n] = sum_k A[m][k]*B[k][n] (+addC), 64x64 tile, 4x4 micro.
__global__ __launch_bounds__(256,1)
void gemm_nn64(const float* __restrict__ A, int lda,
               const float* __restrict__ B, int ldb,
               float* __restrict__ C, int ldc, int K,
               const float* __restrict__ addC)
{
    __shared__ __align__(16) float As[16][68];
    __shared__ __align__(16) float Bs[16][68];
    const int m0 = blockIdx.x*64, n0 = blockIdx.y*64;
    const int tid = threadIdx.x;
    const int ty = tid>>4, tx = tid&15;
    const int arow = tid>>2, akq = (tid&3)*4;
    const int bk = tid>>4, bnq = (tid&15)*4;
    float acc[4][4];
    #pragma unroll
    for (int i=0;i<4;i++)
        #pragma unroll
        for (int j=0;j<4;j++) acc[i][j]=0.f;

    for (int k0=0;k0<K;k0+=16){
        float4 av = *(const float4*)(A + (size_t)(m0+arow)*lda + k0 + akq);
        float4 bv = *(const float4*)(B + (size_t)(k0+bk)*ldb + n0 + bnq);
        __syncthreads();
        As[akq+0][arow]=av.x; As[akq+1][arow]=av.y; As[akq+2][arow]=av.z; As[akq+3][arow]=av.w;
        *(float4*)&Bs[bk][bnq] = bv;
        __syncthreads();
        #pragma unroll
        for (int k=0;k<16;k++){
            float a[4],b[4];
            #pragma unroll
            for (int i=0;i<4;i++){ a[i]=As[k][ty*4+i]; b[i]=Bs[k][tx*4+i]; }
            #pragma unroll
            for (int i=0;i<4;i++)
                #pragma unroll
                for (int j=0;j<4;j++) acc[i][j]+=a[i]*b[j];
        }
    }
    #pragma unroll
    for (int i=0;i<4;i++){
        int m = m0+ty*4+i;
        float* cp = C + (size_t)m*ldc + n0 + tx*4;
        const float* ap = addC ? addC + (size_t)m*ldc + n0 + tx*4 : (const float*)0;
        #pragma unroll
        for (int j=0;j<4;j++){
            float v = acc[i][j];
            if (ap) v += ap[j];
            cp[j] = v;
        }
    }
}

// ---- layer1 bwd @ t=31 only (h0=c0=0) ----
__global__ void bwd1_last(const float* __restrict__ gxb, float* __restrict__ h2)
{
    int n = blockIdx.x, j = threadIdx.x;
    const float* g = gxb + (size_t)n*G;
    float iv = sigm(g[j]);
    float gv = tanhf(g[2*H+j]);
    float ov = sigm(g[3*H+j]);
    float cc = iv*gv;
    h2[(size_t)n*384 + 192 + j] = ov*tanhf(cc);
}

// ---- dynamic network ----
__global__ void dyn_scalars(const float* __restrict__ x, const float* __restrict__ theta,
                            int* __restrict__ pid, int* __restrict__ off)
{
    int n = blockIdx.x*blockDim.x + threadIdx.x;
    if (n >= NS) return;
    float th  = theta[n];
    float x30 = x[((size_t)n*T + 30)*NF];
    float x31 = x[((size_t)n*T + 31)*NF];
    int p0 = (x30 > th) ? 1 : ((x30 < -th) ? -1 : 0);
    int p1 = (x31 > th) ? 1 : ((x31 < -th) ? -1 : 0);
    pid[n] = (p0+1)*3 + (p1+1);
    off[n] = (p1+1)*3;
}

__global__ __launch_bounds__(256,1)
void dyn_beta(const float* __restrict__ PP, const int* __restrict__ pid,
              const int* __restrict__ off, float* __restrict__ BetaT,
              float* __restrict__ t3)
{
    __shared__ float s_raw[1024];
    __shared__ float s_adj[1024*3];
    __shared__ float s_red[256];
    const int y = blockIdx.x, tid = threadIdx.x;
    const int offy = off[y];
    for (int x=tid; x<NS; x+=256){
        size_t base = ((size_t)x*NS + y)*81 + (size_t)pid[x]*9 + offy;
        float a0=PP[base], a1=PP[base+1], a2=PP[base+2];
        s_adj[x*3+0]=a0; s_adj[x*3+1]=a1; s_adj[x*3+2]=a2;
        float nr = sqrtf(a0*a0+a1*a1+a2*a2);
        s_raw[x] = (nr > 0.38f) ? nr : 0.f;
    }
    __syncthreads();
    float lm = -1e30f;
    for (int x=tid; x<NS; x+=256) lm = fmaxf(lm, s_raw[x]);
    s_red[tid]=lm; __syncthreads();
    for (int o=128;o>0;o>>=1){ if(tid<o) s_red[tid]=fmaxf(s_red[tid],s_red[tid+o]); __syncthreads(); }
    const float mx = s_red[0];
    __syncthreads();
    float ls = 0.f;
    for (int x=tid; x<NS; x+=256){ float e=expf(s_raw[x]-mx); s_raw[x]=e; ls+=e; }
    s_red[tid]=ls; __syncthreads();
    for (int o=128;o>0;o>>=1){ if(tid<o) s_red[tid]+=s_red[tid+o]; __syncthreads(); }
    const float inv = 1.f/s_red[0];
    __syncthreads();
    float t0=0.f,t1=0.f,t2=0.f;
    for (int x=tid; x<NS; x+=256){
        float b = s_raw[x]*inv;
        BetaT[(size_t)y*NS + x] = b;
        t0 += b*s_adj[x*3+0]; t1 += b*s_adj[x*3+1]; t2 += b*s_adj[x*3+2];
    }
    s_red[tid]=t0; __syncthreads();
    for (int o=128;o>0;o>>=1){ if(tid<o) s_red[tid]+=s_red[tid+o]; __syncthreads(); }
    if(tid==0) t3[y*3+0]=s_red[0];
    __syncthreads();
    s_red[tid]=t1; __syncthreads();
    for (int o=128;o>0;o>>=1){ if(tid<o) s_red[tid]+=s_red[tid+o]; __syncthreads(); }
    if(tid==0) t3[y*3+1]=s_red[0];
    __syncthreads();
    s_red[tid]=t2; __syncthreads();
    for (int o=128;o>0;o>>=1){ if(tid<o) s_red[tid]+=s_red[tid+o]; __syncthreads(); }
    if(tid==0) t3[y*3+2]=s_red[0];
}

__global__ void agg_extra(const float* __restrict__ t3, const float* __restrict__ Wa,
                          const float* __restrict__ b, float* __restrict__ E)
{
    int y = blockIdx.x, u = threadIdx.x;
    float v = b[u] + t3[y*3+0]*Wa[u] + t3[y*3+1]*Wa[128+u] + t3[y*3+2]*Wa[256+u];
    E[(size_t)y*128 + u] = v;
}

__global__ void out_kernel(const float* __restrict__ nfeat, const float* __restrict__ n1,
                           const float* __restrict__ n2, const float* __restrict__ W,
                           const float* __restrict__ b, float* __restrict__ out)
{
    int warp = (blockIdx.x*blockDim.x + threadIdx.x)>>5;
    int lane = threadIdx.x & 31;
    if (warp >= NS*2) return;
    int n = warp>>1, o = warp&1;
    float s = 0.f;
    for (int k=lane;k<384;k+=32) s += nfeat[(size_t)n*384+k]*W[k*2+o];
    for (int k=lane;k<128;k+=32) s += n1[(size_t)n*128+k]*W[(384+k)*2+o];
    for (int k=lane;k<128;k+=32) s += n2[(size_t)n*128+k]*W[(512+k)*2+o];
    #pragma unroll
    for (int m=16;m>0;m>>=1) s += __shfl_xor_sync(0xffffffffu, s, m);
    if (lane==0) out[warp] = tanhf(s + b[o]);
}

extern "C" void kernel_launch(void* const* d_in, const int* in_sizes, int n_in,
                              void* d_out, int out_size)
{
    const float* x     = (const float*)d_in[0];
    const float* theta = (const float*)d_in[1];
    const float* PP    = (const float*)d_in[2];
    const float* Wih0  = (const float*)d_in[3];
    const float* Whh0  = (const float*)d_in[4];
    const float* bih0  = (const float*)d_in[5];
    const float* bhh0  = (const float*)d_in[6];
    const float* Wih1  = (const float*)d_in[7];
    const float* Whh1  = (const float*)d_in[8];
    const float* bih1  = (const float*)d_in[9];
    const float* bhh1  = (const float*)d_in[10];
    const float* Wagg1 = (const float*)d_in[11];
    const float* bagg1 = (const float*)d_in[12];
    const float* Wagg2 = (const float*)d_in[13];
    const float* bagg2 = (const float*)d_in[14];
    const float* Wout  = (const float*)d_in[15];
    const float* bout  = (const float*)d_in[16];
    float* out = (float*)d_out;

    float *p_gx1, *p_gx1b, *p_h1, *p_h2, *p_BetaT, *p_t3, *p_M, *p_E, *p_n1, *p_n2;
    int *p_pid, *p_off;
    cudaGetSymbolAddress((void**)&p_gx1,  g_gx1);
    cudaGetSymbolAddress((void**)&p_gx1b, g_gx1b);
    cudaGetSymbolAddress((void**)&p_h1,   g_h1);
    cudaGetSymbolAddress((void**)&p_h2,   g_h2);
    cudaGetSymbolAddress((void**)&p_BetaT,g_BetaT);
    cudaGetSymbolAddress((void**)&p_t3,   g_t3);
    cudaGetSymbolAddress((void**)&p_pid,  g_pid);
    cudaGetSymbolAddress((void**)&p_off,  g_off);
    cudaGetSymbolAddress((void**)&p_M,    g_M);
    cudaGetSymbolAddress((void**)&p_E,    g_E);
    cudaGetSymbolAddress((void**)&p_n1,   g_n1);
    cudaGetSymbolAddress((void**)&p_n2,   g_n2);

    const int SMF  = (192*196 + 64*196 + 192*20 + 64*20)*4;  // 221184 B (lstm_mma2f)
    const int SMDB = (192*196 + 2*32*196)*4;                 // lstm_mma1_db
    const int GSH  = 128*132*4;                              // gx_hmma
    cudaFuncSetAttribute(lstm_mma2f,   cudaFuncAttributeMaxDynamicSharedMemorySize, SMF);
    cudaFuncSetAttribute(lstm_mma1_db, cudaFuncAttributeMaxDynamicSharedMemorySize, SMDB);
    cudaFuncSetAttribute(gx_hmma,      cudaFuncAttributeMaxDynamicSharedMemorySize, GSH);

    // #1-3: dynamic network + E1 (independent of LSTM chain)
    dyn_scalars<<<4, 256>>>(x, theta, p_pid, p_off);
    dyn_beta<<<NS, 256>>>(PP, p_pid, p_off, p_BetaT, p_t3);
    agg_extra<<<NS, 128>>>(p_t3, Wagg1 + (size_t)384*128, bagg1, p_E);

    // #4: fused layer0 (input GEMM + recurrence), fwd+bwd — PROFILED SLOT
    lstm_mma2f<<<dim3(64,2), 768, SMF>>>(x, Wih0, bih0, bhh0, Whh0, p_h1);

    // #5: layer1 fwd gx via hmma (K=384)
    gx_hmma<<<dim3(256,6), 256, GSH>>>(p_h1, 384, (size_t)NS*384,
                                       Wih1, p_gx1, 384, bih1, bhh1);

    // #6: layer1 bwd gx at t=31 (rows = s contiguous in time-major h1)
    gemm_nt128<<<dim3(8,6), 256>>>(p_h1 + (size_t)31*NS*384, 384,
                                   Wih1 + (size_t)G*384, 384,
                                   p_gx1b, G, 384, bih1 + G, bhh1 + G);

    // #7-8: layer1 recurrence fwd; bwd single step
    lstm_mma1_db<<<dim3(128,1), 768, SMDB>>>(p_gx1, Whh1, p_h2);
    bwd1_last<<<NS, H>>>(p_gx1b, p_h2);

    // #9-10: agg layer 1 (E1 already computed at #3)
    gemm_nn64<<<dim3(16,2), 256>>>(p_h2, 384, Wagg1, 128, p_M, 128, 384, (const float*)0);
    gemm_nn64<<<dim3(16,2), 256>>>(p_BetaT, NS, p_M, 128, p_n1, 128, NS, p_E);

    // #11-13: agg layer 2
    gemm_nn64<<<dim3(16,2), 256>>>(p_n1, 128, Wagg2, 128, p_M, 128, 128, (const float*)0);
    agg_extra<<<NS, 128>>>(p_t3, Wagg2 + (size_t)128*128, bagg2, p_E);
    gemm_nn64<<<dim3(16,2), 256>>>(p_BetaT, NS, p_M, 128, p_n2, 128, NS, p_E);

    // #14: output
    out_kernel<<<256, 256>>>(p_h2, p_n1, p_n2, Wout, bout, out);
}

// round 16
// speedup vs baseline: 2.3912x; 1.0694x over previous
#include <cuda_runtime.h>
#include <math.h>
#include <stdint.h>

#define NS 1024
#define T  32
#define NF 16
#define H  192
#define G  768

typedef unsigned long long u64;

static __device__ float g_gx1[(size_t)NS*T*G];     // time-major: [tt][G][NS]
static __device__ float g_gx1b[(size_t)NS*G];      // [s][G]
static __device__ float g_h1[(size_t)NS*T*384];    // TIME-MAJOR: [tt][s][384]
static __device__ float g_h2[(size_t)NS*384];
static __device__ float g_BetaT[(size_t)NS*NS];
static __device__ float g_t3[NS*3];
static __device__ int   g_pid[NS];
static __device__ int   g_off[NS];
static __device__ float g_M[NS*128];
static __device__ float g_E[NS*128];
static __device__ float g_n1[NS*128];
static __device__ float g_n2[NS*128];

__device__ __forceinline__ float sigm(float x){ return 1.f/(1.f+expf(-x)); }
__device__ __forceinline__ u64 pk(float x, float y){ u64 r; asm("mov.b64 %0,{%1,%2};":"=l"(r):"f"(x),"f"(y)); return r; }
__device__ __forceinline__ void fma2(u64& d, u64 a, u64 b){ asm("fma.rn.f32x2 %0,%1,%2,%0;":"+l"(d):"l"(a),"l"(b)); }
__device__ __forceinline__ void unpk(u64 v, float& x, float& y){ asm("mov.b64 {%0,%1},%2;":"=f"(x),"=f"(y):"l"(v)); }
__device__ __forceinline__ float lohi(u64 v){ float x,y; unpk(v,x,y); return x+y; }
__device__ __forceinline__ uint32_t smem_u32(const void* p){
    uint32_t a; asm("{ .reg .u64 t; cvta.to.shared.u64 t, %1; cvt.u32.u64 %0, t; }":"=r"(a):"l"(p)); return a;
}
__device__ __forceinline__ uint32_t tf32r(float x){
    uint32_t r; asm("cvt.rna.tf32.f32 %0,%1;":"=r"(r):"f"(x)); return r;
}
#define CL_ARRIVE() asm volatile("barrier.cluster.arrive.aligned;" ::: "memory")
#define CL_WAIT()   asm volatile("barrier.cluster.wait.aligned;"   ::: "memory")

__device__ __forceinline__ void mma_tf32(float& c0, float& c1, float& c2, float& c3,
                                         uint32_t a0, uint32_t a1, uint32_t a2, uint32_t a3,
                                         uint32_t b0, uint32_t b1){
    asm volatile(
        "mma.sync.aligned.m16n8k8.row.col.f32.tf32.tf32.f32 "
        "{%0,%1,%2,%3}, {%4,%5,%6,%7}, {%8,%9}, {%0,%1,%2,%3};"
        : "+f"(c0), "+f"(c1), "+f"(c2), "+f"(c3)
        : "r"(a0), "r"(a1), "r"(a2), "r"(a3), "r"(b0), "r"(b1));
}
__device__ __forceinline__ void dsmem_st4(uint32_t da, float4 v){
    asm volatile("st.shared::cluster.v4.f32 [%0],{%1,%2,%3,%4};"
                 :: "r"(da), "f"(v.x), "f"(v.y), "f"(v.z), "f"(v.w) : "memory");
}

// ---- generic gx GEMM via mma.sync tf32, double-buffered (R14-proven).
__global__ __launch_bounds__(256,2)
void gx_hmma(const float* __restrict__ A, int rstride, size_t tmul,
             const float* __restrict__ Bw, float* __restrict__ Ct, int K,
             const float* __restrict__ bias0, const float* __restrict__ bias1)
{
    extern __shared__ __align__(16) float dyn[];
    float* csh = dyn;                 // [128][132] reused for epilogue
    __shared__ float bsh[128];
    const int tt = blockIdx.x >> 3;
    const int s0 = (blockIdx.x & 7) * 128;
    const int n0 = blockIdx.y * 128;
    const int tid = threadIdx.x;
    const int w    = tid >> 5;
    const int lane = tid & 31;
    const int gid  = lane >> 2;
    const int tid4 = lane & 3;
    const int m0w  = (w & 1) * 64;
    const int n0w  = (w >> 1) * 32;
    const int row = tid>>1, kq = (tid&1)*8;
    const float* aBase = A + (size_t)(s0+row)*rstride + (size_t)tt*tmul + kq;
    const float* bBase = Bw + (size_t)(n0+row)*K + kq;

    if (tid < 128) bsh[tid] = bias0[n0+tid] + bias1[n0+tid];

    float acc[4][4][4];
    #pragma unroll
    for (int mi=0;mi<4;mi++)
        #pragma unroll
        for (int ni=0;ni<4;ni++)
            #pragma unroll
            for (int q=0;q<4;q++) acc[mi][ni][q]=0.f;

    float4 a0 = *(const float4*)(aBase);
    float4 a1 = *(const float4*)(aBase + 4);
    float4 b0 = *(const float4*)(bBase);
    float4 b1 = *(const float4*)(bBase + 4);
    {
        float* As = dyn; float* Bs = dyn + 2176;
        As[(kq+0)*136+row]=__uint_as_float(tf32r(a0.x)); As[(kq+1)*136+row]=__uint_as_float(tf32r(a0.y));
        As[(kq+2)*136+row]=__uint_as_float(tf32r(a0.z)); As[(kq+3)*136+row]=__uint_as_float(tf32r(a0.w));
        As[(kq+4)*136+row]=__uint_as_float(tf32r(a1.x)); As[(kq+5)*136+row]=__uint_as_float(tf32r(a1.y));
        As[(kq+6)*136+row]=__uint_as_float(tf32r(a1.z)); As[(kq+7)*136+row]=__uint_as_float(tf32r(a1.w));
        Bs[(kq+0)*136+row]=__uint_as_float(tf32r(b0.x)); Bs[(kq+1)*136+row]=__uint_as_float(tf32r(b0.y));
        Bs[(kq+2)*136+row]=__uint_as_float(tf32r(b0.z)); Bs[(kq+3)*136+row]=__uint_as_float(tf32r(b0.w));
        Bs[(kq+4)*136+row]=__uint_as_float(tf32r(b1.x)); Bs[(kq+5)*136+row]=__uint_as_float(tf32r(b1.y));
        Bs[(kq+6)*136+row]=__uint_as_float(tf32r(b1.z)); Bs[(kq+7)*136+row]=__uint_as_float(tf32r(b1.w));
    }
    __syncthreads();

    int buf = 0;
    for (int k0=0;k0<K;k0+=16){
        const bool nxt = (k0+16)<K;
        if (nxt){
            a0 = *(const float4*)(aBase + k0+16);
            a1 = *(const float4*)(aBase + k0+20);
            b0 = *(const float4*)(bBase + k0+16);
            b1 = *(const float4*)(bBase + k0+20);
        }
        const float* As = dyn + buf*4352;
        const float* Bs = As + 2176;
        #pragma unroll
        for (int k8=0;k8<16;k8+=8){
            uint32_t af[4][4];
            #pragma unroll
            for (int mi=0;mi<4;mi++){
                int m = m0w + mi*16 + gid;
                af[mi][0] = __float_as_uint(As[(k8+tid4  )*136 + m  ]);
                af[mi][1] = __float_as_uint(As[(k8+tid4  )*136 + m+8]);
                af[mi][2] = __float_as_uint(As[(k8+tid4+4)*136 + m  ]);
                af[mi][3] = __float_as_uint(As[(k8+tid4+4)*136 + m+8]);
            }
            uint32_t bf[4][2];
            #pragma unroll
            for (int ni=0;ni<4;ni++){
                int n = n0w + ni*8 + gid;
                bf[ni][0] = __float_as_uint(Bs[(k8+tid4  )*136 + n]);
                bf[ni][1] = __float_as_uint(Bs[(k8+tid4+4)*136 + n]);
            }
            #pragma unroll
            for (int mi=0;mi<4;mi++)
                #pragma unroll
                for (int ni=0;ni<4;ni++)
                    mma_tf32(acc[mi][ni][0], acc[mi][ni][1], acc[mi][ni][2], acc[mi][ni][3],
                             af[mi][0], af[mi][1], af[mi][2], af[mi][3],
                             bf[ni][0], bf[ni][1]);
        }
        if (nxt){
            float* An = dyn + (buf^1)*4352;
            float* Bn = An + 2176;
            An[(kq+0)*136+row]=__uint_as_float(tf32r(a0.x)); An[(kq+1)*136+row]=__uint_as_float(tf32r(a0.y));
            An[(kq+2)*136+row]=__uint_as_float(tf32r(a0.z)); An[(kq+3)*136+row]=__uint_as_float(tf32r(a0.w));
            An[(kq+4)*136+row]=__uint_as_float(tf32r(a1.x)); An[(kq+5)*136+row]=__uint_as_float(tf32r(a1.y));
            An[(kq+6)*136+row]=__uint_as_float(tf32r(a1.z)); An[(kq+7)*136+row]=__uint_as_float(tf32r(a1.w));
            Bn[(kq+0)*136+row]=__uint_as_float(tf32r(b0.x)); Bn[(kq+1)*136+row]=__uint_as_float(tf32r(b0.y));
            Bn[(kq+2)*136+row]=__uint_as_float(tf32r(b0.z)); Bn[(kq+3)*136+row]=__uint_as_float(tf32r(b0.w));
            Bn[(kq+4)*136+row]=__uint_as_float(tf32r(b1.x)); Bn[(kq+5)*136+row]=__uint_as_float(tf32r(b1.y));
            Bn[(kq+6)*136+row]=__uint_as_float(tf32r(b1.z)); Bn[(kq+7)*136+row]=__uint_as_float(tf32r(b1.w));
            __syncthreads();
            buf ^= 1;
        }
    }
    __syncthreads();
    #pragma unroll
    for (int mi=0;mi<4;mi++){
        #pragma unroll
        for (int ni=0;ni<4;ni++){
            int nl = n0w + ni*8 + tid4*2;
            int ml = m0w + mi*16 + gid;
            csh[(size_t)(nl  )*132 + ml  ] = acc[mi][ni][0] + bsh[nl];
            csh[(size_t)(nl+1)*132 + ml  ] = acc[mi][ni][1] + bsh[nl+1];
            csh[(size_t)(nl  )*132 + ml+8] = acc[mi][ni][2] + bsh[nl];
            csh[(size_t)(nl+1)*132 + ml+8] = acc[mi][ni][3] + bsh[nl+1];
        }
    }
    __syncthreads();
    {
        int jl = tid>>1, half = (tid&1)*64;
        const float* src = csh + (size_t)jl*132 + half;
        float* dst = Ct + ((size_t)tt*G + n0 + jl)*NS + s0 + half;
        #pragma unroll
        for (int v=0;v<16;v++)
            *(float4*)(dst + v*4) = *(const float4*)(src + v*4);
    }
}

// ---- FUSED layer-0 LSTM (input GEMM + recurrence), MW=2, SPC=64.
// DSMEM exchange now cooperative float4 (3 remote ST.128/thread/step).
__global__ __launch_bounds__(768,1) __cluster_dims__(4,1,1)
void lstm_mma2f(const float* __restrict__ x,
                const float* __restrict__ Wih_all, const float* __restrict__ bih_all,
                const float* __restrict__ bhh_all, const float* __restrict__ Whh_all,
                float* __restrict__ outp)
{
    constexpr int MW = 2, SPC = 64, NI = 2, HSP = 196, BSP = 196;
    constexpr int WSP = 20, XSP = 20;
    extern __shared__ float sm[];
    float* Bsh = sm;                       // [192][BSP] Whh tf32, row = ul*4+q
    float* Hs  = Bsh + 192*BSP;            // [SPC][HSP] h tf32
    float* ws  = Hs + SPC*HSP;             // [192][WSP] Wih tf32
    float* xs  = ws + 192*WSP;             // [SPC][XSP] x step-slice tf32

    const int dir  = blockIdx.y;
    const float* Whh = Whh_all + (size_t)dir*G*H;
    const float* Wih = Wih_all + (size_t)dir*G*NF;

    const int tid  = threadIdx.x;
    const int w    = tid >> 5;
    const int lane = tid & 31;
    const int gid  = lane >> 2;
    const int tid4 = lane & 3;
    const int mw   = w % MW;
    const int nw   = w / MW;
    const bool ev  = ((tid4 & 1) == 0);
    uint32_t rank; asm("mov.u32 %0, %%cluster_ctarank;" : "=r"(rank));
    const int cid   = blockIdx.x >> 2;
    const int sbase = cid * SPC;
    const int jsl   = (int)rank * 48;
    const uint32_t hs_base = smem_u32(Hs);

    for (int i = tid; i < 192*48; i += 768){
        int lr = i / 48, c4 = i % 48;
        int ul = lr >> 2, q = lr & 3;
        float4 v = *(const float4*)(Whh + (size_t)(q*192 + jsl + ul)*H + c4*4);
        float* bp = Bsh + lr*BSP + c4*4;
        bp[0]=__uint_as_float(tf32r(v.x)); bp[1]=__uint_as_float(tf32r(v.y));
        bp[2]=__uint_as_float(tf32r(v.z)); bp[3]=__uint_as_float(tf32r(v.w));
    }
    for (int i = tid; i < 192*16; i += 768){
        int lr = i >> 4, k = i & 15;
        int ul = lr >> 2, q = lr & 3;
        ws[lr*WSP + k] = __uint_as_float(tf32r(Wih[(size_t)(q*192 + jsl + ul)*NF + k]));
    }
    for (int i = tid; i < SPC*HSP; i += 768) Hs[i] = 0.f;

    float bq[NI][4];
    #pragma unroll
    for (int ni=0;ni<NI;ni++){
        int ul = 2*(nw*NI + ni) + (tid4>>1);
        #pragma unroll
        for (int q=0;q<4;q++){
            size_t idx = (size_t)dir*G + q*192 + jsl + ul;
            bq[ni][q] = bih_all[idx] + bhh_all[idx];
        }
    }
    CL_ARRIVE(); CL_WAIT();

    float cst[2][NI];
    #pragma unroll
    for (int a=0;a<2;a++)
        #pragma unroll
        for (int b=0;b<NI;b++) cst[a][b]=0.f;

    int sl_t = mw*32 + gid + (ev ? 0 : 8);
    // cooperative exchange indices: 64 rows x 12 float4 = 768 = blockDim
    const int xr  = tid / 12;          // row
    const int xc4 = tid % 12;          // float4 col within 48-unit slice
    const uint32_t xla = hs_base + (uint32_t)(xr*HSP + jsl + xc4*4)*4u;

    for (int step=0; step<T; ++step){
        const int tt = (dir==1) ? (T-1-step) : step;

        for (int i = tid; i < SPC*NF; i += 768){
            int sl = i >> 4, f = i & 15;
            xs[sl*XSP + f] = __uint_as_float(tf32r(
                x[((size_t)(sbase+sl)*T + tt)*NF + f]));
        }
        __syncthreads();

        float acc[2][NI][4];
        #pragma unroll
        for (int mi=0;mi<2;mi++)
            #pragma unroll
            for (int ni=0;ni<NI;ni++)
                #pragma unroll
                for (int q=0;q<4;q++) acc[mi][ni][q]=0.f;

        #pragma unroll
        for (int k8=0;k8<16;k8+=8){
            uint32_t af[2][4];
            #pragma unroll
            for (int mi=0;mi<2;mi++){
                int m = mw*32 + mi*16 + gid;
                af[mi][0] = __float_as_uint(xs[(m  )*XSP + k8+tid4  ]);
                af[mi][1] = __float_as_uint(xs[(m+8)*XSP + k8+tid4  ]);
                af[mi][2] = __float_as_uint(xs[(m  )*XSP + k8+tid4+4]);
                af[mi][3] = __float_as_uint(xs[(m+8)*XSP + k8+tid4+4]);
            }
            uint32_t bf[NI][2];
            #pragma unroll
            for (int ni=0;ni<NI;ni++){
                int n = (nw*NI + ni)*8 + gid;
                bf[ni][0] = __float_as_uint(ws[n*WSP + k8+tid4  ]);
                bf[ni][1] = __float_as_uint(ws[n*WSP + k8+tid4+4]);
            }
            #pragma unroll
            for (int mi=0;mi<2;mi++)
                #pragma unroll
                for (int ni=0;ni<NI;ni++)
                    mma_tf32(acc[mi][ni][0], acc[mi][ni][1], acc[mi][ni][2], acc[mi][ni][3],
                             af[mi][0], af[mi][1], af[mi][2], af[mi][3],
                             bf[ni][0], bf[ni][1]);
        }

        #pragma unroll 2
        for (int k8=0;k8<192;k8+=8){
            uint32_t af[2][4];
            #pragma unroll
            for (int mi=0;mi<2;mi++){
                int m = mw*32 + mi*16 + gid;
                af[mi][0] = __float_as_uint(Hs[(m  )*HSP + k8+tid4  ]);
                af[mi][1] = __float_as_uint(Hs[(m+8)*HSP + k8+tid4  ]);
                af[mi][2] = __float_as_uint(Hs[(m  )*HSP + k8+tid4+4]);
                af[mi][3] = __float_as_uint(Hs[(m+8)*HSP + k8+tid4+4]);
            }
            uint32_t bf[NI][2];
            #pragma unroll
            for (int ni=0;ni<NI;ni++){
                int n = (nw*NI + ni)*8 + gid;
                bf[ni][0] = __float_as_uint(Bsh[n*BSP + k8+tid4  ]);
                bf[ni][1] = __float_as_uint(Bsh[n*BSP + k8+tid4+4]);
            }
            #pragma unroll
            for (int mi=0;mi<2;mi++)
                #pragma unroll
                for (int ni=0;ni<NI;ni++)
                    mma_tf32(acc[mi][ni][0], acc[mi][ni][1], acc[mi][ni][2], acc[mi][ni][3],
                             af[mi][0], af[mi][1], af[mi][2], af[mi][3],
                             bf[ni][0], bf[ni][1]);
        }

        CL_ARRIVE();                  // my reads of Hs(t-1)/xs done
        CL_WAIT();                    // all CTAs' reads done -> safe to write Hs

        float hout[2][NI];
        #pragma unroll
        for (int mi=0;mi<2;mi++){
            #pragma unroll
            for (int ni=0;ni<NI;ni++){
                float c0=acc[mi][ni][0], c1=acc[mi][ni][1];
                float c2=acc[mi][ni][2], c3=acc[mi][ni][3];
                float s0 = ev ? c2 : c0;
                float s1 = ev ? c3 : c1;
                float r0 = __shfl_xor_sync(0xffffffffu, s0, 1);
                float r1 = __shfl_xor_sync(0xffffffffu, s1, 1);
                float pi = (ev ? c0 : r0) + bq[ni][0];
                float pf = (ev ? c1 : r1) + bq[ni][1];
                float pg = (ev ? r0 : c2) + bq[ni][2];
                float po = (ev ? r1 : c3) + bq[ni][3];
                float iv = sigm(pi), fv = sigm(pf);
                float gv = tanhf(pg), ov = sigm(po);
                float cc = fv*cst[mi][ni] + iv*gv;
                cst[mi][ni] = cc;
                float hh = ov*tanhf(cc);
                hout[mi][ni] = hh;
                int sl = sl_t + mi*16;
                int ul = 2*(nw*NI + ni) + (tid4>>1);
                Hs[sl*HSP + jsl + ul] = __uint_as_float(tf32r(hh));
            }
        }
        __syncthreads();              // own slice fully written locally
        // cooperative vectorized push of own 48-unit slice to 3 peers
        {
            float4 v = *(const float4*)(Hs + xr*HSP + jsl + xc4*4);
            #pragma unroll
            for (int r=0;r<4;r++){
                if (r == (int)rank) continue;
                uint32_t da; asm("mapa.shared::cluster.u32 %0,%1,%2;":"=r"(da):"r"(xla),"r"(r));
                dsmem_st4(da, v);
            }
        }
        CL_ARRIVE();                  // release h(t)
        #pragma unroll
        for (int mi=0;mi<2;mi++){
            int s = sbase + sl_t + mi*16;
            #pragma unroll
            for (int ni=0;ni<NI;ni++){
                int ul = 2*(nw*NI + ni) + (tid4>>1);
                outp[((size_t)tt*NS + s)*384 + dir*192 + jsl + ul] = hout[mi][ni];
            }
        }
        CL_WAIT();                    // acquire peers' h(t)
    }
}

// ---- layer1 fwd LSTM, MW=1 (SPC=32), double-buffered Hs, 1 barrier/step.
__global__ __launch_bounds__(768,1) __cluster_dims__(4,1,1)
void lstm_mma1_db(const float* __restrict__ gx, const float* __restrict__ Whh,
                  float* __restrict__ outp)
{
    constexpr int SPC = 32, HSP = 196, BSP = 196;
    extern __shared__ float sm[];
    float* Bsh = sm;               // [192][BSP]
    float* Hs0 = sm + 192*BSP;     // [2][SPC][HSP]

    const int tid  = threadIdx.x;
    const int w    = tid >> 5;
    const int lane = tid & 31;
    const int gid  = lane >> 2;
    const int tid4 = lane & 3;
    const int nw   = w;
    const bool ev  = ((tid4 & 1) == 0);
    uint32_t rank; asm("mov.u32 %0, %%cluster_ctarank;" : "=r"(rank));
    const int cid   = blockIdx.x >> 2;
    const int sbase = cid * SPC;
    const int jsl   = (int)rank * 48;
    const uint32_t hb0 = smem_u32(Hs0);
    const uint32_t hb1 = smem_u32(Hs0 + SPC*HSP);

    for (int i = tid; i < 192*48; i += 768){
        int lr = i / 48, c4 = i % 48;
        int ul = lr >> 2, q = lr & 3;
        float4 v = *(const float4*)(Whh + (size_t)(q*192 + jsl + ul)*H + c4*4);
        float* bp = Bsh + lr*BSP + c4*4;
        bp[0]=__uint_as_float(tf32r(v.x)); bp[1]=__uint_as_float(tf32r(v.y));
        bp[2]=__uint_as_float(tf32r(v.z)); bp[3]=__uint_as_float(tf32r(v.w));
    }
    for (int i = tid; i < 2*SPC*HSP; i += 768) Hs0[i] = 0.f;
    CL_ARRIVE(); CL_WAIT();

    float cst[2];
    cst[0]=0.f; cst[1]=0.f;
    int sl_t = gid + (ev ? 0 : 8);
    const int ul = 2*nw + (tid4>>1);

    for (int step=0; step<T; ++step){
        const int tt = step;
        const float* Hr = Hs0 + (step&1)*SPC*HSP;
        float* Hw = Hs0 + ((step&1)^1)*SPC*HSP;
        const uint32_t hw_base = (step&1) ? hb0 : hb1;

        float gxr[2][4];
        #pragma unroll
        for (int mi=0;mi<2;mi++){
            int s = sbase + sl_t + mi*16;
            #pragma unroll
            for (int q=0;q<4;q++)
                gxr[mi][q] = gx[((size_t)tt*G + q*192 + jsl + ul)*NS + s];
        }

        float acc[2][4];
        #pragma unroll
        for (int mi=0;mi<2;mi++)
            #pragma unroll
            for (int q=0;q<4;q++) acc[mi][q]=0.f;

        #pragma unroll 2
        for (int k8=0;k8<192;k8+=8){
            uint32_t af[2][4];
            #pragma unroll
            for (int mi=0;mi<2;mi++){
                int m = mi*16 + gid;
                af[mi][0] = __float_as_uint(Hr[(m  )*HSP + k8+tid4  ]);
                af[mi][1] = __float_as_uint(Hr[(m+8)*HSP + k8+tid4  ]);
                af[mi][2] = __float_as_uint(Hr[(m  )*HSP + k8+tid4+4]);
                af[mi][3] = __float_as_uint(Hr[(m+8)*HSP + k8+tid4+4]);
            }
            uint32_t bf[2];
            {
                int n = nw*8 + gid;
                bf[0] = __float_as_uint(Bsh[n*BSP + k8+tid4  ]);
                bf[1] = __float_as_uint(Bsh[n*BSP + k8+tid4+4]);
            }
            #pragma unroll
            for (int mi=0;mi<2;mi++)
                mma_tf32(acc[mi][0], acc[mi][1], acc[mi][2], acc[mi][3],
                         af[mi][0], af[mi][1], af[mi][2], af[mi][3],
                         bf[0], bf[1]);
        }

        float hout[2];
        #pragma unroll
        for (int mi=0;mi<2;mi++){
            float c0=acc[mi][0], c1=acc[mi][1], c2=acc[mi][2], c3=acc[mi][3];
            float s0 = ev ? c2 : c0;
            float s1 = ev ? c3 : c1;
            float r0 = __shfl_xor_sync(0xffffffffu, s0, 1);
            float r1 = __shfl_xor_sync(0xffffffffu, s1, 1);
            float pi = (ev ? c0 : r0) + gxr[mi][0];
            float pf = (ev ? c1 : r1) + gxr[mi][1];
            float pg = (ev ? r0 : c2) + gxr[mi][2];
            float po = (ev ? r1 : c3) + gxr[mi][3];
            float iv = sigm(pi), fv = sigm(pf);
            float gv = tanhf(pg), ov = sigm(po);
            float cc = fv*cst[mi] + iv*gv;
            cst[mi] = cc;
            float hh = ov*tanhf(cc);
            hout[mi] = hh;
            int sl = sl_t + mi*16;
            Hw[sl*HSP + jsl + ul] = __uint_as_float(tf32r(hh));
        }
        __syncthreads();              // own slice written locally to Hw
        // cooperative push: 32 rows x 12 float4 x 3 peers = 1152 ops / 768 thr
        for (int i = tid; i < 1152; i += 768){
            int pr = i / 384, j = i - pr*384;
            int r  = pr + (pr >= (int)rank ? 1 : 0);
            int row = j / 12, c4 = j - row*12;
            uint32_t la = hw_base + (uint32_t)(row*HSP + jsl + c4*4)*4u;
            float4 v = *(const float4*)(Hw + row*HSP + jsl + c4*4);
            uint32_t da; asm("mapa.shared::cluster.u32 %0,%1,%2;":"=r"(da):"r"(la),"r"(r));
            dsmem_st4(da, v);
        }
        CL_ARRIVE();
        if (step==T-1){
            #pragma unroll
            for (int mi=0;mi<2;mi++){
                int s = sbase + sl_t + mi*16;
                outp[(size_t)s*384 + jsl + ul] = hout[mi];
            }
        }
        CL_WAIT();
    }
}

// ---- plain NT gemm (gx1b), C[m][n] layout ----
__global__ __launch_bounds__(256,2)
void gemm_nt128(const float* __restrict__ A, int lda,
                const float* __restrict__ B, int ldb,
                float* __restrict__ C, int ldc, int K,
                const float* __restrict__ bias0, const float* __restrict__ bias1)
{
    __shared__ __align__(16) float As[16][136];
    __shared__ __align__(16) float Bs[16][136];
    const int m0 = blockIdx.x*128, n0 = blockIdx.y*128;
    const int tid = threadIdx.x;
    const int ty = tid>>4, tx = tid&15;
    const int row = tid>>1, kq = (tid&1)*8;
    u64 acc[4][8];
    #pragma unroll
    for (int i=0;i<4;i++)
        #pragma unroll
        for (int j=0;j<8;j++) acc[i][j]=0ull;

    for (int k0=0;k0<K;k0+=16){
        float4 a0 = *(const float4*)(A + (size_t)(m0+row)*lda + k0 + kq);
        float4 a1 = *(const float4*)(A + (size_t)(m0+row)*lda + k0 + kq + 4);
        float4 b0 = *(const float4*)(B + (size_t)(n0+row)*ldb + k0 + kq);
        float4 b1 = *(const float4*)(B + (size_t)(n0+row)*ldb + k0 + kq + 4);
        __syncthreads();
        As[kq+0][row]=a0.x; As[kq+1][row]=a0.y; As[kq+2][row]=a0.z; As[kq+3][row]=a0.w;
        As[kq+4][row]=a1.x; As[kq+5][row]=a1.y; As[kq+6][row]=a1.z; As[kq+7][row]=a1.w;
        Bs[kq+0][row]=b0.x; Bs[kq+1][row]=b0.y; Bs[kq+2][row]=b0.z; Bs[kq+3][row]=b0.w;
        Bs[kq+4][row]=b1.x; Bs[kq+5][row]=b1.y; Bs[kq+6][row]=b1.z; Bs[kq+7][row]=b1.w;
        __syncthreads();
        #pragma unroll
        for (int k=0;k<16;k++){
            ulonglong2 av0 = *(const ulonglong2*)&As[k][ty*8];
            ulonglong2 av1 = *(const ulonglong2*)&As[k][ty*8+4];
            float4 bA = *(const float4*)&Bs[k][tx*8];
            float4 bB = *(const float4*)&Bs[k][tx*8+4];
            u64 bb[8];
            bb[0]=pk(bA.x,bA.x); bb[1]=pk(bA.y,bA.y); bb[2]=pk(bA.z,bA.z); bb[3]=pk(bA.w,bA.w);
            bb[4]=pk(bB.x,bB.x); bb[5]=pk(bB.y,bB.y); bb[6]=pk(bB.z,bB.z); bb[7]=pk(bB.w,bB.w);
            u64 aa[4] = { av0.x, av0.y, av1.x, av1.y };
            #pragma unroll
            for (int i2=0;i2<4;i2++)
                #pragma unroll
                for (int j=0;j<8;j++) fma2(acc[i2][j], aa[i2], bb[j]);
        }
    }
    float bv[8];
    #pragma unroll
    for (int j=0;j<8;j++){
        int n = n0+tx*8+j;
        float v = 0.f;
        if (bias0) v += bias0[n];
        if (bias1) v += bias1[n];
        bv[j]=v;
    }
    #pragma unroll
    for (int i2=0;i2<4;i2++){
        float r0[8], r1[8];
        #pragma unroll
        for (int j=0;j<8;j++){ unpk(acc[i2][j], r0[j], r1[j]); r0[j]+=bv[j]; r1[j]+=bv[j]; }
        float* c0 = C + (size_t)(m0+ty*8+2*i2)*ldc + n0 + tx*8;
        float* c1 = C + (size_t)(m0+ty*8+2*i2+1)*ldc + n0 + tx*8;
        *(float4*)c0     = make_float4(r0[0],r0[1],r0[2],r0[3]);
        *(float4*)(c0+4) = make_float4(r0[4],r0[5],r0[6],r0[7]);
        *(float4*)c1     = make_float4(r1[0],r1[1],r1[2],r1[3]);
        *(float4*)(c1+4) = make_float4(r1[4],r1[5],r1[6],r1[7]);
    }
}

// ---- C[m][n] = sum_k A[m][k]*B[k][n] (+addC), 64x64 tile, 4x4 micro.
__global__ __launch_bounds__(256,1)
void gemm_nn64(const float* __restrict__ A, int lda,
               const float* __restrict__ B, int ldb,
               float* __restrict__ C, int ldc, int K,
               const float* __restrict__ addC)
{
    __shared__ __align__(16) float As[16][68];
    __shared__ __align__(16) float Bs[16][68];
    const int m0 = blockIdx.x*64, n0 = blockIdx.y*64;
    const int tid = threadIdx.x;
    const int ty = tid>>4, tx = tid&15;
    const int arow = tid>>2, akq = (tid&3)*4;
    const int bk = tid>>4, bnq = (tid&15)*4;
    float acc[4][4];
    #pragma unroll
    for (int i=0;i<4;i++)
        #pragma unroll
        for (int j=0;j<4;j++) acc[i][j]=0.f;

    for (int k0=0;k0<K;k0+=16){
        float4 av = *(const float4*)(A + (size_t)(m0+arow)*lda + k0 + akq);
        float4 bv = *(const float4*)(B + (size_t)(k0+bk)*ldb + n0 + bnq);
        __syncthreads();
        As[akq+0][arow]=av.x; As[akq+1][arow]=av.y; As[akq+2][arow]=av.z; As[akq+3][arow]=av.w;
        *(float4*)&Bs[bk][bnq] = bv;
        __syncthreads();
        #pragma unroll
        for (int k=0;k<16;k++){
            float a[4],b[4];
            #pragma unroll
            for (int i=0;i<4;i++){ a[i]=As[k][ty*4+i]; b[i]=Bs[k][tx*4+i]; }
            #pragma unroll
            for (int i=0;i<4;i++)
                #pragma unroll
                for (int j=0;j<4;j++) acc[i][j]+=a[i]*b[j];
        }
    }
    #pragma unroll
    for (int i=0;i<4;i++){
        int m = m0+ty*4+i;
        float* cp = C + (size_t)m*ldc + n0 + tx*4;
        const float* ap = addC ? addC + (size_t)m*ldc + n0 + tx*4 : (const float*)0;
        #pragma unroll
        for (int j=0;j<4;j++){
            float v = acc[i][j];
            if (ap) v += ap[j];
            cp[j] = v;
        }
    }
}

// ---- layer1 bwd @ t=31 only (h0=c0=0) ----
__global__ void bwd1_last(const float* __restrict__ gxb, float* __restrict__ h2)
{
    int n = blockIdx.x, j = threadIdx.x;
    const float* g = gxb + (size_t)n*G;
    float iv = sigm(g[j]);
    float gv = tanhf(g[2*H+j]);
    float ov = sigm(g[3*H+j]);
    float cc = iv*gv;
    h2[(size_t)n*384 + 192 + j] = ov*tanhf(cc);
}

// ---- dynamic network ----
__global__ void dyn_scalars(const float* __restrict__ x, const float* __restrict__ theta,
                            int* __restrict__ pid, int* __restrict__ off)
{
    int n = blockIdx.x*blockDim.x + threadIdx.x;
    if (n >= NS) return;
    float th  = theta[n];
    float x30 = x[((size_t)n*T + 30)*NF];
    float x31 = x[((size_t)n*T + 31)*NF];
    int p0 = (x30 > th) ? 1 : ((x30 < -th) ? -1 : 0);
    int p1 = (x31 > th) ? 1 : ((x31 < -th) ? -1 : 0);
    pid[n] = (p0+1)*3 + (p1+1);
    off[n] = (p1+1)*3;
}

__global__ __launch_bounds__(256,1)
void dyn_beta(const float* __restrict__ PP, const int* __restrict__ pid,
              const int* __restrict__ off, float* __restrict__ BetaT,
              float* __restrict__ t3)
{
    __shared__ float s_raw[1024];
    __shared__ float s_adj[1024*3];
    __shared__ float s_red[256];
    const int y = blockIdx.x, tid = threadIdx.x;
    const int offy = off[y];
    for (int x=tid; x<NS; x+=256){
        size_t base = ((size_t)x*NS + y)*81 + (size_t)pid[x]*9 + offy;
        float a0=PP[base], a1=PP[base+1], a2=PP[base+2];
        s_adj[x*3+0]=a0; s_adj[x*3+1]=a1; s_adj[x*3+2]=a2;
        float nr = sqrtf(a0*a0+a1*a1+a2*a2);
        s_raw[x] = (nr > 0.38f) ? nr : 0.f;
    }
    __syncthreads();
    float lm = -1e30f;
    for (int x=tid; x<NS; x+=256) lm = fmaxf(lm, s_raw[x]);
    s_red[tid]=lm; __syncthreads();
    for (int o=128;o>0;o>>=1){ if(tid<o) s_red[tid]=fmaxf(s_red[tid],s_red[tid+o]); __syncthreads(); }
    const float mx = s_red[0];
    __syncthreads();
    float ls = 0.f;
    for (int x=tid; x<NS; x+=256){ float e=expf(s_raw[x]-mx); s_raw[x]=e; ls+=e; }
    s_red[tid]=ls; __syncthreads();
    for (int o=128;o>0;o>>=1){ if(tid<o) s_red[tid]+=s_red[tid+o]; __syncthreads(); }
    const float inv = 1.f/s_red[0];
    __syncthreads();
    float t0=0.f,t1=0.f,t2=0.f;
    for (int x=tid; x<NS; x+=256){
        float b = s_raw[x]*inv;
        BetaT[(size_t)y*NS + x] = b;
        t0 += b*s_adj[x*3+0]; t1 += b*s_adj[x*3+1]; t2 += b*s_adj[x*3+2];
    }
    s_red[tid]=t0; __syncthreads();
    for (int o=128;o>0;o>>=1){ if(tid<o) s_red[tid]+=s_red[tid+o]; __syncthreads(); }
    if(tid==0) t3[y*3+0]=s_red[0];
    __syncthreads();
    s_red[tid]=t1; __syncthreads();
    for (int o=128;o>0;o>>=1){ if(tid<o) s_red[tid]+=s_red[tid+o]; __syncthreads(); }
    if(tid==0) t3[y*3+1]=s_red[0];
    __syncthreads();
    s_red[tid]=t2; __syncthreads();
    for (int o=128;o>0;o>>=1){ if(tid<o) s_red[tid]+=s_red[tid+o]; __syncthreads(); }
    if(tid==0) t3[y*3+2]=s_red[0];
}

__global__ void agg_extra(const float* __restrict__ t3, const float* __restrict__ Wa,
                          const float* __restrict__ b, float* __restrict__ E)
{
    int y = blockIdx.x, u = threadIdx.x;
    float v = b[u] + t3[y*3+0]*Wa[u] + t3[y*3+1]*Wa[128+u] + t3[y*3+2]*Wa[256+u];
    E[(size_t)y*128 + u] = v;
}

__global__ void out_kernel(const float* __restrict__ nfeat, const float* __restrict__ n1,
                           const float* __restrict__ n2, const float* __restrict__ W,
                           const float* __restrict__ b, float* __restrict__ out)
{
    int warp = (blockIdx.x*blockDim.x + threadIdx.x)>>5;
    int lane = threadIdx.x & 31;
    if (warp >= NS*2) return;
    int n = warp>>1, o = warp&1;
    float s = 0.f;
    for (int k=lane;k<384;k+=32) s += nfeat[(size_t)n*384+k]*W[k*2+o];
    for (int k=lane;k<128;k+=32) s += n1[(size_t)n*128+k]*W[(384+k)*2+o];
    for (int k=lane;k<128;k+=32) s += n2[(size_t)n*128+k]*W[(512+k)*2+o];
    #pragma unroll
    for (int m=16;m>0;m>>=1) s += __shfl_xor_sync(0xffffffffu, s, m);
    if (lane==0) out[warp] = tanhf(s + b[o]);
}

extern "C" void kernel_launch(void* const* d_in, const int* in_sizes, int n_in,
                              void* d_out, int out_size)
{
    const float* x     = (const float*)d_in[0];
    const float* theta = (const float*)d_in[1];
    const float* PP    = (const float*)d_in[2];
    const float* Wih0  = (const float*)d_in[3];
    const float* Whh0  = (const float*)d_in[4];
    const float* bih0  = (const float*)d_in[5];
    const float* bhh0  = (const float*)d_in[6];
    const float* Wih1  = (const float*)d_in[7];
    const float* Whh1  = (const float*)d_in[8];
    const float* bih1  = (const float*)d_in[9];
    const float* bhh1  = (const float*)d_in[10];
    const float* Wagg1 = (const float*)d_in[11];
    const float* bagg1 = (const float*)d_in[12];
    const float* Wagg2 = (const float*)d_in[13];
    const float* bagg2 = (const float*)d_in[14];
    const float* Wout  = (const float*)d_in[15];
    const float* bout  = (const float*)d_in[16];
    float* out = (float*)d_out;

    float *p_gx1, *p_gx1b, *p_h1, *p_h2, *p_BetaT, *p_t3, *p_M, *p_E, *p_n1, *p_n2;
    int *p_pid, *p_off;
    cudaGetSymbolAddress((void**)&p_gx1,  g_gx1);
    cudaGetSymbolAddress((void**)&p_gx1b, g_gx1b);
    cudaGetSymbolAddress((void**)&p_h1,   g_h1);
    cudaGetSymbolAddress((void**)&p_h2,   g_h2);
    cudaGetSymbolAddress((void**)&p_BetaT,g_BetaT);
    cudaGetSymbolAddress((void**)&p_t3,   g_t3);
    cudaGetSymbolAddress((void**)&p_pid,  g_pid);
    cudaGetSymbolAddress((void**)&p_off,  g_off);
    cudaGetSymbolAddress((void**)&p_M,    g_M);
    cudaGetSymbolAddress((void**)&p_E,    g_E);
    cudaGetSymbolAddress((void**)&p_n1,   g_n1);
    cudaGetSymbolAddress((void**)&p_n2,   g_n2);

    const int SMF  = (192*196 + 64*196 + 192*20 + 64*20)*4;  // 221184 B
    const int SMDB = (192*196 + 2*32*196)*4;                 // lstm_mma1_db
    const int GSH  = 128*132*4;                              // gx_hmma
    cudaFuncSetAttribute(lstm_mma2f,   cudaFuncAttributeMaxDynamicSharedMemorySize, SMF);
    cudaFuncSetAttribute(lstm_mma1_db, cudaFuncAttributeMaxDynamicSharedMemorySize, SMDB);
    cudaFuncSetAttribute(gx_hmma,      cudaFuncAttributeMaxDynamicSharedMemorySize, GSH);

    // #1-3: dynamic network + E1 (independent of LSTM chain)
    dyn_scalars<<<4, 256>>>(x, theta, p_pid, p_off);
    dyn_beta<<<NS, 256>>>(PP, p_pid, p_off, p_BetaT, p_t3);
    agg_extra<<<NS, 128>>>(p_t3, Wagg1 + (size_t)384*128, bagg1, p_E);

    // #4: fused layer0 (input GEMM + recurrence), fwd+bwd — PROFILED SLOT
    lstm_mma2f<<<dim3(64,2), 768, SMF>>>(x, Wih0, bih0, bhh0, Whh0, p_h1);

    // #5: layer1 fwd gx via hmma (K=384)
    gx_hmma<<<dim3(256,6), 256, GSH>>>(p_h1, 384, (size_t)NS*384,
                                       Wih1, p_gx1, 384, bih1, bhh1);

    // #6: layer1 bwd gx at t=31 (rows = s contiguous in time-major h1)
    gemm_nt128<<<dim3(8,6), 256>>>(p_h1 + (size_t)31*NS*384, 384,
                                   Wih1 + (size_t)G*384, 384,
                                   p_gx1b, G, 384, bih1 + G, bhh1 + G);

    // #7-8: layer1 recurrence fwd; bwd single step
    lstm_mma1_db<<<dim3(128,1), 768, SMDB>>>(p_gx1, Whh1, p_h2);
    bwd1_last<<<NS, H>>>(p_gx1b, p_h2);

    // #9-10: agg layer 1 (E1 already computed at #3)
    gemm_nn64<<<dim3(16,2), 256>>>(p_h2, 384, Wagg1, 128, p_M, 128, 384, (const float*)0);
    gemm_nn64<<<dim3(16,2), 256>>>(p_BetaT, NS, p_M, 128, p_n1, 128, NS, p_E);

    // #11-13: agg layer 2
    gemm_nn64<<<dim3(16,2), 256>>>(p_n1, 128, Wagg2, 128, p_M, 128, 128, (const float*)0);
    agg_extra<<<NS, 128>>>(p_t3, Wagg2 + (size_t)128*128, bagg2, p_E);
    gemm_nn64<<<dim3(16,2), 256>>>(p_BetaT, NS, p_M, 128, p_n2, 128, NS, p_E);

    // #14: output
    out_kernel<<<256, 256>>>(p_h2, p_n1, p_n2, Wout, bout, out);
}

// round 17
// speedup vs baseline: 2.4586x; 1.0282x over previous
#include <cuda_runtime.h>
#include <math.h>
#include <stdint.h>

#define NS 1024
#define T  32
#define NF 16
#define H  192
#define G  768

typedef unsigned long long u64;

static __device__ float g_gx1[(size_t)NS*T*G];     // time-major: [tt][G][NS]
static __device__ float g_gx1b[(size_t)NS*G];      // [s][G]
static __device__ float g_h1[(size_t)NS*T*384];    // TIME-MAJOR: [tt][s][384]
static __device__ float g_h2[(size_t)NS*384];
static __device__ float g_BetaT[(size_t)NS*NS];
static __device__ float g_t3[NS*3];
static __device__ int   g_pid[NS];
static __device__ int   g_off[NS];
static __device__ float g_M[NS*128];
static __device__ float g_E[NS*128];
static __device__ float g_n1[NS*128];
static __device__ float g_n2[NS*128];

__device__ __forceinline__ float sigm(float x){ return 1.f/(1.f+expf(-x)); }
__device__ __forceinline__ u64 pk(float x, float y){ u64 r; asm("mov.b64 %0,{%1,%2};":"=l"(r):"f"(x),"f"(y)); return r; }
__device__ __forceinline__ void fma2(u64& d, u64 a, u64 b){ asm("fma.rn.f32x2 %0,%1,%2,%0;":"+l"(d):"l"(a),"l"(b)); }
__device__ __forceinline__ void unpk(u64 v, float& x, float& y){ asm("mov.b64 {%0,%1},%2;":"=f"(x),"=f"(y):"l"(v)); }
__device__ __forceinline__ float lohi(u64 v){ float x,y; unpk(v,x,y); return x+y; }
__device__ __forceinline__ uint32_t smem_u32(const void* p){
    uint32_t a; asm("{ .reg .u64 t; cvta.to.shared.u64 t, %1; cvt.u32.u64 %0, t; }":"=r"(a):"l"(p)); return a;
}
__device__ __forceinline__ uint32_t tf32r(float x){
    uint32_t r; asm("cvt.rna.tf32.f32 %0,%1;":"=r"(r):"f"(x)); return r;
}
#define CL_ARRIVE() asm volatile("barrier.cluster.arrive.aligned;" ::: "memory")
#define CL_WAIT()   asm volatile("barrier.cluster.wait.aligned;"   ::: "memory")

__device__ __forceinline__ void mma_tf32(float& c0, float& c1, float& c2, float& c3,
                                         uint32_t a0, uint32_t a1, uint32_t a2, uint32_t a3,
                                         uint32_t b0, uint32_t b1){
    asm volatile(
        "mma.sync.aligned.m16n8k8.row.col.f32.tf32.tf32.f32 "
        "{%0,%1,%2,%3}, {%4,%5,%6,%7}, {%8,%9}, {%0,%1,%2,%3};"
        : "+f"(c0), "+f"(c1), "+f"(c2), "+f"(c3)
        : "r"(a0), "r"(a1), "r"(a2), "r"(a3), "r"(b0), "r"(b1));
}
__device__ __forceinline__ void dsmem_st4(uint32_t da, float4 v){
    asm volatile("st.shared::cluster.v4.f32 [%0],{%1,%2,%3,%4};"
                 :: "r"(da), "f"(v.x), "f"(v.y), "f"(v.z), "f"(v.w) : "memory");
}

// ---- generic gx GEMM via mma.sync tf32, double-buffered (R14-proven).
__global__ __launch_bounds__(256,2)
void gx_hmma(const float* __restrict__ A, int rstride, size_t tmul,
             const float* __restrict__ Bw, float* __restrict__ Ct, int K,
             const float* __restrict__ bias0, const float* __restrict__ bias1)
{
    extern __shared__ __align__(16) float dyn[];
    float* csh = dyn;                 // [128][132] reused for epilogue
    __shared__ float bsh[128];
    const int tt = blockIdx.x >> 3;
    const int s0 = (blockIdx.x & 7) * 128;
    const int n0 = blockIdx.y * 128;
    const int tid = threadIdx.x;
    const int w    = tid >> 5;
    const int lane = tid & 31;
    const int gid  = lane >> 2;
    const int tid4 = lane & 3;
    const int m0w  = (w & 1) * 64;
    const int n0w  = (w >> 1) * 32;
    const int row = tid>>1, kq = (tid&1)*8;
    const float* aBase = A + (size_t)(s0+row)*rstride + (size_t)tt*tmul + kq;
    const float* bBase = Bw + (size_t)(n0+row)*K + kq;

    if (tid < 128) bsh[tid] = bias0[n0+tid] + bias1[n0+tid];

    float acc[4][4][4];
    #pragma unroll
    for (int mi=0;mi<4;mi++)
        #pragma unroll
        for (int ni=0;ni<4;ni++)
            #pragma unroll
            for (int q=0;q<4;q++) acc[mi][ni][q]=0.f;

    float4 a0 = *(const float4*)(aBase);
    float4 a1 = *(const float4*)(aBase + 4);
    float4 b0 = *(const float4*)(bBase);
    float4 b1 = *(const float4*)(bBase + 4);
    {
        float* As = dyn; float* Bs = dyn + 2176;
        As[(kq+0)*136+row]=__uint_as_float(tf32r(a0.x)); As[(kq+1)*136+row]=__uint_as_float(tf32r(a0.y));
        As[(kq+2)*136+row]=__uint_as_float(tf32r(a0.z)); As[(kq+3)*136+row]=__uint_as_float(tf32r(a0.w));
        As[(kq+4)*136+row]=__uint_as_float(tf32r(a1.x)); As[(kq+5)*136+row]=__uint_as_float(tf32r(a1.y));
        As[(kq+6)*136+row]=__uint_as_float(tf32r(a1.z)); As[(kq+7)*136+row]=__uint_as_float(tf32r(a1.w));
        Bs[(kq+0)*136+row]=__uint_as_float(tf32r(b0.x)); Bs[(kq+1)*136+row]=__uint_as_float(tf32r(b0.y));
        Bs[(kq+2)*136+row]=__uint_as_float(tf32r(b0.z)); Bs[(kq+3)*136+row]=__uint_as_float(tf32r(b0.w));
        Bs[(kq+4)*136+row]=__uint_as_float(tf32r(b1.x)); Bs[(kq+5)*136+row]=__uint_as_float(tf32r(b1.y));
        Bs[(kq+6)*136+row]=__uint_as_float(tf32r(b1.z)); Bs[(kq+7)*136+row]=__uint_as_float(tf32r(b1.w));
    }
    __syncthreads();

    int buf = 0;
    for (int k0=0;k0<K;k0+=16){
        const bool nxt = (k0+16)<K;
        if (nxt){
            a0 = *(const float4*)(aBase + k0+16);
            a1 = *(const float4*)(aBase + k0+20);
            b0 = *(const float4*)(bBase + k0+16);
            b1 = *(const float4*)(bBase + k0+20);
        }
        const float* As = dyn + buf*4352;
        const float* Bs = As + 2176;
        #pragma unroll
        for (int k8=0;k8<16;k8+=8){
            uint32_t af[4][4];
            #pragma unroll
            for (int mi=0;mi<4;mi++){
                int m = m0w + mi*16 + gid;
                af[mi][0] = __float_as_uint(As[(k8+tid4  )*136 + m  ]);
                af[mi][1] = __float_as_uint(As[(k8+tid4  )*136 + m+8]);
                af[mi][2] = __float_as_uint(As[(k8+tid4+4)*136 + m  ]);
                af[mi][3] = __float_as_uint(As[(k8+tid4+4)*136 + m+8]);
            }
            uint32_t bf[4][2];
            #pragma unroll
            for (int ni=0;ni<4;ni++){
                int n = n0w + ni*8 + gid;
                bf[ni][0] = __float_as_uint(Bs[(k8+tid4  )*136 + n]);
                bf[ni][1] = __float_as_uint(Bs[(k8+tid4+4)*136 + n]);
            }
            #pragma unroll
            for (int mi=0;mi<4;mi++)
                #pragma unroll
                for (int ni=0;ni<4;ni++)
                    mma_tf32(acc[mi][ni][0], acc[mi][ni][1], acc[mi][ni][2], acc[mi][ni][3],
                             af[mi][0], af[mi][1], af[mi][2], af[mi][3],
                             bf[ni][0], bf[ni][1]);
        }
        if (nxt){
            float* An = dyn + (buf^1)*4352;
            float* Bn = An + 2176;
            An[(kq+0)*136+row]=__uint_as_float(tf32r(a0.x)); An[(kq+1)*136+row]=__uint_as_float(tf32r(a0.y));
            An[(kq+2)*136+row]=__uint_as_float(tf32r(a0.z)); An[(kq+3)*136+row]=__uint_as_float(tf32r(a0.w));
            An[(kq+4)*136+row]=__uint_as_float(tf32r(a1.x)); An[(kq+5)*136+row]=__uint_as_float(tf32r(a1.y));
            An[(kq+6)*136+row]=__uint_as_float(tf32r(a1.z)); An[(kq+7)*136+row]=__uint_as_float(tf32r(a1.w));
            Bn[(kq+0)*136+row]=__uint_as_float(tf32r(b0.x)); Bn[(kq+1)*136+row]=__uint_as_float(tf32r(b0.y));
            Bn[(kq+2)*136+row]=__uint_as_float(tf32r(b0.z)); Bn[(kq+3)*136+row]=__uint_as_float(tf32r(b0.w));
            Bn[(kq+4)*136+row]=__uint_as_float(tf32r(b1.x)); Bn[(kq+5)*136+row]=__uint_as_float(tf32r(b1.y));
            Bn[(kq+6)*136+row]=__uint_as_float(tf32r(b1.z)); Bn[(kq+7)*136+row]=__uint_as_float(tf32r(b1.w));
            __syncthreads();
            buf ^= 1;
        }
    }
    __syncthreads();
    #pragma unroll
    for (int mi=0;mi<4;mi++){
        #pragma unroll
        for (int ni=0;ni<4;ni++){
            int nl = n0w + ni*8 + tid4*2;
            int ml = m0w + mi*16 + gid;
            csh[(size_t)(nl  )*132 + ml  ] = acc[mi][ni][0] + bsh[nl];
            csh[(size_t)(nl+1)*132 + ml  ] = acc[mi][ni][1] + bsh[nl+1];
            csh[(size_t)(nl  )*132 + ml+8] = acc[mi][ni][2] + bsh[nl];
            csh[(size_t)(nl+1)*132 + ml+8] = acc[mi][ni][3] + bsh[nl+1];
        }
    }
    __syncthreads();
    {
        int jl = tid>>1, half = (tid&1)*64;
        const float* src = csh + (size_t)jl*132 + half;
        float* dst = Ct + ((size_t)tt*G + n0 + jl)*NS + s0 + half;
        #pragma unroll
        for (int v=0;v<16;v++)
            *(float4*)(dst + v*4) = *(const float4*)(src + v*4);
    }
}

// ---- FUSED layer-0 LSTM (input GEMM + recurrence), MW=2, SPC=64.
// xs staging for step t+1 hidden in pair-1 barrier window.
__global__ __launch_bounds__(768,1) __cluster_dims__(4,1,1)
void lstm_mma2f(const float* __restrict__ x,
                const float* __restrict__ Wih_all, const float* __restrict__ bih_all,
                const float* __restrict__ bhh_all, const float* __restrict__ Whh_all,
                float* __restrict__ outp)
{
    constexpr int MW = 2, SPC = 64, NI = 2, HSP = 196, BSP = 196;
    constexpr int WSP = 20, XSP = 20;
    extern __shared__ float sm[];
    float* Bsh = sm;                       // [192][BSP] Whh tf32, row = ul*4+q
    float* Hs  = Bsh + 192*BSP;            // [SPC][HSP] h tf32
    float* ws  = Hs + SPC*HSP;             // [192][WSP] Wih tf32
    float* xs  = ws + 192*WSP;             // [SPC][XSP] x step-slice tf32

    const int dir  = blockIdx.y;
    const float* Whh = Whh_all + (size_t)dir*G*H;
    const float* Wih = Wih_all + (size_t)dir*G*NF;

    const int tid  = threadIdx.x;
    const int w    = tid >> 5;
    const int lane = tid & 31;
    const int gid  = lane >> 2;
    const int tid4 = lane & 3;
    const int mw   = w % MW;
    const int nw   = w / MW;
    const bool ev  = ((tid4 & 1) == 0);
    uint32_t rank; asm("mov.u32 %0, %%cluster_ctarank;" : "=r"(rank));
    const int cid   = blockIdx.x >> 2;
    const int sbase = cid * SPC;
    const int jsl   = (int)rank * 48;
    const uint32_t hs_base = smem_u32(Hs);

    for (int i = tid; i < 192*48; i += 768){
        int lr = i / 48, c4 = i % 48;
        int ul = lr >> 2, q = lr & 3;
        float4 v = *(const float4*)(Whh + (size_t)(q*192 + jsl + ul)*H + c4*4);
        float* bp = Bsh + lr*BSP + c4*4;
        bp[0]=__uint_as_float(tf32r(v.x)); bp[1]=__uint_as_float(tf32r(v.y));
        bp[2]=__uint_as_float(tf32r(v.z)); bp[3]=__uint_as_float(tf32r(v.w));
    }
    for (int i = tid; i < 192*16; i += 768){
        int lr = i >> 4, k = i & 15;
        int ul = lr >> 2, q = lr & 3;
        ws[lr*WSP + k] = __uint_as_float(tf32r(Wih[(size_t)(q*192 + jsl + ul)*NF + k]));
    }
    for (int i = tid; i < SPC*HSP; i += 768) Hs[i] = 0.f;
    // prologue: stage xs for step 0
    {
        const int tt0 = (dir==1) ? (T-1) : 0;
        for (int i = tid; i < SPC*NF; i += 768){
            int sl = i >> 4, f = i & 15;
            xs[sl*XSP + f] = __uint_as_float(tf32r(
                x[((size_t)(sbase+sl)*T + tt0)*NF + f]));
        }
    }

    float bq[NI][4];
    #pragma unroll
    for (int ni=0;ni<NI;ni++){
        int ul = 2*(nw*NI + ni) + (tid4>>1);
        #pragma unroll
        for (int q=0;q<4;q++){
            size_t idx = (size_t)dir*G + q*192 + jsl + ul;
            bq[ni][q] = bih_all[idx] + bhh_all[idx];
        }
    }
    CL_ARRIVE(); CL_WAIT();

    float cst[2][NI];
    #pragma unroll
    for (int a=0;a<2;a++)
        #pragma unroll
        for (int b=0;b<NI;b++) cst[a][b]=0.f;

    int sl_t = mw*32 + gid + (ev ? 0 : 8);
    const int xr  = tid / 12;
    const int xc4 = tid % 12;
    const uint32_t xla = hs_base + (uint32_t)(xr*HSP + jsl + xc4*4)*4u;

    for (int step=0; step<T; ++step){
        const int tt = (dir==1) ? (T-1-step) : step;

        float acc[2][NI][4];
        #pragma unroll
        for (int mi=0;mi<2;mi++)
            #pragma unroll
            for (int ni=0;ni<NI;ni++)
                #pragma unroll
                for (int q=0;q<4;q++) acc[mi][ni][q]=0.f;

        #pragma unroll
        for (int k8=0;k8<16;k8+=8){
            uint32_t af[2][4];
            #pragma unroll
            for (int mi=0;mi<2;mi++){
                int m = mw*32 + mi*16 + gid;
                af[mi][0] = __float_as_uint(xs[(m  )*XSP + k8+tid4  ]);
                af[mi][1] = __float_as_uint(xs[(m+8)*XSP + k8+tid4  ]);
                af[mi][2] = __float_as_uint(xs[(m  )*XSP + k8+tid4+4]);
                af[mi][3] = __float_as_uint(xs[(m+8)*XSP + k8+tid4+4]);
            }
            uint32_t bf[NI][2];
            #pragma unroll
            for (int ni=0;ni<NI;ni++){
                int n = (nw*NI + ni)*8 + gid;
                bf[ni][0] = __float_as_uint(ws[n*WSP + k8+tid4  ]);
                bf[ni][1] = __float_as_uint(ws[n*WSP + k8+tid4+4]);
            }
            #pragma unroll
            for (int mi=0;mi<2;mi++)
                #pragma unroll
                for (int ni=0;ni<NI;ni++)
                    mma_tf32(acc[mi][ni][0], acc[mi][ni][1], acc[mi][ni][2], acc[mi][ni][3],
                             af[mi][0], af[mi][1], af[mi][2], af[mi][3],
                             bf[ni][0], bf[ni][1]);
        }

        #pragma unroll 2
        for (int k8=0;k8<192;k8+=8){
            uint32_t af[2][4];
            #pragma unroll
            for (int mi=0;mi<2;mi++){
                int m = mw*32 + mi*16 + gid;
                af[mi][0] = __float_as_uint(Hs[(m  )*HSP + k8+tid4  ]);
                af[mi][1] = __float_as_uint(Hs[(m+8)*HSP + k8+tid4  ]);
                af[mi][2] = __float_as_uint(Hs[(m  )*HSP + k8+tid4+4]);
                af[mi][3] = __float_as_uint(Hs[(m+8)*HSP + k8+tid4+4]);
            }
            uint32_t bf[NI][2];
            #pragma unroll
            for (int ni=0;ni<NI;ni++){
                int n = (nw*NI + ni)*8 + gid;
                bf[ni][0] = __float_as_uint(Bsh[n*BSP + k8+tid4  ]);
                bf[ni][1] = __float_as_uint(Bsh[n*BSP + k8+tid4+4]);
            }
            #pragma unroll
            for (int mi=0;mi<2;mi++)
                #pragma unroll
                for (int ni=0;ni<NI;ni++)
                    mma_tf32(acc[mi][ni][0], acc[mi][ni][1], acc[mi][ni][2], acc[mi][ni][3],
                             af[mi][0], af[mi][1], af[mi][2], af[mi][3],
                             bf[ni][0], bf[ni][1]);
        }

        CL_ARRIVE();                  // my reads of Hs(t-1)/xs done
        __syncthreads();              // all local threads past their reads
        // stage xs for next step inside the barrier window
        if (step+1 < T){
            const int ttn = (dir==1) ? (T-2-step) : (step+1);
            for (int i = tid; i < SPC*NF; i += 768){
                int sl = i >> 4, f = i & 15;
                xs[sl*XSP + f] = __uint_as_float(tf32r(
                    x[((size_t)(sbase+sl)*T + ttn)*NF + f]));
            }
        }
        CL_WAIT();                    // all CTAs' reads done -> safe to write Hs

        float hout[2][NI];
        #pragma unroll
        for (int mi=0;mi<2;mi++){
            #pragma unroll
            for (int ni=0;ni<NI;ni++){
                float c0=acc[mi][ni][0], c1=acc[mi][ni][1];
                float c2=acc[mi][ni][2], c3=acc[mi][ni][3];
                float s0 = ev ? c2 : c0;
                float s1 = ev ? c3 : c1;
                float r0 = __shfl_xor_sync(0xffffffffu, s0, 1);
                float r1 = __shfl_xor_sync(0xffffffffu, s1, 1);
                float pi = (ev ? c0 : r0) + bq[ni][0];
                float pf = (ev ? c1 : r1) + bq[ni][1];
                float pg = (ev ? r0 : c2) + bq[ni][2];
                float po = (ev ? r1 : c3) + bq[ni][3];
                float iv = sigm(pi), fv = sigm(pf);
                float gv = tanhf(pg), ov = sigm(po);
                float cc = fv*cst[mi][ni] + iv*gv;
                cst[mi][ni] = cc;
                float hh = ov*tanhf(cc);
                hout[mi][ni] = hh;
                int sl = sl_t + mi*16;
                int ul = 2*(nw*NI + ni) + (tid4>>1);
                Hs[sl*HSP + jsl + ul] = __uint_as_float(tf32r(hh));
            }
        }
        __syncthreads();              // own slice fully written locally (and xs staged)
        {
            float4 v = *(const float4*)(Hs + xr*HSP + jsl + xc4*4);
            #pragma unroll
            for (int r=0;r<4;r++){
                if (r == (int)rank) continue;
                uint32_t da; asm("mapa.shared::cluster.u32 %0,%1,%2;":"=r"(da):"r"(xla),"r"(r));
                dsmem_st4(da, v);
            }
        }
        CL_ARRIVE();                  // release h(t)
        #pragma unroll
        for (int mi=0;mi<2;mi++){
            int s = sbase + sl_t + mi*16;
            #pragma unroll
            for (int ni=0;ni<NI;ni++){
                int ul = 2*(nw*NI + ni) + (tid4>>1);
                outp[((size_t)tt*NS + s)*384 + dir*192 + jsl + ul] = hout[mi][ni];
            }
        }
        CL_WAIT();                    // acquire peers' h(t)
    }
}

// ---- layer1 fwd LSTM, MW=1 (SPC=32), double-buffered Hs, 1 barrier/step.
__global__ __launch_bounds__(768,1) __cluster_dims__(4,1,1)
void lstm_mma1_db(const float* __restrict__ gx, const float* __restrict__ Whh,
                  float* __restrict__ outp)
{
    constexpr int SPC = 32, HSP = 196, BSP = 196;
    extern __shared__ float sm[];
    float* Bsh = sm;               // [192][BSP]
    float* Hs0 = sm + 192*BSP;     // [2][SPC][HSP]

    const int tid  = threadIdx.x;
    const int w    = tid >> 5;
    const int lane = tid & 31;
    const int gid  = lane >> 2;
    const int tid4 = lane & 3;
    const int nw   = w;
    const bool ev  = ((tid4 & 1) == 0);
    uint32_t rank; asm("mov.u32 %0, %%cluster_ctarank;" : "=r"(rank));
    const int cid   = blockIdx.x >> 2;
    const int sbase = cid * SPC;
    const int jsl   = (int)rank * 48;
    const uint32_t hb0 = smem_u32(Hs0);
    const uint32_t hb1 = smem_u32(Hs0 + SPC*HSP);

    for (int i = tid; i < 192*48; i += 768){
        int lr = i / 48, c4 = i % 48;
        int ul = lr >> 2, q = lr & 3;
        float4 v = *(const float4*)(Whh + (size_t)(q*192 + jsl + ul)*H + c4*4);
        float* bp = Bsh + lr*BSP + c4*4;
        bp[0]=__uint_as_float(tf32r(v.x)); bp[1]=__uint_as_float(tf32r(v.y));
        bp[2]=__uint_as_float(tf32r(v.z)); bp[3]=__uint_as_float(tf32r(v.w));
    }
    for (int i = tid; i < 2*SPC*HSP; i += 768) Hs0[i] = 0.f;
    CL_ARRIVE(); CL_WAIT();

    float cst[2];
    cst[0]=0.f; cst[1]=0.f;
    int sl_t = gid + (ev ? 0 : 8);
    const int ul = 2*nw + (tid4>>1);

    for (int step=0; step<T; ++step){
        const int tt = step;
        const float* Hr = Hs0 + (step&1)*SPC*HSP;
        float* Hw = Hs0 + ((step&1)^1)*SPC*HSP;
        const uint32_t hw_base = (step&1) ? hb0 : hb1;

        float gxr[2][4];
        #pragma unroll
        for (int mi=0;mi<2;mi++){
            int s = sbase + sl_t + mi*16;
            #pragma unroll
            for (int q=0;q<4;q++)
                gxr[mi][q] = gx[((size_t)tt*G + q*192 + jsl + ul)*NS + s];
        }

        float acc[2][4];
        #pragma unroll
        for (int mi=0;mi<2;mi++)
            #pragma unroll
            for (int q=0;q<4;q++) acc[mi][q]=0.f;

        #pragma unroll 2
        for (int k8=0;k8<192;k8+=8){
            uint32_t af[2][4];
            #pragma unroll
            for (int mi=0;mi<2;mi++){
                int m = mi*16 + gid;
                af[mi][0] = __float_as_uint(Hr[(m  )*HSP + k8+tid4  ]);
                af[mi][1] = __float_as_uint(Hr[(m+8)*HSP + k8+tid4  ]);
                af[mi][2] = __float_as_uint(Hr[(m  )*HSP + k8+tid4+4]);
                af[mi][3] = __float_as_uint(Hr[(m+8)*HSP + k8+tid4+4]);
            }
            uint32_t bf[2];
            {
                int n = nw*8 + gid;
                bf[0] = __float_as_uint(Bsh[n*BSP + k8+tid4  ]);
                bf[1] = __float_as_uint(Bsh[n*BSP + k8+tid4+4]);
            }
            #pragma unroll
            for (int mi=0;mi<2;mi++)
                mma_tf32(acc[mi][0], acc[mi][1], acc[mi][2], acc[mi][3],
                         af[mi][0], af[mi][1], af[mi][2], af[mi][3],
                         bf[0], bf[1]);
        }

        float hout[2];
        #pragma unroll
        for (int mi=0;mi<2;mi++){
            float c0=acc[mi][0], c1=acc[mi][1], c2=acc[mi][2], c3=acc[mi][3];
            float s0 = ev ? c2 : c0;
            float s1 = ev ? c3 : c1;
            float r0 = __shfl_xor_sync(0xffffffffu, s0, 1);
            float r1 = __shfl_xor_sync(0xffffffffu, s1, 1);
            float pi = (ev ? c0 : r0) + gxr[mi][0];
            float pf = (ev ? c1 : r1) + gxr[mi][1];
            float pg = (ev ? r0 : c2) + gxr[mi][2];
            float po = (ev ? r1 : c3) + gxr[mi][3];
            float iv = sigm(pi), fv = sigm(pf);
            float gv = tanhf(pg), ov = sigm(po);
            float cc = fv*cst[mi] + iv*gv;
            cst[mi] = cc;
            float hh = ov*tanhf(cc);
            hout[mi] = hh;
            int sl = sl_t + mi*16;
            Hw[sl*HSP + jsl + ul] = __uint_as_float(tf32r(hh));
        }
        __syncthreads();
        for (int i = tid; i < 1152; i += 768){
            int pr = i / 384, j = i - pr*384;
            int r  = pr + (pr >= (int)rank ? 1 : 0);
            int row = j / 12, c4 = j - row*12;
            uint32_t la = hw_base + (uint32_t)(row*HSP + jsl + c4*4)*4u;
            float4 v = *(const float4*)(Hw + row*HSP + jsl + c4*4);
            uint32_t da; asm("mapa.shared::cluster.u32 %0,%1,%2;":"=r"(da):"r"(la),"r"(r));
            dsmem_st4(da, v);
        }
        CL_ARRIVE();
        if (step==T-1){
            #pragma unroll
            for (int mi=0;mi<2;mi++){
                int s = sbase + sl_t + mi*16;
                outp[(size_t)s*384 + jsl + ul] = hout[mi];
            }
        }
        CL_WAIT();
    }
}

// ---- plain NT gemm (gx1b), C[m][n] layout ----
__global__ __launch_bounds__(256,2)
void gemm_nt128(const float* __restrict__ A, int lda,
                const float* __restrict__ B, int ldb,
                float* __restrict__ C, int ldc, int K,
                const float* __restrict__ bias0, const float* __restrict__ bias1)
{
    __shared__ __align__(16) float As[16][136];
    __shared__ __align__(16) float Bs[16][136];
    const int m0 = blockIdx.x*128, n0 = blockIdx.y*128;
    const int tid = threadIdx.x;
    const int ty = tid>>4, tx = tid&15;
    const int row = tid>>1, kq = (tid&1)*8;
    u64 acc[4][8];
    #pragma unroll
    for (int i=0;i<4;i++)
        #pragma unroll
        for (int j=0;j<8;j++) acc[i][j]=0ull;

    for (int k0=0;k0<K;k0+=16){
        float4 a0 = *(const float4*)(A + (size_t)(m0+row)*lda + k0 + kq);
        float4 a1 = *(const float4*)(A + (size_t)(m0+row)*lda + k0 + kq + 4);
        float4 b0 = *(const float4*)(B + (size_t)(n0+row)*ldb + k0 + kq);
        float4 b1 = *(const float4*)(B + (size_t)(n0+row)*ldb + k0 + kq + 4);
        __syncthreads();
        As[kq+0][row]=a0.x; As[kq+1][row]=a0.y; As[kq+2][row]=a0.z; As[kq+3][row]=a0.w;
        As[kq+4][row]=a1.x; As[kq+5][row]=a1.y; As[kq+6][row]=a1.z; As[kq+7][row]=a1.w;
        Bs[kq+0][row]=b0.x; Bs[kq+1][row]=b0.y; Bs[kq+2][row]=b0.z; Bs[kq+3][row]=b0.w;
        Bs[kq+4][row]=b1.x; Bs[kq+5][row]=b1.y; Bs[kq+6][row]=b1.z; Bs[kq+7][row]=b1.w;
        __syncthreads();
        #pragma unroll
        for (int k=0;k<16;k++){
            ulonglong2 av0 = *(const ulonglong2*)&As[k][ty*8];
            ulonglong2 av1 = *(const ulonglong2*)&As[k][ty*8+4];
            float4 bA = *(const float4*)&Bs[k][tx*8];
            float4 bB = *(const float4*)&Bs[k][tx*8+4];
            u64 bb[8];
            bb[0]=pk(bA.x,bA.x); bb[1]=pk(bA.y,bA.y); bb[2]=pk(bA.z,bA.z); bb[3]=pk(bA.w,bA.w);
            bb[4]=pk(bB.x,bB.x); bb[5]=pk(bB.y,bB.y); bb[6]=pk(bB.z,bB.z); bb[7]=pk(bB.w,bB.w);
            u64 aa[4] = { av0.x, av0.y, av1.x, av1.y };
            #pragma unroll
            for (int i2=0;i2<4;i2++)
                #pragma unroll
                for (int j=0;j<8;j++) fma2(acc[i2][j], aa[i2], bb[j]);
        }
    }
    float bv[8];
    #pragma unroll
    for (int j=0;j<8;j++){
        int n = n0+tx*8+j;
        float v = 0.f;
        if (bias0) v += bias0[n];
        if (bias1) v += bias1[n];
        bv[j]=v;
    }
    #pragma unroll
    for (int i2=0;i2<4;i2++){
        float r0[8], r1[8];
        #pragma unroll
        for (int j=0;j<8;j++){ unpk(acc[i2][j], r0[j], r1[j]); r0[j]+=bv[j]; r1[j]+=bv[j]; }
        float* c0 = C + (size_t)(m0+ty*8+2*i2)*ldc + n0 + tx*8;
        float* c1 = C + (size_t)(m0+ty*8+2*i2+1)*ldc + n0 + tx*8;
        *(float4*)c0     = make_float4(r0[0],r0[1],r0[2],r0[3]);
        *(float4*)(c0+4) = make_float4(r0[4],r0[5],r0[6],r0[7]);
        *(float4*)c1     = make_float4(r1[0],r1[1],r1[2],r1[3]);
        *(float4*)(c1+4) = make_float4(r1[4],r1[5],r1[6],r1[7]);
    }
}

// ---- C[m][n] = sum_k A[m][k]*B[k][n] (+addC), 32x64 tile (grid 32x2), 2x4 micro.
__global__ __launch_bounds__(256,2)
void gemm_nn32(const float* __restrict__ A, int lda,
               const float* __restrict__ B, int ldb,
               float* __restrict__ C, int ldc, int K,
               const float* __restrict__ addC)
{
    __shared__ __align__(16) float As[16][36];
    __shared__ __align__(16) float Bs[16][68];
    const int m0 = blockIdx.x*32, n0 = blockIdx.y*64;
    const int tid = threadIdx.x;
    const int ty = tid>>4, tx = tid&15;      // ty: 0..15 -> 2 rows; tx: 0..15 -> 4 cols
    const int arow = tid>>3, akq = (tid&7)*2;
    const int bk = tid>>4, bnq = (tid&15)*4;
    float acc[2][4];
    #pragma unroll
    for (int i=0;i<2;i++)
        #pragma unroll
        for (int j=0;j<4;j++) acc[i][j]=0.f;

    for (int k0=0;k0<K;k0+=16){
        float2 av = *(const float2*)(A + (size_t)(m0+arow)*lda + k0 + akq);
        float4 bv = *(const float4*)(B + (size_t)(k0+bk)*ldb + n0 + bnq);
        __syncthreads();
        As[akq+0][arow]=av.x; As[akq+1][arow]=av.y;
        *(float4*)&Bs[bk][bnq] = bv;
        __syncthreads();
        #pragma unroll
        for (int k=0;k<16;k++){
            float a[2],b[4];
            a[0]=As[k][ty*2]; a[1]=As[k][ty*2+1];
            #pragma unroll
            for (int j=0;j<4;j++) b[j]=Bs[k][tx*4+j];
            #pragma unroll
            for (int i=0;i<2;i++)
                #pragma unroll
                for (int j=0;j<4;j++) acc[i][j]+=a[i]*b[j];
        }
    }
    #pragma unroll
    for (int i=0;i<2;i++){
        int m = m0+ty*2+i;
        float* cp = C + (size_t)m*ldc + n0 + tx*4;
        const float* ap = addC ? addC + (size_t)m*ldc + n0 + tx*4 : (const float*)0;
        #pragma unroll
        for (int j=0;j<4;j++){
            float v = acc[i][j];
            if (ap) v += ap[j];
            cp[j] = v;
        }
    }
}

// ---- layer1 bwd @ t=31 only (h0=c0=0) ----
__global__ void bwd1_last(const float* __restrict__ gxb, float* __restrict__ h2)
{
    int n = blockIdx.x, j = threadIdx.x;
    const float* g = gxb + (size_t)n*G;
    float iv = sigm(g[j]);
    float gv = tanhf(g[2*H+j]);
    float ov = sigm(g[3*H+j]);
    float cc = iv*gv;
    h2[(size_t)n*384 + 192 + j] = ov*tanhf(cc);
}

// ---- dynamic network ----
__global__ void dyn_scalars(const float* __restrict__ x, const float* __restrict__ theta,
                            int* __restrict__ pid, int* __restrict__ off)
{
    int n = blockIdx.x*blockDim.x + threadIdx.x;
    if (n >= NS) return;
    float th  = theta[n];
    float x30 = x[((size_t)n*T + 30)*NF];
    float x31 = x[((size_t)n*T + 31)*NF];
    int p0 = (x30 > th) ? 1 : ((x30 < -th) ? -1 : 0);
    int p1 = (x31 > th) ? 1 : ((x31 < -th) ? -1 : 0);
    pid[n] = (p0+1)*3 + (p1+1);
    off[n] = (p1+1)*3;
}

__global__ __launch_bounds__(256,1)
void dyn_beta(const float* __restrict__ PP, const int* __restrict__ pid,
              const int* __restrict__ off, float* __restrict__ BetaT,
              float* __restrict__ t3)
{
    __shared__ float s_raw[1024];
    __shared__ float s_adj[1024*3];
    __shared__ float s_red[256];
    const int y = blockIdx.x, tid = threadIdx.x;
    const int offy = off[y];
    for (int x=tid; x<NS; x+=256){
        size_t base = ((size_t)x*NS + y)*81 + (size_t)pid[x]*9 + offy;
        float a0=PP[base], a1=PP[base+1], a2=PP[base+2];
        s_adj[x*3+0]=a0; s_adj[x*3+1]=a1; s_adj[x*3+2]=a2;
        float nr = sqrtf(a0*a0+a1*a1+a2*a2);
        s_raw[x] = (nr > 0.38f) ? nr : 0.f;
    }
    __syncthreads();
    float lm = -1e30f;
    for (int x=tid; x<NS; x+=256) lm = fmaxf(lm, s_raw[x]);
    s_red[tid]=lm; __syncthreads();
    for (int o=128;o>0;o>>=1){ if(tid<o) s_red[tid]=fmaxf(s_red[tid],s_red[tid+o]); __syncthreads(); }
    const float mx = s_red[0];
    __syncthreads();
    float ls = 0.f;
    for (int x=tid; x<NS; x+=256){ float e=expf(s_raw[x]-mx); s_raw[x]=e; ls+=e; }
    s_red[tid]=ls; __syncthreads();
    for (int o=128;o>0;o>>=1){ if(tid<o) s_red[tid]+=s_red[tid+o]; __syncthreads(); }
    const float inv = 1.f/s_red[0];
    __syncthreads();
    float t0=0.f,t1=0.f,t2=0.f;
    for (int x=tid; x<NS; x+=256){
        float b = s_raw[x]*inv;
        BetaT[(size_t)y*NS + x] = b;
        t0 += b*s_adj[x*3+0]; t1 += b*s_adj[x*3+1]; t2 += b*s_adj[x*3+2];
    }
    s_red[tid]=t0; __syncthreads();
    for (int o=128;o>0;o>>=1){ if(tid<o) s_red[tid]+=s_red[tid+o]; __syncthreads(); }
    if(tid==0) t3[y*3+0]=s_red[0];
    __syncthreads();
    s_red[tid]=t1; __syncthreads();
    for (int o=128;o>0;o>>=1){ if(tid<o) s_red[tid]+=s_red[tid+o]; __syncthreads(); }
    if(tid==0) t3[y*3+1]=s_red[0];
    __syncthreads();
    s_red[tid]=t2; __syncthreads();
    for (int o=128;o>0;o>>=1){ if(tid<o) s_red[tid]+=s_red[tid+o]; __syncthreads(); }
    if(tid==0) t3[y*3+2]=s_red[0];
}

__global__ void agg_extra(const float* __restrict__ t3, const float* __restrict__ Wa,
                          const float* __restrict__ b, float* __restrict__ E)
{
    int y = blockIdx.x, u = threadIdx.x;
    float v = b[u] + t3[y*3+0]*Wa[u] + t3[y*3+1]*Wa[128+u] + t3[y*3+2]*Wa[256+u];
    E[(size_t)y*128 + u] = v;
}

__global__ void out_kernel(const float* __restrict__ nfeat, const float* __restrict__ n1,
                           const float* __restrict__ n2, const float* __restrict__ W,
                           const float* __restrict__ b, float* __restrict__ out)
{
    int warp = (blockIdx.x*blockDim.x + threadIdx.x)>>5;
    int lane = threadIdx.x & 31;
    if (warp >= NS*2) return;
    int n = warp>>1, o = warp&1;
    float s = 0.f;
    for (int k=lane;k<384;k+=32) s += nfeat[(size_t)n*384+k]*W[k*2+o];
    for (int k=lane;k<128;k+=32) s += n1[(size_t)n*128+k]*W[(384+k)*2+o];
    for (int k=lane;k<128;k+=32) s += n2[(size_t)n*128+k]*W[(512+k)*2+o];
    #pragma unroll
    for (int m=16;m>0;m>>=1) s += __shfl_xor_sync(0xffffffffu, s, m);
    if (lane==0) out[warp] = tanhf(s + b[o]);
}

extern "C" void kernel_launch(void* const* d_in, const int* in_sizes, int n_in,
                              void* d_out, int out_size)
{
    const float* x     = (const float*)d_in[0];
    const float* theta = (const float*)d_in[1];
    const float* PP    = (const float*)d_in[2];
    const float* Wih0  = (const float*)d_in[3];
    const float* Whh0  = (const float*)d_in[4];
    const float* bih0  = (const float*)d_in[5];
    const float* bhh0  = (const float*)d_in[6];
    const float* Wih1  = (const float*)d_in[7];
    const float* Whh1  = (const float*)d_in[8];
    const float* bih1  = (const float*)d_in[9];
    const float* bhh1  = (const float*)d_in[10];
    const float* Wagg1 = (const float*)d_in[11];
    const float* bagg1 = (const float*)d_in[12];
    const float* Wagg2 = (const float*)d_in[13];
    const float* bagg2 = (const float*)d_in[14];
    const float* Wout  = (const float*)d_in[15];
    const float* bout  = (const float*)d_in[16];
    float* out = (float*)d_out;

    float *p_gx1, *p_gx1b, *p_h1, *p_h2, *p_BetaT, *p_t3, *p_M, *p_E, *p_n1, *p_n2;
    int *p_pid, *p_off;
    cudaGetSymbolAddress((void**)&p_gx1,  g_gx1);
    cudaGetSymbolAddress((void**)&p_gx1b, g_gx1b);
    cudaGetSymbolAddress((void**)&p_h1,   g_h1);
    cudaGetSymbolAddress((void**)&p_h2,   g_h2);
    cudaGetSymbolAddress((void**)&p_BetaT,g_BetaT);
    cudaGetSymbolAddress((void**)&p_t3,   g_t3);
    cudaGetSymbolAddress((void**)&p_pid,  g_pid);
    cudaGetSymbolAddress((void**)&p_off,  g_off);
    cudaGetSymbolAddress((void**)&p_M,    g_M);
    cudaGetSymbolAddress((void**)&p_E,    g_E);
    cudaGetSymbolAddress((void**)&p_n1,   g_n1);
    cudaGetSymbolAddress((void**)&p_n2,   g_n2);

    const int SMF  = (192*196 + 64*196 + 192*20 + 64*20)*4;  // 221184 B
    const int SMDB = (192*196 + 2*32*196)*4;                 // lstm_mma1_db
    const int GSH  = 128*132*4;                              // gx_hmma
    cudaFuncSetAttribute(lstm_mma2f,   cudaFuncAttributeMaxDynamicSharedMemorySize, SMF);
    cudaFuncSetAttribute(lstm_mma1_db, cudaFuncAttributeMaxDynamicSharedMemorySize, SMDB);
    cudaFuncSetAttribute(gx_hmma,      cudaFuncAttributeMaxDynamicSharedMemorySize, GSH);

    // #1-3: dynamic network + E1 (independent of LSTM chain)
    dyn_scalars<<<4, 256>>>(x, theta, p_pid, p_off);
    dyn_beta<<<NS, 256>>>(PP, p_pid, p_off, p_BetaT, p_t3);
    agg_extra<<<NS, 128>>>(p_t3, Wagg1 + (size_t)384*128, bagg1, p_E);

    // #4: fused layer0 (input GEMM + recurrence), fwd+bwd — PROFILED SLOT
    lstm_mma2f<<<dim3(64,2), 768, SMF>>>(x, Wih0, bih0, bhh0, Whh0, p_h1);

    // #5: layer1 fwd gx via hmma (K=384)
    gx_hmma<<<dim3(256,6), 256, GSH>>>(p_h1, 384, (size_t)NS*384,
                                       Wih1, p_gx1, 384, bih1, bhh1);

    // #6: layer1 bwd gx at t=31 (rows = s contiguous in time-major h1)
    gemm_nt128<<<dim3(8,6), 256>>>(p_h1 + (size_t)31*NS*384, 384,
                                   Wih1 + (size_t)G*384, 384,
                                   p_gx1b, G, 384, bih1 + G, bhh1 + G);

    // #7-8: layer1 recurrence fwd; bwd single step
    lstm_mma1_db<<<dim3(128,1), 768, SMDB>>>(p_gx1, Whh1, p_h2);
    bwd1_last<<<NS, H>>>(p_gx1b, p_h2);

    // #9-10: agg layer 1 (E1 already computed at #3)
    gemm_nn32<<<dim3(32,2), 256>>>(p_h2, 384, Wagg1, 128, p_M, 128, 384, (const float*)0);
    gemm_nn32<<<dim3(32,2), 256>>>(p_BetaT, NS, p_M, 128, p_n1, 128, NS, p_E);

    // #11-13: agg layer 2
    gemm_nn32<<<dim3(32,2), 256>>>(p_n1, 128, Wagg2, 128, p_M, 128, 128, (const float*)0);
    agg_extra<<<NS, 128>>>(p_t3, Wagg2 + (size_t)128*128, bagg2, p_E);
    gemm_nn32<<<dim3(32,2), 256>>>(p_BetaT, NS, p_M, 128, p_n2, 128, NS, p_E);

    // #14: output
    out_kernel<<<256, 256>>>(p_h2, p_n1, p_n2, Wout, bout, out);
}